// round 1
// baseline (speedup 1.0000x reference)
#include <cuda_runtime.h>
#include <cuda_bf16.h>

// Problem constants
#define NB  4
#define CCH 256
#define LF  4096
#define L2  1024
#define HH  4
#define EE  64

// ---------------- device scratch (static allocations; no cudaMalloc) ----------------
__device__ float d_xagg[NB * CCH * L2];          // 4 MB
__device__ float d_xa  [NB * CCH * L2];          // 4 MB
__device__ float d_qb  [NB * CCH * LF];          // 16 MB
__device__ float d_kb  [NB * CCH * L2];          // 4 MB
__device__ float d_vb  [NB * CCH * L2];          // 4 MB
__device__ float d_ob  [NB * CCH * LF];          // 16 MB
__device__ float d_scores[(size_t)NB * HH * LF * L2]; // 256 MB
__device__ float d_bns[CCH];
__device__ float d_bnt[CCH];

// ---------------- BN fold: y = x*s + t for the two stacked eval BNs ----------------
__global__ void bnfold_kernel(const float* __restrict__ g1, const float* __restrict__ b1,
                              const float* __restrict__ m1, const float* __restrict__ v1,
                              const float* __restrict__ g2, const float* __restrict__ b2,
                              const float* __restrict__ m2, const float* __restrict__ v2) {
    int c = threadIdx.x;
    float i1 = g1[c] * rsqrtf(v1[c] + 1e-5f);
    float c1 = b1[c] - m1[c] * i1;
    float i2 = g2[c] * rsqrtf(v2[c] + 1e-5f);
    float c2 = b2[c] - m2[c] * i2;
    d_bns[c] = i1 * i2;
    d_bnt[c] = c1 * i2 + c2;
}

// ---------------- aggregation: mean + max over groups of 4 along L ----------------
// flattened: xagg[i] from x[4i..4i+3],  i in [0, NB*CCH*L2)
__global__ void aggregate_kernel(const float* __restrict__ x) {
    int i = blockIdx.x * blockDim.x + threadIdx.x;
    float4 t = reinterpret_cast<const float4*>(x)[i];
    float mx = fmaxf(fmaxf(t.x, t.y), fmaxf(t.z, t.w));
    d_xagg[i] = 0.25f * (t.x + t.y + t.z + t.w) + mx;
}

// ---------------- generic fp32 tiled GEMM ----------------
// Computes Y[m][n] = alpha * (rs?rs[m]:1) * sum_k opA(m,k)*opB(k,n) + (rb?rb[m]:0)
//   AT=false: A stored [K][M] (k-major rows), AT=true: A stored [M][K]
//   BT=false: B stored [K][N],                BT=true: B stored [N][K]
// 256 threads = 16x16; thread (ty,tx) owns rows ty+16*i, cols tx+16*j (conflict-free smem reads).
// All dims assumed to divide tiles exactly (true for every launch below).
template <int BM, int BN, int TM, int TNN, bool AT, bool BT>
__global__ __launch_bounds__(256) void gemm_kernel(
    const float* __restrict__ A, const float* __restrict__ B, float* __restrict__ Y,
    int K, int lda, int ldb, int ldy,
    long aB, long bB, long yB, float alpha,
    const float* __restrict__ rs, const float* __restrict__ rb)
{
    __shared__ float sA[16][BM];
    __shared__ float sB[16][BN];

    A += (long)blockIdx.z * aB;
    B += (long)blockIdx.z * bB;
    Y += (long)blockIdx.z * yB;

    int tid = threadIdx.x;
    int tx = tid & 15, ty = tid >> 4;
    int m0 = blockIdx.y * BM;
    int n0 = blockIdx.x * BN;

    float acc[TM][TNN];
#pragma unroll
    for (int i = 0; i < TM; i++)
#pragma unroll
        for (int j = 0; j < TNN; j++) acc[i][j] = 0.0f;

    for (int k0 = 0; k0 < K; k0 += 16) {
        // ---- load A tile ----
        if (AT) {
#pragma unroll
            for (int idx = tid * 4; idx < 16 * BM; idx += 1024) {
                int r = idx >> 4, kc = idx & 15;
                float4 t = *reinterpret_cast<const float4*>(A + (long)(m0 + r) * lda + k0 + kc);
                sA[kc + 0][r] = t.x; sA[kc + 1][r] = t.y;
                sA[kc + 2][r] = t.z; sA[kc + 3][r] = t.w;
            }
        } else {
#pragma unroll
            for (int idx = tid * 4; idx < 16 * BM; idx += 1024) {
                int kk = idx / BM, c = idx % BM;
                float4 t = *reinterpret_cast<const float4*>(A + (long)(k0 + kk) * lda + m0 + c);
                *reinterpret_cast<float4*>(&sA[kk][c]) = t;
            }
        }
        // ---- load B tile ----
        if (BT) {
#pragma unroll
            for (int idx = tid * 4; idx < 16 * BN; idx += 1024) {
                int r = idx >> 4, kc = idx & 15;
                float4 t = *reinterpret_cast<const float4*>(B + (long)(n0 + r) * ldb + k0 + kc);
                sB[kc + 0][r] = t.x; sB[kc + 1][r] = t.y;
                sB[kc + 2][r] = t.z; sB[kc + 3][r] = t.w;
            }
        } else {
#pragma unroll
            for (int idx = tid * 4; idx < 16 * BN; idx += 1024) {
                int kk = idx / BN, c = idx % BN;
                float4 t = *reinterpret_cast<const float4*>(B + (long)(k0 + kk) * ldb + n0 + c);
                *reinterpret_cast<float4*>(&sB[kk][c]) = t;
            }
        }
        __syncthreads();

#pragma unroll
        for (int kk = 0; kk < 16; kk++) {
            float a[TM], b[TNN];
#pragma unroll
            for (int i = 0; i < TM; i++) a[i] = sA[kk][ty + 16 * i];
#pragma unroll
            for (int j = 0; j < TNN; j++) b[j] = sB[kk][tx + 16 * j];
#pragma unroll
            for (int i = 0; i < TM; i++)
#pragma unroll
                for (int j = 0; j < TNN; j++) acc[i][j] = fmaf(a[i], b[j], acc[i][j]);
        }
        __syncthreads();
    }

#pragma unroll
    for (int i = 0; i < TM; i++) {
        int m = m0 + ty + 16 * i;
        float s = alpha * (rs ? rs[m] : 1.0f);
        float bsh = rb ? rb[m] : 0.0f;
#pragma unroll
        for (int j = 0; j < TNN; j++) {
            Y[(long)m * ldy + n0 + tx + 16 * j] = acc[i][j] * s + bsh;
        }
    }
}

// ---------------- row softmax over 1024 elements, in place on d_scores ----------------
__global__ __launch_bounds__(256) void softmax_kernel() {
    long r = blockIdx.x;
    float* p = d_scores + r * (long)L2;
    int t = threadIdx.x;
    __shared__ float red[256];

    float4 v = reinterpret_cast<float4*>(p)[t];
    float mx = fmaxf(fmaxf(v.x, v.y), fmaxf(v.z, v.w));
    red[t] = mx; __syncthreads();
#pragma unroll
    for (int s = 128; s > 0; s >>= 1) {
        if (t < s) red[t] = fmaxf(red[t], red[t + s]);
        __syncthreads();
    }
    mx = red[0];
    __syncthreads();

    v.x = __expf(v.x - mx); v.y = __expf(v.y - mx);
    v.z = __expf(v.z - mx); v.w = __expf(v.w - mx);
    float sm = v.x + v.y + v.z + v.w;
    red[t] = sm; __syncthreads();
#pragma unroll
    for (int s = 128; s > 0; s >>= 1) {
        if (t < s) red[t] += red[t + s];
        __syncthreads();
    }
    float inv = 1.0f / red[0];
    v.x *= inv; v.y *= inv; v.z *= inv; v.w *= inv;
    reinterpret_cast<float4*>(p)[t] = v;
}

// ---------------- launch ----------------
extern "C" void kernel_launch(void* const* d_in, const int* in_sizes, int n_in,
                              void* d_out, int out_size) {
    const float* x  = (const float*)d_in[0];
    const float* Wq = (const float*)d_in[1];  const float* bq = (const float*)d_in[2];
    const float* Wk = (const float*)d_in[3];  const float* bk = (const float*)d_in[4];
    const float* Wv = (const float*)d_in[5];  const float* bv = (const float*)d_in[6];
    const float* Wo = (const float*)d_in[7];  const float* bo = (const float*)d_in[8];
    const float* Wa = (const float*)d_in[9];
    const float* g1 = (const float*)d_in[10]; const float* b1 = (const float*)d_in[11];
    const float* m1 = (const float*)d_in[12]; const float* v1 = (const float*)d_in[13];
    const float* g2 = (const float*)d_in[14]; const float* b2 = (const float*)d_in[15];
    const float* m2 = (const float*)d_in[16]; const float* v2 = (const float*)d_in[17];
    float* out = (float*)d_out;
    (void)in_sizes; (void)n_in; (void)out_size;

    float *pXagg, *pXa, *pQ, *pK, *pV, *pO, *pSc, *pS, *pT;
    cudaGetSymbolAddress((void**)&pXagg, d_xagg);
    cudaGetSymbolAddress((void**)&pXa,   d_xa);
    cudaGetSymbolAddress((void**)&pQ,    d_qb);
    cudaGetSymbolAddress((void**)&pK,    d_kb);
    cudaGetSymbolAddress((void**)&pV,    d_vb);
    cudaGetSymbolAddress((void**)&pO,    d_ob);
    cudaGetSymbolAddress((void**)&pSc,   d_scores);
    cudaGetSymbolAddress((void**)&pS,    d_bns);
    cudaGetSymbolAddress((void**)&pT,    d_bnt);

    // 1) fold the two BNs
    bnfold_kernel<<<1, 256>>>(g1, b1, m1, v1, g2, b2, m2, v2);

    // 2) avg+max pooling  x[N,C,L] -> xagg[N,C,L2]
    aggregate_kernel<<<(NB * CCH * L2) / 256, 256>>>(x);

    // 3) q = Wq @ x + bq                     (per n: [256,256]@[256,4096])
    gemm_kernel<128,128,8,8,true,false><<<dim3(LF/128, CCH/128, NB), 256>>>(
        Wq, x, pQ, CCH, CCH, LF, LF, 0, (long)CCH*LF, (long)CCH*LF, 1.0f, nullptr, bq);

    // 4) xa = BN2(BN1(Wa @ xagg))            (per n: [256,256]@[256,1024], folded epilogue)
    gemm_kernel<128,128,8,8,true,false><<<dim3(L2/128, CCH/128, NB), 256>>>(
        Wa, pXagg, pXa, CCH, CCH, L2, L2, 0, (long)CCH*L2, (long)CCH*L2, 1.0f, pS, pT);

    // 5) k = Wk @ xa + bk ;  v = Wv @ xa + bv
    gemm_kernel<128,128,8,8,true,false><<<dim3(L2/128, CCH/128, NB), 256>>>(
        Wk, pXa, pK, CCH, CCH, L2, L2, 0, (long)CCH*L2, (long)CCH*L2, 1.0f, nullptr, bk);
    gemm_kernel<128,128,8,8,true,false><<<dim3(L2/128, CCH/128, NB), 256>>>(
        Wv, pXa, pV, CCH, CCH, L2, L2, 0, (long)CCH*L2, (long)CCH*L2, 1.0f, nullptr, bv);

    // 6) scores[l][m] = 0.125 * sum_e q[e][l] * k[e][m]   (per (n,h): [4096,64]x[64,1024])
    gemm_kernel<128,128,8,8,false,false><<<dim3(L2/128, LF/128, NB*HH), 256>>>(
        pQ, pK, pSc, EE, LF, L2, L2,
        (long)EE*LF, (long)EE*L2, (long)LF*L2, 0.125f, nullptr, nullptr);

    // 7) softmax along m (rows of 1024), in place
    softmax_kernel<<<NB * HH * LF, 256>>>();

    // 8) o[e][l] = sum_m v[e][m] * P[l][m]    (per (n,h): M=64, N=4096, K=1024)
    gemm_kernel<64,128,4,8,true,true><<<dim3(LF/128, 1, NB*HH), 256>>>(
        pV, pSc, pO, L2, L2, L2, LF,
        (long)EE*L2, (long)LF*L2, (long)EE*LF, 1.0f, nullptr, nullptr);

    // 9) out = Wo @ o + bo
    gemm_kernel<128,128,8,8,true,false><<<dim3(LF/128, CCH/128, NB), 256>>>(
        Wo, pO, out, CCH, CCH, LF, LF, 0, (long)CCH*LF, (long)CCH*LF, 1.0f, nullptr, bo);
}

// round 2
// speedup vs baseline: 1.7718x; 1.7718x over previous
#include <cuda_runtime.h>
#include <cuda_bf16.h>
#include <cstdint>

// Problem constants
#define NB  4
#define CCH 256
#define LF  4096
#define L2  1024
#define HH  4
#define EE  64

// ---------------- device scratch (static; no cudaMalloc) ----------------
__device__ float d_xagg[NB * CCH * L2];
__device__ float d_xa  [NB * CCH * L2];
__device__ float d_qb  [NB * CCH * LF];
__device__ float d_kb  [NB * CCH * L2];
__device__ float d_vb  [NB * CCH * L2];
__device__ float d_ob  [NB * CCH * LF];
__device__ float d_scores[(size_t)NB * HH * LF * L2]; // 256 MB
__device__ float d_bns[CCH];
__device__ float d_bnt[CCH];

// ---------------- BN fold ----------------
__global__ void bnfold_kernel(const float* __restrict__ g1, const float* __restrict__ b1,
                              const float* __restrict__ m1, const float* __restrict__ v1,
                              const float* __restrict__ g2, const float* __restrict__ b2,
                              const float* __restrict__ m2, const float* __restrict__ v2) {
    int c = threadIdx.x;
    float i1 = g1[c] * rsqrtf(v1[c] + 1e-5f);
    float c1 = b1[c] - m1[c] * i1;
    float i2 = g2[c] * rsqrtf(v2[c] + 1e-5f);
    float c2 = b2[c] - m2[c] * i2;
    d_bns[c] = i1 * i2;
    d_bnt[c] = c1 * i2 + c2;
}

// ---------------- aggregation: mean + max over groups of 4 ----------------
__global__ void aggregate_kernel(const float* __restrict__ x) {
    int i = blockIdx.x * blockDim.x + threadIdx.x;
    float4 t = reinterpret_cast<const float4*>(x)[i];
    float mx = fmaxf(fmaxf(t.x, t.y), fmaxf(t.z, t.w));
    d_xagg[i] = 0.25f * (t.x + t.y + t.z + t.w) + mx;
}

// ---------------- tf32 helpers ----------------
__device__ __forceinline__ uint32_t f2tf(float x) {
    uint32_t r;
    asm("cvt.rna.tf32.f32 %0, %1;" : "=r"(r) : "f"(x));
    return r;
}

__device__ __forceinline__ void mma_tf32(float4& c, const uint32_t a[4], const uint32_t b[2]) {
    asm volatile(
        "mma.sync.aligned.m16n8k8.row.col.f32.tf32.tf32.f32 "
        "{%0,%1,%2,%3}, {%4,%5,%6,%7}, {%8,%9}, {%0,%1,%2,%3};\n"
        : "+f"(c.x), "+f"(c.y), "+f"(c.z), "+f"(c.w)
        : "r"(a[0]), "r"(a[1]), "r"(a[2]), "r"(a[3]), "r"(b[0]), "r"(b[1]));
}

// ---------------- tf32 tensor-core GEMM ----------------
// Y[m][n] = alpha * (rs?rs[m]:1) * sum_k opA(m,k)*opB(k,n) + (rb?rb[m]:0)
//   AT=true : A stored [M][K] row-major;  AT=false: A stored [K][M]
//   BT=false: B stored [K][N];            BT=true : B stored [N][K]
// Block: BM x 128, BK=32, 256 threads = 8 warps (2 x 4), warp tile (TMt*16) x 32.
// smem pads: sA stride 36 (frag bank = 4g+tig, conflict-free),
//            sB stride 136 (frag bank = 8*tig+g, conflict-free).
template <int BM, int TMt, bool AT, bool BT>
__global__ __launch_bounds__(256) void mma_gemm(
    const float* __restrict__ A, const float* __restrict__ B, float* __restrict__ Y,
    int K, int lda, int ldb, int ldy,
    long aB, long bB, long yB, float alpha,
    const float* __restrict__ rs, const float* __restrict__ rb)
{
    __shared__ uint32_t sA[BM][36];
    __shared__ uint32_t sB[32][136];

    A += (long)blockIdx.z * aB;
    B += (long)blockIdx.z * bB;
    Y += (long)blockIdx.z * yB;

    const int tid  = threadIdx.x;
    const int lane = tid & 31;
    const int wid  = tid >> 5;
    const int wm   = wid >> 2;       // 0..1
    const int wn   = wid & 3;        // 0..3
    const int g    = lane >> 2;      // 0..7
    const int tig  = lane & 3;       // 0..3
    const int m0   = blockIdx.y * BM;
    const int n0   = blockIdx.x * 128;

    float4 acc[TMt][4];
#pragma unroll
    for (int i = 0; i < TMt; i++)
#pragma unroll
        for (int j = 0; j < 4; j++) acc[i][j] = make_float4(0.f, 0.f, 0.f, 0.f);

    for (int k0 = 0; k0 < K; k0 += 32) {
        // ---- stage A tile: sA[m][k] (tf32) ----
        if (AT) {
#pragma unroll 2
            for (int idx = tid; idx < BM * 8; idx += 256) {
                int r = idx >> 3, c4 = (idx & 7) << 2;
                float4 t = *reinterpret_cast<const float4*>(A + (long)(m0 + r) * lda + k0 + c4);
                uint32_t* d = &sA[r][c4];
                d[0] = f2tf(t.x); d[1] = f2tf(t.y); d[2] = f2tf(t.z); d[3] = f2tf(t.w);
            }
        } else {
#pragma unroll 2
            for (int idx = tid; idx < BM * 8; idx += 256) {
                int kr = idx / (BM / 4), mq = (idx % (BM / 4)) << 2;
                float4 t = *reinterpret_cast<const float4*>(A + (long)(k0 + kr) * lda + m0 + mq);
                sA[mq + 0][kr] = f2tf(t.x);
                sA[mq + 1][kr] = f2tf(t.y);
                sA[mq + 2][kr] = f2tf(t.z);
                sA[mq + 3][kr] = f2tf(t.w);
            }
        }
        // ---- stage B tile: sB[k][n] (tf32) ----
        if (!BT) {
#pragma unroll 2
            for (int idx = tid; idx < 1024; idx += 256) {
                int kr = idx >> 5, c4 = (idx & 31) << 2;
                float4 t = *reinterpret_cast<const float4*>(B + (long)(k0 + kr) * ldb + n0 + c4);
                uint32_t* d = &sB[kr][c4];
                d[0] = f2tf(t.x); d[1] = f2tf(t.y); d[2] = f2tf(t.z); d[3] = f2tf(t.w);
            }
        } else {
#pragma unroll 2
            for (int idx = tid; idx < 1024; idx += 256) {
                int nr = idx >> 3, kq = (idx & 7) << 2;
                float4 t = *reinterpret_cast<const float4*>(B + (long)(n0 + nr) * ldb + k0 + kq);
                sB[kq + 0][nr] = f2tf(t.x);
                sB[kq + 1][nr] = f2tf(t.y);
                sB[kq + 2][nr] = f2tf(t.z);
                sB[kq + 3][nr] = f2tf(t.w);
            }
        }
        __syncthreads();

#pragma unroll
        for (int kk = 0; kk < 32; kk += 8) {
            uint32_t a[TMt][4], b[4][2];
#pragma unroll
            for (int mt = 0; mt < TMt; mt++) {
                int r = wm * (TMt * 16) + mt * 16 + g;
                a[mt][0] = sA[r][kk + tig];
                a[mt][1] = sA[r + 8][kk + tig];
                a[mt][2] = sA[r][kk + tig + 4];
                a[mt][3] = sA[r + 8][kk + tig + 4];
            }
#pragma unroll
            for (int nt = 0; nt < 4; nt++) {
                int c = wn * 32 + nt * 8 + g;
                b[nt][0] = sB[kk + tig][c];
                b[nt][1] = sB[kk + tig + 4][c];
            }
#pragma unroll
            for (int mt = 0; mt < TMt; mt++)
#pragma unroll
                for (int nt = 0; nt < 4; nt++)
                    mma_tf32(acc[mt][nt], a[mt], b[nt]);
        }
        __syncthreads();
    }

    // ---- epilogue ----
#pragma unroll
    for (int mt = 0; mt < TMt; mt++) {
        int r = m0 + wm * (TMt * 16) + mt * 16 + g;
        float s0 = alpha * (rs ? rs[r] : 1.0f),     t0 = rb ? rb[r] : 0.0f;
        float s1 = alpha * (rs ? rs[r + 8] : 1.0f), t1 = rb ? rb[r + 8] : 0.0f;
#pragma unroll
        for (int nt = 0; nt < 4; nt++) {
            int c = n0 + wn * 32 + nt * 8 + 2 * tig;
            float2 lo = make_float2(acc[mt][nt].x * s0 + t0, acc[mt][nt].y * s0 + t0);
            float2 hi = make_float2(acc[mt][nt].z * s1 + t1, acc[mt][nt].w * s1 + t1);
            *reinterpret_cast<float2*>(Y + (long)r * ldy + c) = lo;
            *reinterpret_cast<float2*>(Y + (long)(r + 8) * ldy + c) = hi;
        }
    }
}

// ---------------- row softmax over 1024 elements, in place ----------------
__global__ __launch_bounds__(256) void softmax_kernel() {
    long r = blockIdx.x;
    float* p = d_scores + r * (long)L2;
    int t = threadIdx.x;
    __shared__ float red[256];

    float4 v = reinterpret_cast<float4*>(p)[t];
    float mx = fmaxf(fmaxf(v.x, v.y), fmaxf(v.z, v.w));
    red[t] = mx; __syncthreads();
#pragma unroll
    for (int s = 128; s > 0; s >>= 1) {
        if (t < s) red[t] = fmaxf(red[t], red[t + s]);
        __syncthreads();
    }
    mx = red[0];
    __syncthreads();

    v.x = __expf(v.x - mx); v.y = __expf(v.y - mx);
    v.z = __expf(v.z - mx); v.w = __expf(v.w - mx);
    float sm = v.x + v.y + v.z + v.w;
    red[t] = sm; __syncthreads();
#pragma unroll
    for (int s = 128; s > 0; s >>= 1) {
        if (t < s) red[t] += red[t + s];
        __syncthreads();
    }
    float inv = 1.0f / red[0];
    v.x *= inv; v.y *= inv; v.z *= inv; v.w *= inv;
    reinterpret_cast<float4*>(p)[t] = v;
}

// ---------------- launch ----------------
extern "C" void kernel_launch(void* const* d_in, const int* in_sizes, int n_in,
                              void* d_out, int out_size) {
    const float* x  = (const float*)d_in[0];
    const float* Wq = (const float*)d_in[1];  const float* bq = (const float*)d_in[2];
    const float* Wk = (const float*)d_in[3];  const float* bk = (const float*)d_in[4];
    const float* Wv = (const float*)d_in[5];  const float* bv = (const float*)d_in[6];
    const float* Wo = (const float*)d_in[7];  const float* bo = (const float*)d_in[8];
    const float* Wa = (const float*)d_in[9];
    const float* g1 = (const float*)d_in[10]; const float* b1 = (const float*)d_in[11];
    const float* m1 = (const float*)d_in[12]; const float* v1 = (const float*)d_in[13];
    const float* g2 = (const float*)d_in[14]; const float* b2 = (const float*)d_in[15];
    const float* m2 = (const float*)d_in[16]; const float* v2 = (const float*)d_in[17];
    float* out = (float*)d_out;
    (void)in_sizes; (void)n_in; (void)out_size;

    float *pXagg, *pXa, *pQ, *pK, *pV, *pO, *pSc, *pS, *pT;
    cudaGetSymbolAddress((void**)&pXagg, d_xagg);
    cudaGetSymbolAddress((void**)&pXa,   d_xa);
    cudaGetSymbolAddress((void**)&pQ,    d_qb);
    cudaGetSymbolAddress((void**)&pK,    d_kb);
    cudaGetSymbolAddress((void**)&pV,    d_vb);
    cudaGetSymbolAddress((void**)&pO,    d_ob);
    cudaGetSymbolAddress((void**)&pSc,   d_scores);
    cudaGetSymbolAddress((void**)&pS,    d_bns);
    cudaGetSymbolAddress((void**)&pT,    d_bnt);

    // 1) fold the two BNs
    bnfold_kernel<<<1, 256>>>(g1, b1, m1, v1, g2, b2, m2, v2);

    // 2) avg+max pooling
    aggregate_kernel<<<(NB * CCH * L2) / 256, 256>>>(x);

    // 3) q = Wq @ x + bq          [256,256]@[256,4096] per n
    mma_gemm<128, 4, true, false><<<dim3(LF / 128, CCH / 128, NB), 256>>>(
        Wq, x, pQ, CCH, CCH, LF, LF, 0, (long)CCH * LF, (long)CCH * LF, 1.0f, nullptr, bq);

    // 4) xa = BN2(BN1(Wa @ xagg)) [256,256]@[256,1024] per n, folded epilogue
    mma_gemm<128, 4, true, false><<<dim3(L2 / 128, CCH / 128, NB), 256>>>(
        Wa, pXagg, pXa, CCH, CCH, L2, L2, 0, (long)CCH * L2, (long)CCH * L2, 1.0f, pS, pT);

    // 5) k, v projections
    mma_gemm<128, 4, true, false><<<dim3(L2 / 128, CCH / 128, NB), 256>>>(
        Wk, pXa, pK, CCH, CCH, L2, L2, 0, (long)CCH * L2, (long)CCH * L2, 1.0f, nullptr, bk);
    mma_gemm<128, 4, true, false><<<dim3(L2 / 128, CCH / 128, NB), 256>>>(
        Wv, pXa, pV, CCH, CCH, L2, L2, 0, (long)CCH * L2, (long)CCH * L2, 1.0f, nullptr, bv);

    // 6) scores[l][m] = 0.125 * sum_e q[e][l] k[e][m]   per (n,h): [4096,64]x[64,1024]
    mma_gemm<128, 4, false, false><<<dim3(L2 / 128, LF / 128, NB * HH), 256>>>(
        pQ, pK, pSc, EE, LF, L2, L2,
        (long)EE * LF, (long)EE * L2, (long)LF * L2, 0.125f, nullptr, nullptr);

    // 7) softmax rows of 1024, in place
    softmax_kernel<<<NB * HH * LF, 256>>>();

    // 8) o[e][l] = sum_m v[e][m] * P[l][m]   per (n,h): M=64, N=4096, K=1024
    mma_gemm<64, 2, true, true><<<dim3(LF / 128, 1, NB * HH), 256>>>(
        pV, pSc, pO, L2, L2, L2, LF,
        (long)EE * L2, (long)LF * L2, (long)EE * LF, 1.0f, nullptr, nullptr);

    // 9) out = Wo @ o + bo
    mma_gemm<128, 4, true, false><<<dim3(LF / 128, CCH / 128, NB), 256>>>(
        Wo, pO, out, CCH, CCH, LF, LF, 0, (long)CCH * LF, (long)CCH * LF, 1.0f, nullptr, bo);
}

// round 4
// speedup vs baseline: 2.6981x; 1.5228x over previous
#include <cuda_runtime.h>
#include <cuda_bf16.h>
#include <cstdint>

// Problem constants
#define NB  4
#define CCH 256
#define LF  4096
#define L2  1024
#define HH  4
#define EE  64

// ---------------- device scratch (static; no cudaMalloc) ----------------
__device__ float d_xagg[NB * CCH * L2];
__device__ float d_xa  [NB * CCH * L2];
__device__ float d_qb  [NB * CCH * LF];
__device__ float d_kb  [NB * CCH * L2];
__device__ float d_vb  [NB * CCH * L2];
__device__ float d_ob  [NB * CCH * LF];
__device__ float d_bns[CCH];
__device__ float d_bnt[CCH];

// ---------------- BN fold ----------------
__global__ void bnfold_kernel(const float* __restrict__ g1, const float* __restrict__ b1,
                              const float* __restrict__ m1, const float* __restrict__ v1,
                              const float* __restrict__ g2, const float* __restrict__ b2,
                              const float* __restrict__ m2, const float* __restrict__ v2) {
    int c = threadIdx.x;
    float i1 = g1[c] * rsqrtf(v1[c] + 1e-5f);
    float c1 = b1[c] - m1[c] * i1;
    float i2 = g2[c] * rsqrtf(v2[c] + 1e-5f);
    float c2 = b2[c] - m2[c] * i2;
    d_bns[c] = i1 * i2;
    d_bnt[c] = c1 * i2 + c2;
}

// ---------------- aggregation: mean + max over groups of 4 ----------------
__global__ void aggregate_kernel(const float* __restrict__ x) {
    int i = blockIdx.x * blockDim.x + threadIdx.x;
    float4 t = reinterpret_cast<const float4*>(x)[i];
    float mx = fmaxf(fmaxf(t.x, t.y), fmaxf(t.z, t.w));
    d_xagg[i] = 0.25f * (t.x + t.y + t.z + t.w) + mx;
}

// ---------------- tf32 / cp.async helpers ----------------
__device__ __forceinline__ uint32_t f2tf(float x) {
    uint32_t r;
    asm("cvt.rna.tf32.f32 %0, %1;" : "=r"(r) : "f"(x));
    return r;
}
__device__ __forceinline__ void mma_tf32(float4& c, const uint32_t a[4], const uint32_t b[2]) {
    asm volatile(
        "mma.sync.aligned.m16n8k8.row.col.f32.tf32.tf32.f32 "
        "{%0,%1,%2,%3}, {%4,%5,%6,%7}, {%8,%9}, {%0,%1,%2,%3};\n"
        : "+f"(c.x), "+f"(c.y), "+f"(c.z), "+f"(c.w)
        : "r"(a[0]), "r"(a[1]), "r"(a[2]), "r"(a[3]), "r"(b[0]), "r"(b[1]));
}
__device__ __forceinline__ uint32_t stou(const void* p) {
    return (uint32_t)__cvta_generic_to_shared(p);
}
__device__ __forceinline__ void cpa16(uint32_t dst, const void* src) {
    asm volatile("cp.async.cg.shared.global [%0], [%1], 16;\n" :: "r"(dst), "l"(src));
}
__device__ __forceinline__ void cp_commit() { asm volatile("cp.async.commit_group;\n"); }
template <int N> __device__ __forceinline__ void cp_wait() {
    asm volatile("cp.async.wait_group %0;\n" :: "n"(N));
}

// 64-row x 128-float tile load, gmem row stride gstride, smem row stride sld (floats)
__device__ __forceinline__ void load_tile_async(const float* gbase, long gstride,
                                                float* sbase, int sld) {
    uint32_t s0 = stou(sbase);
    int tid = threadIdx.x;
#pragma unroll
    for (int i = 0; i < 8; i++) {
        int idx = tid + i * 256;
        int r = idx >> 5, c = (idx & 31) << 2;
        cpa16(s0 + (uint32_t)(r * sld + c) * 4u, gbase + (long)r * gstride + c);
    }
}

// ---------------- fused flash attention ----------------
// Per (n,h): S = (Q^T K)/8, P = softmax_row(S), O = V P^T, O written [e][l].
// Q:[64][LF], K,V:[64][L2] per head.  CTA: 128 query cols, loop over 8 key tiles of 128.
// 8 warps as 2x4 (wm x wn).  QK: warp tile 64l x 32m.  PV: warp tile 64l x 16e.
#define SQ_OFF 0
#define SK_OFF 8704
#define SV_OFF 26112
#define SP_OFF 34560
#define RMAX_OFF 51456
#define RSUM_OFF 51584
#define RSCL_OFF 51712
#define PART_OFF 51840
#define FLASH_SMEM_BYTES ((52352) * 4)

__global__ __launch_bounds__(256, 1) void flash_kernel(
    const float* __restrict__ Q, const float* __restrict__ K,
    const float* __restrict__ V, float* __restrict__ O)
{
    extern __shared__ float smem[];
    float* sQ = smem + SQ_OFF;    // [64][136] (becomes tf32 bits after cvt pass)
    float* sK = smem + SK_OFF;    // [2][64][136] fp32
    float* sV = smem + SV_OFF;    // [64][132] fp32
    float* sP = smem + SP_OFF;    // [128][132] fp32
    float* rmax = smem + RMAX_OFF;
    float* rsum = smem + RSUM_OFF;
    float* rscl = smem + RSCL_OFF;
    float* part = smem + PART_OFF; // [128][4]

    const int tid  = threadIdx.x;
    const int lane = tid & 31;
    const int wid  = tid >> 5;
    const int wm   = wid >> 2;      // 0..1
    const int wn   = wid & 3;       // 0..3
    const int g    = lane >> 2;     // 0..7
    const int tig  = lane & 3;      // 0..3

    const int l0 = blockIdx.x * 128;
    const int nh = blockIdx.y;
    const int n  = nh >> 2, h = nh & 3;
    const float* qb = Q + ((long)n * CCH + h * 64) * LF + l0;
    const float* kb = K + ((long)n * CCH + h * 64) * L2;
    const float* vb = V + ((long)n * CCH + h * 64) * L2;
    float*       ob = O + ((long)n * CCH + h * 64) * LF + l0;

    if (tid < 128) { rmax[tid] = -1e30f; rsum[tid] = 0.0f; }

    // prologue: Q (group0), K0 (group1)
    load_tile_async(qb, LF, sQ, 136);  cp_commit();
    load_tile_async(kb, L2, sK, 136);  cp_commit();

    // convert Q in place to tf32, fold 1/sqrt(E)=0.125 (exact power of 2)
    cp_wait<1>();
    __syncthreads();
    {
        uint32_t* q32 = reinterpret_cast<uint32_t*>(sQ);
        for (int i = tid; i < 64 * 128; i += 256) {
            int r = i >> 7, c = i & 127;
            q32[r * 136 + c] = f2tf(0.125f * sQ[r * 136 + c]);
        }
    }
    __syncthreads();

    const uint32_t* q32 = reinterpret_cast<const uint32_t*>(sQ);

    float4 accO[4][2];
#pragma unroll
    for (int mt = 0; mt < 4; mt++)
#pragma unroll
        for (int nt = 0; nt < 2; nt++) accO[mt][nt] = make_float4(0.f, 0.f, 0.f, 0.f);

#pragma unroll
    for (int t = 0; t < 8; t++) {
        const float* sKb = sK + (t & 1) * 8704;

        // prefetch V_t and K_{t+1}
        load_tile_async(vb + t * 128, L2, sV, 132);  cp_commit();
        if (t < 7) { load_tile_async(kb + (t + 1) * 128, L2, sK + ((t + 1) & 1) * 8704, 136); cp_commit(); }

        // wait for K_t
        if (t < 7) cp_wait<2>(); else cp_wait<1>();
        __syncthreads();

        // ---- S = Q^T K (tile) ----
        float4 accS[4][4];
#pragma unroll
        for (int mt = 0; mt < 4; mt++)
#pragma unroll
            for (int nt = 0; nt < 4; nt++) accS[mt][nt] = make_float4(0.f, 0.f, 0.f, 0.f);

#pragma unroll
        for (int kk = 0; kk < 8; kk++) {
            uint32_t a[4][4], b[4][2];
#pragma unroll
            for (int mt = 0; mt < 4; mt++) {
                int l = wm * 64 + mt * 16 + g;
                int e = kk * 8 + tig;
                a[mt][0] = q32[e * 136 + l];
                a[mt][1] = q32[e * 136 + l + 8];
                a[mt][2] = q32[(e + 4) * 136 + l];
                a[mt][3] = q32[(e + 4) * 136 + l + 8];
            }
#pragma unroll
            for (int nt = 0; nt < 4; nt++) {
                int m = wn * 32 + nt * 8 + g;
                b[nt][0] = f2tf(sKb[(kk * 8 + tig) * 136 + m]);
                b[nt][1] = f2tf(sKb[(kk * 8 + tig + 4) * 136 + m]);
            }
#pragma unroll
            for (int mt = 0; mt < 4; mt++)
#pragma unroll
                for (int nt = 0; nt < 4; nt++)
                    mma_tf32(accS[mt][nt], a[mt], b[nt]);
        }

        // ---- online softmax: per-row tile max ----
        {
            float pm[4][2];
#pragma unroll
            for (int mt = 0; mt < 4; mt++) {
                float lo = -1e30f, hi = -1e30f;
#pragma unroll
                for (int nt = 0; nt < 4; nt++) {
                    lo = fmaxf(lo, fmaxf(accS[mt][nt].x, accS[mt][nt].y));
                    hi = fmaxf(hi, fmaxf(accS[mt][nt].z, accS[mt][nt].w));
                }
                pm[mt][0] = lo; pm[mt][1] = hi;
            }
#pragma unroll
            for (int mt = 0; mt < 4; mt++)
#pragma unroll
                for (int hh = 0; hh < 2; hh++) {
                    float v = pm[mt][hh];
                    v = fmaxf(v, __shfl_xor_sync(0xffffffffu, v, 1));
                    v = fmaxf(v, __shfl_xor_sync(0xffffffffu, v, 2));
                    if (tig == 0) part[(wm * 64 + mt * 16 + hh * 8 + g) * 4 + wn] = v;
                }
        }
        __syncthreads();
        if (tid < 128) {
            int r = tid;
            float tm = fmaxf(fmaxf(part[r * 4 + 0], part[r * 4 + 1]),
                             fmaxf(part[r * 4 + 2], part[r * 4 + 3]));
            float om = rmax[r];
            float nm = fmaxf(om, tm);
            float sc = __expf(om - nm);
            rmax[r] = nm;
            rscl[r] = sc;
            rsum[r] *= sc;
        }
        __syncthreads();

        // ---- P = exp(S - rowmax), partial row sums, stage P to smem ----
        {
            float ps[4][2];
#pragma unroll
            for (int mt = 0; mt < 4; mt++) {
#pragma unroll
                for (int hh = 0; hh < 2; hh++) {
                    int row = wm * 64 + mt * 16 + hh * 8 + g;
                    float nm = rmax[row];
                    float s = 0.0f;
#pragma unroll
                    for (int nt = 0; nt < 4; nt++) {
                        float v0 = hh ? accS[mt][nt].z : accS[mt][nt].x;
                        float v1 = hh ? accS[mt][nt].w : accS[mt][nt].y;
                        float e0 = __expf(v0 - nm);
                        float e1 = __expf(v1 - nm);
                        s += e0 + e1;
                        int col = wn * 32 + nt * 8 + 2 * tig;
                        sP[row * 132 + col]     = e0;
                        sP[row * 132 + col + 1] = e1;
                    }
                    ps[mt][hh] = s;
                }
            }
#pragma unroll
            for (int mt = 0; mt < 4; mt++)
#pragma unroll
                for (int hh = 0; hh < 2; hh++) {
                    float v = ps[mt][hh];
                    v += __shfl_xor_sync(0xffffffffu, v, 1);
                    v += __shfl_xor_sync(0xffffffffu, v, 2);
                    if (tig == 0) part[(wm * 64 + mt * 16 + hh * 8 + g) * 4 + wn] = v;
                }
        }
        __syncthreads();
        if (tid < 128) {
            rsum[tid] += part[tid * 4 + 0] + part[tid * 4 + 1] +
                         part[tid * 4 + 2] + part[tid * 4 + 3];
        }

        // ---- rescale running O ----
#pragma unroll
        for (int mt = 0; mt < 4; mt++) {
            int row = wm * 64 + mt * 16 + g;
            float s0 = rscl[row], s1 = rscl[row + 8];
#pragma unroll
            for (int nt = 0; nt < 2; nt++) {
                accO[mt][nt].x *= s0; accO[mt][nt].y *= s0;
                accO[mt][nt].z *= s1; accO[mt][nt].w *= s1;
            }
        }

        // ---- wait for V_t, then O += P V^T ----
        if (t < 7) cp_wait<1>(); else cp_wait<0>();
        __syncthreads();

#pragma unroll 4
        for (int kk = 0; kk < 16; kk++) {
            uint32_t a[4][4], b[2][2];
#pragma unroll
            for (int mt = 0; mt < 4; mt++) {
                int row = wm * 64 + mt * 16 + g;
                int m = kk * 8 + tig;
                a[mt][0] = f2tf(sP[row * 132 + m]);
                a[mt][1] = f2tf(sP[(row + 8) * 132 + m]);
                a[mt][2] = f2tf(sP[row * 132 + m + 4]);
                a[mt][3] = f2tf(sP[(row + 8) * 132 + m + 4]);
            }
#pragma unroll
            for (int nt = 0; nt < 2; nt++) {
                int e = wn * 16 + nt * 8 + g;
                b[nt][0] = f2tf(sV[e * 132 + kk * 8 + tig]);
                b[nt][1] = f2tf(sV[e * 132 + kk * 8 + tig + 4]);
            }
#pragma unroll
            for (int mt = 0; mt < 4; mt++)
#pragma unroll
                for (int nt = 0; nt < 2; nt++)
                    mma_tf32(accO[mt][nt], a[mt], b[nt]);
        }
        __syncthreads();  // protect sV / sK buffers for next iteration
    }

    // ---- epilogue: O[e][l] = accO / rowsum ----
#pragma unroll
    for (int mt = 0; mt < 4; mt++) {
        int row = wm * 64 + mt * 16 + g;
        float i0 = 1.0f / rsum[row];
        float i1 = 1.0f / rsum[row + 8];
#pragma unroll
        for (int nt = 0; nt < 2; nt++) {
            int e = wn * 16 + nt * 8 + 2 * tig;
            ob[(long)e * LF + row]           = accO[mt][nt].x * i0;
            ob[(long)(e + 1) * LF + row]     = accO[mt][nt].y * i0;
            ob[(long)e * LF + row + 8]       = accO[mt][nt].z * i1;
            ob[(long)(e + 1) * LF + row + 8] = accO[mt][nt].w * i1;
        }
    }
}

// ---------------- tf32 tensor-core GEMM (projections) ----------------
template <int BM, int TMt, bool AT, bool BT>
__global__ __launch_bounds__(256) void mma_gemm(
    const float* __restrict__ A, const float* __restrict__ B, float* __restrict__ Y,
    int K, int lda, int ldb, int ldy,
    long aB, long bB, long yB, float alpha,
    const float* __restrict__ rs, const float* __restrict__ rb)
{
    __shared__ uint32_t sA[BM][36];
    __shared__ uint32_t sB[32][136];

    A += (long)blockIdx.z * aB;
    B += (long)blockIdx.z * bB;
    Y += (long)blockIdx.z * yB;

    const int tid  = threadIdx.x;
    const int lane = tid & 31;
    const int wid  = tid >> 5;
    const int wm   = wid >> 2;
    const int wn   = wid & 3;
    const int g    = lane >> 2;
    const int tig  = lane & 3;
    const int m0   = blockIdx.y * BM;
    const int n0   = blockIdx.x * 128;

    float4 acc[TMt][4];
#pragma unroll
    for (int i = 0; i < TMt; i++)
#pragma unroll
        for (int j = 0; j < 4; j++) acc[i][j] = make_float4(0.f, 0.f, 0.f, 0.f);

    for (int k0 = 0; k0 < K; k0 += 32) {
        if (AT) {
#pragma unroll 2
            for (int idx = tid; idx < BM * 8; idx += 256) {
                int r = idx >> 3, c4 = (idx & 7) << 2;
                float4 t = *reinterpret_cast<const float4*>(A + (long)(m0 + r) * lda + k0 + c4);
                uint32_t* d = &sA[r][c4];
                d[0] = f2tf(t.x); d[1] = f2tf(t.y); d[2] = f2tf(t.z); d[3] = f2tf(t.w);
            }
        } else {
#pragma unroll 2
            for (int idx = tid; idx < BM * 8; idx += 256) {
                int kr = idx / (BM / 4), mq = (idx % (BM / 4)) << 2;
                float4 t = *reinterpret_cast<const float4*>(A + (long)(k0 + kr) * lda + m0 + mq);
                sA[mq + 0][kr] = f2tf(t.x);
                sA[mq + 1][kr] = f2tf(t.y);
                sA[mq + 2][kr] = f2tf(t.z);
                sA[mq + 3][kr] = f2tf(t.w);
            }
        }
        if (!BT) {
#pragma unroll 2
            for (int idx = tid; idx < 1024; idx += 256) {
                int kr = idx >> 5, c4 = (idx & 31) << 2;
                float4 t = *reinterpret_cast<const float4*>(B + (long)(k0 + kr) * ldb + n0 + c4);
                uint32_t* d = &sB[kr][c4];
                d[0] = f2tf(t.x); d[1] = f2tf(t.y); d[2] = f2tf(t.z); d[3] = f2tf(t.w);
            }
        } else {
#pragma unroll 2
            for (int idx = tid; idx < 1024; idx += 256) {
                int nr = idx >> 3, kq = (idx & 7) << 2;
                float4 t = *reinterpret_cast<const float4*>(B + (long)(n0 + nr) * ldb + k0 + kq);
                sB[kq + 0][nr] = f2tf(t.x);
                sB[kq + 1][nr] = f2tf(t.y);
                sB[kq + 2][nr] = f2tf(t.z);
                sB[kq + 3][nr] = f2tf(t.w);
            }
        }
        __syncthreads();

#pragma unroll
        for (int kk = 0; kk < 32; kk += 8) {
            uint32_t a[TMt][4], b[4][2];
#pragma unroll
            for (int mt = 0; mt < TMt; mt++) {
                int r = wm * (TMt * 16) + mt * 16 + g;
                a[mt][0] = sA[r][kk + tig];
                a[mt][1] = sA[r + 8][kk + tig];
                a[mt][2] = sA[r][kk + tig + 4];
                a[mt][3] = sA[r + 8][kk + tig + 4];
            }
#pragma unroll
            for (int nt = 0; nt < 4; nt++) {
                int c = wn * 32 + nt * 8 + g;
                b[nt][0] = sB[kk + tig][c];
                b[nt][1] = sB[kk + tig + 4][c];
            }
#pragma unroll
            for (int mt = 0; mt < TMt; mt++)
#pragma unroll
                for (int nt = 0; nt < 4; nt++)
                    mma_tf32(acc[mt][nt], a[mt], b[nt]);
        }
        __syncthreads();
    }

#pragma unroll
    for (int mt = 0; mt < TMt; mt++) {
        int r = m0 + wm * (TMt * 16) + mt * 16 + g;
        float s0 = alpha * (rs ? rs[r] : 1.0f),     t0 = rb ? rb[r] : 0.0f;
        float s1 = alpha * (rs ? rs[r + 8] : 1.0f), t1 = rb ? rb[r + 8] : 0.0f;
#pragma unroll
        for (int nt = 0; nt < 4; nt++) {
            int c = n0 + wn * 32 + nt * 8 + 2 * tig;
            float2 lo = make_float2(acc[mt][nt].x * s0 + t0, acc[mt][nt].y * s0 + t0);
            float2 hi = make_float2(acc[mt][nt].z * s1 + t1, acc[mt][nt].w * s1 + t1);
            *reinterpret_cast<float2*>(Y + (long)r * ldy + c) = lo;
            *reinterpret_cast<float2*>(Y + (long)(r + 8) * ldy + c) = hi;
        }
    }
}

// ---------------- launch ----------------
extern "C" void kernel_launch(void* const* d_in, const int* in_sizes, int n_in,
                              void* d_out, int out_size) {
    const float* x  = (const float*)d_in[0];
    const float* Wq = (const float*)d_in[1];  const float* bq = (const float*)d_in[2];
    const float* Wk = (const float*)d_in[3];  const float* bk = (const float*)d_in[4];
    const float* Wv = (const float*)d_in[5];  const float* bv = (const float*)d_in[6];
    const float* Wo = (const float*)d_in[7];  const float* bo = (const float*)d_in[8];
    const float* Wa = (const float*)d_in[9];
    const float* g1 = (const float*)d_in[10]; const float* b1 = (const float*)d_in[11];
    const float* m1 = (const float*)d_in[12]; const float* v1 = (const float*)d_in[13];
    const float* g2 = (const float*)d_in[14]; const float* b2 = (const float*)d_in[15];
    const float* m2 = (const float*)d_in[16]; const float* v2 = (const float*)d_in[17];
    float* out = (float*)d_out;
    (void)in_sizes; (void)n_in; (void)out_size;

    float *pXagg, *pXa, *pQ, *pK, *pV, *pO, *pS, *pT;
    cudaGetSymbolAddress((void**)&pXagg, d_xagg);
    cudaGetSymbolAddress((void**)&pXa,   d_xa);
    cudaGetSymbolAddress((void**)&pQ,    d_qb);
    cudaGetSymbolAddress((void**)&pK,    d_kb);
    cudaGetSymbolAddress((void**)&pV,    d_vb);
    cudaGetSymbolAddress((void**)&pO,    d_ob);
    cudaGetSymbolAddress((void**)&pS,    d_bns);
    cudaGetSymbolAddress((void**)&pT,    d_bnt);

    cudaFuncSetAttribute(flash_kernel, cudaFuncAttributeMaxDynamicSharedMemorySize,
                         FLASH_SMEM_BYTES);

    // 1) fold the two BNs
    bnfold_kernel<<<1, 256>>>(g1, b1, m1, v1, g2, b2, m2, v2);

    // 2) avg+max pooling
    aggregate_kernel<<<(NB * CCH * L2) / 256, 256>>>(x);

    // 3) q = Wq @ x + bq
    mma_gemm<128, 4, true, false><<<dim3(LF / 128, CCH / 128, NB), 256>>>(
        Wq, x, pQ, CCH, CCH, LF, LF, 0, (long)CCH * LF, (long)CCH * LF, 1.0f, nullptr, bq);

    // 4) xa = BN2(BN1(Wa @ xagg))
    mma_gemm<128, 4, true, false><<<dim3(L2 / 128, CCH / 128, NB), 256>>>(
        Wa, pXagg, pXa, CCH, CCH, L2, L2, 0, (long)CCH * L2, (long)CCH * L2, 1.0f, pS, pT);

    // 5) k, v projections
    mma_gemm<128, 4, true, false><<<dim3(L2 / 128, CCH / 128, NB), 256>>>(
        Wk, pXa, pK, CCH, CCH, L2, L2, 0, (long)CCH * L2, (long)CCH * L2, 1.0f, nullptr, bk);
    mma_gemm<128, 4, true, false><<<dim3(L2 / 128, CCH / 128, NB), 256>>>(
        Wv, pXa, pV, CCH, CCH, L2, L2, 0, (long)CCH * L2, (long)CCH * L2, 1.0f, nullptr, bv);

    // 6) fused attention: scores + softmax + PV, O written [C][L]
    flash_kernel<<<dim3(LF / 128, NB * HH), 256, FLASH_SMEM_BYTES>>>(pQ, pK, pV, pO);

    // 7) out = Wo @ o + bo
    mma_gemm<128, 4, true, false><<<dim3(LF / 128, CCH / 128, NB), 256>>>(
        Wo, pO, out, CCH, CCH, LF, LF, 0, (long)CCH * LF, (long)CCH * LF, 1.0f, nullptr, bo);
}

// round 5
// speedup vs baseline: 3.1061x; 1.1512x over previous
#include <cuda_runtime.h>
#include <cuda_bf16.h>
#include <cstdint>

// Problem constants
#define NB  4
#define CCH 256
#define LF  4096
#define L2  1024
#define HH  4
#define EE  64

// ---------------- device scratch (static; no cudaMalloc) ----------------
__device__ float d_xagg[NB * CCH * L2];
__device__ float d_xa  [NB * CCH * L2];
__device__ float d_qb  [NB * CCH * LF];
__device__ float d_kb  [NB * CCH * L2];
__device__ float d_vb  [NB * CCH * L2];
__device__ float d_ob  [NB * CCH * LF];
__device__ float d_bns[CCH];
__device__ float d_bnt[CCH];

// ---------------- BN fold ----------------
__global__ void bnfold_kernel(const float* __restrict__ g1, const float* __restrict__ b1,
                              const float* __restrict__ m1, const float* __restrict__ v1,
                              const float* __restrict__ g2, const float* __restrict__ b2,
                              const float* __restrict__ m2, const float* __restrict__ v2) {
    int c = threadIdx.x;
    float i1 = g1[c] * rsqrtf(v1[c] + 1e-5f);
    float c1 = b1[c] - m1[c] * i1;
    float i2 = g2[c] * rsqrtf(v2[c] + 1e-5f);
    float c2 = b2[c] - m2[c] * i2;
    d_bns[c] = i1 * i2;
    d_bnt[c] = c1 * i2 + c2;
}

// ---------------- aggregation: mean + max over groups of 4 ----------------
__global__ void aggregate_kernel(const float* __restrict__ x) {
    int i = blockIdx.x * blockDim.x + threadIdx.x;
    float4 t = reinterpret_cast<const float4*>(x)[i];
    float mx = fmaxf(fmaxf(t.x, t.y), fmaxf(t.z, t.w));
    d_xagg[i] = 0.25f * (t.x + t.y + t.z + t.w) + mx;
}

// ---------------- tf32 / cp.async helpers ----------------
__device__ __forceinline__ uint32_t f2tf(float x) {
    uint32_t r;
    asm("cvt.rna.tf32.f32 %0, %1;" : "=r"(r) : "f"(x));
    return r;
}
__device__ __forceinline__ void mma_tf32(float4& c, const uint32_t a[4], const uint32_t b[2]) {
    asm volatile(
        "mma.sync.aligned.m16n8k8.row.col.f32.tf32.tf32.f32 "
        "{%0,%1,%2,%3}, {%4,%5,%6,%7}, {%8,%9}, {%0,%1,%2,%3};\n"
        : "+f"(c.x), "+f"(c.y), "+f"(c.z), "+f"(c.w)
        : "r"(a[0]), "r"(a[1]), "r"(a[2]), "r"(a[3]), "r"(b[0]), "r"(b[1]));
}
__device__ __forceinline__ uint32_t stou(const void* p) {
    return (uint32_t)__cvta_generic_to_shared(p);
}
__device__ __forceinline__ void cpa16(uint32_t dst, const void* src) {
    asm volatile("cp.async.cg.shared.global [%0], [%1], 16;\n" :: "r"(dst), "l"(src));
}
__device__ __forceinline__ void cp_commit() { asm volatile("cp.async.commit_group;\n"); }
template <int N> __device__ __forceinline__ void cp_wait() {
    asm volatile("cp.async.wait_group %0;\n" :: "n"(N));
}

// ---------------- cp.async double-buffered tf32 GEMM ----------------
// Y[m][n] = alpha*(rs?rs[m]:1)*sum_k A[m][k]*B[k][n] + (rb?rb[m]:0)
// A row-major [M][K] (lda), B [K][N] (ldb).  256 thr = 8 warps (2 x 4).
// Warp tile (TMt*16) x 32.  BK=32, 2 smem stages, fp32 in smem, cvt at frag load.
template <int BM, int TMt>
__global__ __launch_bounds__(256) void mma_gemm(
    const float* __restrict__ A, const float* __restrict__ B, float* __restrict__ Y,
    int K, int lda, int ldb, int ldy,
    long aB, long bB, long yB, float alpha,
    const float* __restrict__ rs, const float* __restrict__ rb)
{
    extern __shared__ float sm[];
    float* sA = sm;                 // [2][BM][36]
    float* sB = sm + 2 * BM * 36;   // [2][32][136]

    A += (long)blockIdx.z * aB;
    B += (long)blockIdx.z * bB;
    Y += (long)blockIdx.z * yB;

    const int tid  = threadIdx.x;
    const int lane = tid & 31;
    const int wid  = tid >> 5;
    const int wm   = wid >> 2;
    const int wn   = wid & 3;
    const int g    = lane >> 2;
    const int tig  = lane & 3;
    const int m0   = blockIdx.y * BM;
    const int n0   = blockIdx.x * 128;

    float4 acc[TMt][4];
#pragma unroll
    for (int i = 0; i < TMt; i++)
#pragma unroll
        for (int j = 0; j < 4; j++) acc[i][j] = make_float4(0.f, 0.f, 0.f, 0.f);

    const int ntiles = K >> 5;

    auto prefetch = [&](int t, int buf) {
        float* dA = sA + buf * BM * 36;
        float* dB = sB + buf * 32 * 136;
#pragma unroll
        for (int i = tid; i < BM * 8; i += 256) {
            int r = i >> 3, c = (i & 7) << 2;
            cpa16(stou(dA + r * 36 + c), A + (long)(m0 + r) * lda + (t << 5) + c);
        }
#pragma unroll
        for (int i = tid; i < 1024; i += 256) {
            int r = i >> 5, c = (i & 31) << 2;
            cpa16(stou(dB + r * 136 + c), B + (long)((t << 5) + r) * ldb + n0 + c);
        }
    };

    prefetch(0, 0);
    cp_commit();

    for (int t = 0; t < ntiles; t++) {
        const int buf = t & 1;
        if (t + 1 < ntiles) {
            prefetch(t + 1, buf ^ 1);
            cp_commit();
            cp_wait<1>();
        } else {
            cp_wait<0>();
        }
        __syncthreads();

        const float* cA = sA + buf * BM * 36;
        const float* cB = sB + buf * 32 * 136;

#pragma unroll
        for (int kk = 0; kk < 32; kk += 8) {
            uint32_t a[TMt][4], b[4][2];
#pragma unroll
            for (int mt = 0; mt < TMt; mt++) {
                int r = wm * (TMt * 16) + mt * 16 + g;
                a[mt][0] = f2tf(cA[r * 36 + kk + tig]);
                a[mt][1] = f2tf(cA[(r + 8) * 36 + kk + tig]);
                a[mt][2] = f2tf(cA[r * 36 + kk + tig + 4]);
                a[mt][3] = f2tf(cA[(r + 8) * 36 + kk + tig + 4]);
            }
#pragma unroll
            for (int nt = 0; nt < 4; nt++) {
                int c = wn * 32 + nt * 8 + g;
                b[nt][0] = f2tf(cB[(kk + tig) * 136 + c]);
                b[nt][1] = f2tf(cB[(kk + tig + 4) * 136 + c]);
            }
#pragma unroll
            for (int mt = 0; mt < TMt; mt++)
#pragma unroll
                for (int nt = 0; nt < 4; nt++)
                    mma_tf32(acc[mt][nt], a[mt], b[nt]);
        }
        __syncthreads();
    }

#pragma unroll
    for (int mt = 0; mt < TMt; mt++) {
        int r = m0 + wm * (TMt * 16) + mt * 16 + g;
        float s0 = alpha * (rs ? rs[r] : 1.0f),     t0 = rb ? rb[r] : 0.0f;
        float s1 = alpha * (rs ? rs[r + 8] : 1.0f), t1 = rb ? rb[r + 8] : 0.0f;
#pragma unroll
        for (int nt = 0; nt < 4; nt++) {
            int c = n0 + wn * 32 + nt * 8 + 2 * tig;
            float2 lo = make_float2(acc[mt][nt].x * s0 + t0, acc[mt][nt].y * s0 + t0);
            float2 hi = make_float2(acc[mt][nt].z * s1 + t1, acc[mt][nt].w * s1 + t1);
            *reinterpret_cast<float2*>(Y + (long)r * ldy + c) = lo;
            *reinterpret_cast<float2*>(Y + (long)(r + 8) * ldy + c) = hi;
        }
    }
}

#define GEMM128_SMEM ((2 * 128 * 36 + 2 * 32 * 136) * 4)
#define GEMM64_SMEM  ((2 * 64 * 36 + 2 * 32 * 136) * 4)

// ---------------- fused flash attention ----------------
#define SQ_OFF 0
#define SK_OFF 8704
#define SV_OFF 26112
#define SP_OFF 34560
#define RMAX_OFF 51456
#define RSUM_OFF 51584
#define RSCL_OFF 51712
#define PART_OFF 51840
#define FLASH_SMEM_BYTES ((52352) * 4)

__global__ __launch_bounds__(256, 1) void flash_kernel(
    const float* __restrict__ Q, const float* __restrict__ K,
    const float* __restrict__ V, float* __restrict__ O)
{
    extern __shared__ float smem[];
    float* sQ = smem + SQ_OFF;    // [64][136] -> tf32 bits after cvt pass
    float* sK = smem + SK_OFF;    // [2][64][136] fp32
    float* sV = smem + SV_OFF;    // [64][132] fp32
    uint32_t* sP = reinterpret_cast<uint32_t*>(smem + SP_OFF); // [128][132] tf32 bits
    float* rmax = smem + RMAX_OFF;
    float* rsum = smem + RSUM_OFF;
    float* rscl = smem + RSCL_OFF;
    float* part = smem + PART_OFF; // [128][4]

    const int tid  = threadIdx.x;
    const int lane = tid & 31;
    const int wid  = tid >> 5;
    const int wm   = wid >> 2;
    const int wn   = wid & 3;
    const int g    = lane >> 2;
    const int tig  = lane & 3;

    const int l0 = blockIdx.x * 128;
    const int nh = blockIdx.y;
    const int n  = nh >> 2, h = nh & 3;
    const float* qb = Q + ((long)n * CCH + h * 64) * LF + l0;
    const float* kb = K + ((long)n * CCH + h * 64) * L2;
    const float* vb = V + ((long)n * CCH + h * 64) * L2;
    float*       ob = O + ((long)n * CCH + h * 64) * LF + l0;

    if (tid < 128) { rmax[tid] = -1e30f; rsum[tid] = 0.0f; }

    // prologue loads
    {
        uint32_t s0 = stou(sQ);
#pragma unroll
        for (int i = 0; i < 8; i++) {
            int idx = tid + i * 256;
            int r = idx >> 5, c = (idx & 31) << 2;
            cpa16(s0 + (uint32_t)(r * 136 + c) * 4u, qb + (long)r * LF + c);
        }
        cp_commit();
        uint32_t s1 = stou(sK);
#pragma unroll
        for (int i = 0; i < 8; i++) {
            int idx = tid + i * 256;
            int r = idx >> 5, c = (idx & 31) << 2;
            cpa16(s1 + (uint32_t)(r * 136 + c) * 4u, kb + (long)r * L2 + c);
        }
        cp_commit();
    }

    cp_wait<1>();
    __syncthreads();
    {
        uint32_t* q32 = reinterpret_cast<uint32_t*>(sQ);
        for (int i = tid; i < 64 * 128; i += 256) {
            int r = i >> 7, c = i & 127;
            q32[r * 136 + c] = f2tf(0.125f * sQ[r * 136 + c]);
        }
    }
    __syncthreads();

    const uint32_t* q32 = reinterpret_cast<const uint32_t*>(sQ);

    float4 accO[4][2];
#pragma unroll
    for (int mt = 0; mt < 4; mt++)
#pragma unroll
        for (int nt = 0; nt < 2; nt++) accO[mt][nt] = make_float4(0.f, 0.f, 0.f, 0.f);

#pragma unroll
    for (int t = 0; t < 8; t++) {
        const float* sKb = sK + (t & 1) * 8704;

        // prefetch V_t and K_{t+1}
        {
            uint32_t s0 = stou(sV);
            const float* vsrc = vb + t * 128;
#pragma unroll
            for (int i = 0; i < 8; i++) {
                int idx = tid + i * 256;
                int r = idx >> 5, c = (idx & 31) << 2;
                cpa16(s0 + (uint32_t)(r * 132 + c) * 4u, vsrc + (long)r * L2 + c);
            }
            cp_commit();
        }
        if (t < 7) {
            uint32_t s0 = stou(sK + ((t + 1) & 1) * 8704);
            const float* ksrc = kb + (t + 1) * 128;
#pragma unroll
            for (int i = 0; i < 8; i++) {
                int idx = tid + i * 256;
                int r = idx >> 5, c = (idx & 31) << 2;
                cpa16(s0 + (uint32_t)(r * 136 + c) * 4u, ksrc + (long)r * L2 + c);
            }
            cp_commit();
        }

        if (t < 7) cp_wait<2>(); else cp_wait<1>();
        __syncthreads();

        // ---- S = Q^T K ----
        float4 accS[4][4];
#pragma unroll
        for (int mt = 0; mt < 4; mt++)
#pragma unroll
            for (int nt = 0; nt < 4; nt++) accS[mt][nt] = make_float4(0.f, 0.f, 0.f, 0.f);

#pragma unroll
        for (int kk = 0; kk < 8; kk++) {
            uint32_t a[4][4], b[4][2];
#pragma unroll
            for (int mt = 0; mt < 4; mt++) {
                int l = wm * 64 + mt * 16 + g;
                int e = kk * 8 + tig;
                a[mt][0] = q32[e * 136 + l];
                a[mt][1] = q32[e * 136 + l + 8];
                a[mt][2] = q32[(e + 4) * 136 + l];
                a[mt][3] = q32[(e + 4) * 136 + l + 8];
            }
#pragma unroll
            for (int nt = 0; nt < 4; nt++) {
                int m = wn * 32 + nt * 8 + g;
                b[nt][0] = f2tf(sKb[(kk * 8 + tig) * 136 + m]);
                b[nt][1] = f2tf(sKb[(kk * 8 + tig + 4) * 136 + m]);
            }
#pragma unroll
            for (int mt = 0; mt < 4; mt++)
#pragma unroll
                for (int nt = 0; nt < 4; nt++)
                    mma_tf32(accS[mt][nt], a[mt], b[nt]);
        }

        // ---- per-row tile max ----
        {
            float pm[4][2];
#pragma unroll
            for (int mt = 0; mt < 4; mt++) {
                float lo = -1e30f, hi = -1e30f;
#pragma unroll
                for (int nt = 0; nt < 4; nt++) {
                    lo = fmaxf(lo, fmaxf(accS[mt][nt].x, accS[mt][nt].y));
                    hi = fmaxf(hi, fmaxf(accS[mt][nt].z, accS[mt][nt].w));
                }
                pm[mt][0] = lo; pm[mt][1] = hi;
            }
#pragma unroll
            for (int mt = 0; mt < 4; mt++)
#pragma unroll
                for (int hh = 0; hh < 2; hh++) {
                    float v = pm[mt][hh];
                    v = fmaxf(v, __shfl_xor_sync(0xffffffffu, v, 1));
                    v = fmaxf(v, __shfl_xor_sync(0xffffffffu, v, 2));
                    if (tig == 0) part[(wm * 64 + mt * 16 + hh * 8 + g) * 4 + wn] = v;
                }
        }
        __syncthreads();
        if (tid < 128) {
            int r = tid;
            float tm = fmaxf(fmaxf(part[r * 4 + 0], part[r * 4 + 1]),
                             fmaxf(part[r * 4 + 2], part[r * 4 + 3]));
            float om = rmax[r];
            float nm = fmaxf(om, tm);
            float sc = __expf(om - nm);
            rmax[r] = nm;
            rscl[r] = sc;
            rsum[r] *= sc;
        }
        __syncthreads();

        // ---- P = exp(S - rowmax) -> tf32 in sP, partial sums ----
        {
            float ps[4][2];
#pragma unroll
            for (int mt = 0; mt < 4; mt++) {
#pragma unroll
                for (int hh = 0; hh < 2; hh++) {
                    int row = wm * 64 + mt * 16 + hh * 8 + g;
                    float nm = rmax[row];
                    float s = 0.0f;
#pragma unroll
                    for (int nt = 0; nt < 4; nt++) {
                        float v0 = hh ? accS[mt][nt].z : accS[mt][nt].x;
                        float v1 = hh ? accS[mt][nt].w : accS[mt][nt].y;
                        float e0 = __expf(v0 - nm);
                        float e1 = __expf(v1 - nm);
                        s += e0 + e1;
                        int col = wn * 32 + nt * 8 + 2 * tig;
                        sP[row * 132 + col]     = f2tf(e0);
                        sP[row * 132 + col + 1] = f2tf(e1);
                    }
                    ps[mt][hh] = s;
                }
            }
#pragma unroll
            for (int mt = 0; mt < 4; mt++)
#pragma unroll
                for (int hh = 0; hh < 2; hh++) {
                    float v = ps[mt][hh];
                    v += __shfl_xor_sync(0xffffffffu, v, 1);
                    v += __shfl_xor_sync(0xffffffffu, v, 2);
                    if (tig == 0) part[(wm * 64 + mt * 16 + hh * 8 + g) * 4 + wn] = v;
                }
        }
        __syncthreads();
        if (tid < 128) {
            rsum[tid] += part[tid * 4 + 0] + part[tid * 4 + 1] +
                         part[tid * 4 + 2] + part[tid * 4 + 3];
        }

        // ---- rescale running O ----
#pragma unroll
        for (int mt = 0; mt < 4; mt++) {
            int row = wm * 64 + mt * 16 + g;
            float s0 = rscl[row], s1 = rscl[row + 8];
#pragma unroll
            for (int nt = 0; nt < 2; nt++) {
                accO[mt][nt].x *= s0; accO[mt][nt].y *= s0;
                accO[mt][nt].z *= s1; accO[mt][nt].w *= s1;
            }
        }

        // ---- wait V_t, O += P V^T ----
        if (t < 7) cp_wait<1>(); else cp_wait<0>();
        __syncthreads();

#pragma unroll 4
        for (int kk = 0; kk < 16; kk++) {
            uint32_t a[4][4], b[2][2];
#pragma unroll
            for (int mt = 0; mt < 4; mt++) {
                int row = wm * 64 + mt * 16 + g;
                int m = kk * 8 + tig;
                a[mt][0] = sP[row * 132 + m];
                a[mt][1] = sP[(row + 8) * 132 + m];
                a[mt][2] = sP[row * 132 + m + 4];
                a[mt][3] = sP[(row + 8) * 132 + m + 4];
            }
#pragma unroll
            for (int nt = 0; nt < 2; nt++) {
                int e = wn * 16 + nt * 8 + g;
                b[nt][0] = f2tf(sV[e * 132 + kk * 8 + tig]);
                b[nt][1] = f2tf(sV[e * 132 + kk * 8 + tig + 4]);
            }
#pragma unroll
            for (int mt = 0; mt < 4; mt++)
#pragma unroll
                for (int nt = 0; nt < 2; nt++)
                    mma_tf32(accO[mt][nt], a[mt], b[nt]);
        }
        __syncthreads();
    }

    // ---- epilogue ----
#pragma unroll
    for (int mt = 0; mt < 4; mt++) {
        int row = wm * 64 + mt * 16 + g;
        float i0 = 1.0f / rsum[row];
        float i1 = 1.0f / rsum[row + 8];
#pragma unroll
        for (int nt = 0; nt < 2; nt++) {
            int e = wn * 16 + nt * 8 + 2 * tig;
            ob[(long)e * LF + row]           = accO[mt][nt].x * i0;
            ob[(long)(e + 1) * LF + row]     = accO[mt][nt].y * i0;
            ob[(long)e * LF + row + 8]       = accO[mt][nt].z * i1;
            ob[(long)(e + 1) * LF + row + 8] = accO[mt][nt].w * i1;
        }
    }
}

// ---------------- launch ----------------
extern "C" void kernel_launch(void* const* d_in, const int* in_sizes, int n_in,
                              void* d_out, int out_size) {
    const float* x  = (const float*)d_in[0];
    const float* Wq = (const float*)d_in[1];  const float* bq = (const float*)d_in[2];
    const float* Wk = (const float*)d_in[3];  const float* bk = (const float*)d_in[4];
    const float* Wv = (const float*)d_in[5];  const float* bv = (const float*)d_in[6];
    const float* Wo = (const float*)d_in[7];  const float* bo = (const float*)d_in[8];
    const float* Wa = (const float*)d_in[9];
    const float* g1 = (const float*)d_in[10]; const float* b1 = (const float*)d_in[11];
    const float* m1 = (const float*)d_in[12]; const float* v1 = (const float*)d_in[13];
    const float* g2 = (const float*)d_in[14]; const float* b2 = (const float*)d_in[15];
    const float* m2 = (const float*)d_in[16]; const float* v2 = (const float*)d_in[17];
    float* out = (float*)d_out;
    (void)in_sizes; (void)n_in; (void)out_size;

    float *pXagg, *pXa, *pQ, *pK, *pV, *pO, *pS, *pT;
    cudaGetSymbolAddress((void**)&pXagg, d_xagg);
    cudaGetSymbolAddress((void**)&pXa,   d_xa);
    cudaGetSymbolAddress((void**)&pQ,    d_qb);
    cudaGetSymbolAddress((void**)&pK,    d_kb);
    cudaGetSymbolAddress((void**)&pV,    d_vb);
    cudaGetSymbolAddress((void**)&pO,    d_ob);
    cudaGetSymbolAddress((void**)&pS,    d_bns);
    cudaGetSymbolAddress((void**)&pT,    d_bnt);

    cudaFuncSetAttribute(flash_kernel, cudaFuncAttributeMaxDynamicSharedMemorySize,
                         FLASH_SMEM_BYTES);
    cudaFuncSetAttribute(mma_gemm<128, 4>, cudaFuncAttributeMaxDynamicSharedMemorySize,
                         GEMM128_SMEM);
    cudaFuncSetAttribute(mma_gemm<64, 2>, cudaFuncAttributeMaxDynamicSharedMemorySize,
                         GEMM64_SMEM);

    // 1) fold the two BNs
    bnfold_kernel<<<1, 256>>>(g1, b1, m1, v1, g2, b2, m2, v2);

    // 2) avg+max pooling
    aggregate_kernel<<<(NB * CCH * L2) / 256, 256>>>(x);

    // 3) q = Wq @ x + bq
    mma_gemm<128, 4><<<dim3(LF / 128, CCH / 128, NB), 256, GEMM128_SMEM>>>(
        Wq, x, pQ, CCH, CCH, LF, LF, 0, (long)CCH * LF, (long)CCH * LF, 1.0f, nullptr, bq);

    // 4) xa = BN2(BN1(Wa @ xagg))
    mma_gemm<64, 2><<<dim3(L2 / 128, CCH / 64, NB), 256, GEMM64_SMEM>>>(
        Wa, pXagg, pXa, CCH, CCH, L2, L2, 0, (long)CCH * L2, (long)CCH * L2, 1.0f, pS, pT);

    // 5) k, v projections
    mma_gemm<64, 2><<<dim3(L2 / 128, CCH / 64, NB), 256, GEMM64_SMEM>>>(
        Wk, pXa, pK, CCH, CCH, L2, L2, 0, (long)CCH * L2, (long)CCH * L2, 1.0f, nullptr, bk);
    mma_gemm<64, 2><<<dim3(L2 / 128, CCH / 64, NB), 256, GEMM64_SMEM>>>(
        Wv, pXa, pV, CCH, CCH, L2, L2, 0, (long)CCH * L2, (long)CCH * L2, 1.0f, nullptr, bv);

    // 6) fused attention
    flash_kernel<<<dim3(LF / 128, NB * HH), 256, FLASH_SMEM_BYTES>>>(pQ, pK, pV, pO);

    // 7) out = Wo @ o + bo
    mma_gemm<128, 4><<<dim3(LF / 128, CCH / 128, NB), 256, GEMM128_SMEM>>>(
        Wo, pO, out, CCH, CCH, LF, LF, 0, (long)CCH * LF, (long)CCH * LF, 1.0f, nullptr, bo);
}

// round 6
// speedup vs baseline: 3.9084x; 1.2583x over previous
#include <cuda_runtime.h>
#include <cuda_bf16.h>
#include <cstdint>

// Problem constants
#define NB  4
#define CCH 256
#define LF  4096
#define L2  1024
#define HH  4
#define EE  64

// ---------------- device scratch (static; no cudaMalloc) ----------------
__device__ float d_xagg[NB * CCH * L2];
__device__ float d_xa  [NB * CCH * L2];
__device__ float d_qb  [NB * CCH * LF];   // tf32 bits of 0.125*(Wq x + bq)
__device__ float d_kb  [NB * CCH * L2];   // tf32 bits of (Wk xa + bk)
__device__ float d_vb  [NB * CCH * L2];   // tf32 bits of (Wv xa + bv)
__device__ float d_ob  [NB * CCH * LF];
__device__ float d_bns[CCH];
__device__ float d_bnt[CCH];

// ---------------- BN fold ----------------
__global__ void bnfold_kernel(const float* __restrict__ g1, const float* __restrict__ b1,
                              const float* __restrict__ m1, const float* __restrict__ v1,
                              const float* __restrict__ g2, const float* __restrict__ b2,
                              const float* __restrict__ m2, const float* __restrict__ v2) {
    int c = threadIdx.x;
    float i1 = g1[c] * rsqrtf(v1[c] + 1e-5f);
    float c1 = b1[c] - m1[c] * i1;
    float i2 = g2[c] * rsqrtf(v2[c] + 1e-5f);
    float c2 = b2[c] - m2[c] * i2;
    d_bns[c] = i1 * i2;
    d_bnt[c] = c1 * i2 + c2;
}

// ---------------- aggregation: mean + max over groups of 4 ----------------
__global__ void aggregate_kernel(const float* __restrict__ x) {
    int i = blockIdx.x * blockDim.x + threadIdx.x;
    float4 t = reinterpret_cast<const float4*>(x)[i];
    float mx = fmaxf(fmaxf(t.x, t.y), fmaxf(t.z, t.w));
    d_xagg[i] = 0.25f * (t.x + t.y + t.z + t.w) + mx;
}

// ---------------- tf32 / cp.async helpers ----------------
__device__ __forceinline__ uint32_t f2tf(float x) {
    uint32_t r;
    asm("cvt.rna.tf32.f32 %0, %1;" : "=r"(r) : "f"(x));
    return r;
}
__device__ __forceinline__ void mma_tf32(float4& c, const uint32_t a[4], const uint32_t b[2]) {
    asm volatile(
        "mma.sync.aligned.m16n8k8.row.col.f32.tf32.tf32.f32 "
        "{%0,%1,%2,%3}, {%4,%5,%6,%7}, {%8,%9}, {%0,%1,%2,%3};\n"
        : "+f"(c.x), "+f"(c.y), "+f"(c.z), "+f"(c.w)
        : "r"(a[0]), "r"(a[1]), "r"(a[2]), "r"(a[3]), "r"(b[0]), "r"(b[1]));
}
__device__ __forceinline__ uint32_t stou(const void* p) {
    return (uint32_t)__cvta_generic_to_shared(p);
}
__device__ __forceinline__ void cpa16(uint32_t dst, const void* src) {
    asm volatile("cp.async.cg.shared.global [%0], [%1], 16;\n" :: "r"(dst), "l"(src));
}
__device__ __forceinline__ void cp_commit() { asm volatile("cp.async.commit_group;\n"); }
template <int N> __device__ __forceinline__ void cp_wait() {
    asm volatile("cp.async.wait_group %0;\n" :: "n"(N));
}
#define GBAR(id) asm volatile("bar.sync %0, %1;" :: "r"(id), "r"(128) : "memory")

// ---------------- cp.async double-buffered tf32 GEMM ----------------
// Y[m][n] = alpha*(rs?rs[m]:1)*sum_k A[m][k]*B[k][n] + beta*(rb?rb[m]:0)
// If CVT: output stored as tf32 bits (cvt.rna) in the float buffer.
template <int BM, int TMt, bool CVT>
__global__ __launch_bounds__(256) void mma_gemm(
    const float* __restrict__ A, const float* __restrict__ B, float* __restrict__ Y,
    int K, int lda, int ldb, int ldy,
    long aB, long bB, long yB, float alpha, float beta,
    const float* __restrict__ rs, const float* __restrict__ rb)
{
    extern __shared__ float sm[];
    float* sA = sm;                 // [2][BM][36]
    float* sB = sm + 2 * BM * 36;   // [2][32][136]

    A += (long)blockIdx.z * aB;
    B += (long)blockIdx.z * bB;
    Y += (long)blockIdx.z * yB;

    const int tid  = threadIdx.x;
    const int lane = tid & 31;
    const int wid  = tid >> 5;
    const int wm   = wid >> 2;
    const int wn   = wid & 3;
    const int g    = lane >> 2;
    const int tig  = lane & 3;
    const int m0   = blockIdx.y * BM;
    const int n0   = blockIdx.x * 128;

    float4 acc[TMt][4];
#pragma unroll
    for (int i = 0; i < TMt; i++)
#pragma unroll
        for (int j = 0; j < 4; j++) acc[i][j] = make_float4(0.f, 0.f, 0.f, 0.f);

    const int ntiles = K >> 5;

    auto prefetch = [&](int t, int buf) {
        float* dA = sA + buf * BM * 36;
        float* dB = sB + buf * 32 * 136;
#pragma unroll
        for (int i = tid; i < BM * 8; i += 256) {
            int r = i >> 3, c = (i & 7) << 2;
            cpa16(stou(dA + r * 36 + c), A + (long)(m0 + r) * lda + (t << 5) + c);
        }
#pragma unroll
        for (int i = tid; i < 1024; i += 256) {
            int r = i >> 5, c = (i & 31) << 2;
            cpa16(stou(dB + r * 136 + c), B + (long)((t << 5) + r) * ldb + n0 + c);
        }
    };

    prefetch(0, 0);
    cp_commit();

    for (int t = 0; t < ntiles; t++) {
        const int buf = t & 1;
        if (t + 1 < ntiles) {
            prefetch(t + 1, buf ^ 1);
            cp_commit();
            cp_wait<1>();
        } else {
            cp_wait<0>();
        }
        __syncthreads();

        const float* cA = sA + buf * BM * 36;
        const float* cB = sB + buf * 32 * 136;

#pragma unroll
        for (int kk = 0; kk < 32; kk += 8) {
            uint32_t a[TMt][4], b[4][2];
#pragma unroll
            for (int mt = 0; mt < TMt; mt++) {
                int r = wm * (TMt * 16) + mt * 16 + g;
                a[mt][0] = f2tf(cA[r * 36 + kk + tig]);
                a[mt][1] = f2tf(cA[(r + 8) * 36 + kk + tig]);
                a[mt][2] = f2tf(cA[r * 36 + kk + tig + 4]);
                a[mt][3] = f2tf(cA[(r + 8) * 36 + kk + tig + 4]);
            }
#pragma unroll
            for (int nt = 0; nt < 4; nt++) {
                int c = wn * 32 + nt * 8 + g;
                b[nt][0] = f2tf(cB[(kk + tig) * 136 + c]);
                b[nt][1] = f2tf(cB[(kk + tig + 4) * 136 + c]);
            }
#pragma unroll
            for (int mt = 0; mt < TMt; mt++)
#pragma unroll
                for (int nt = 0; nt < 4; nt++)
                    mma_tf32(acc[mt][nt], a[mt], b[nt]);
        }
        __syncthreads();
    }

#pragma unroll
    for (int mt = 0; mt < TMt; mt++) {
        int r = m0 + wm * (TMt * 16) + mt * 16 + g;
        float s0 = alpha * (rs ? rs[r] : 1.0f),     t0 = beta * (rb ? rb[r] : 0.0f);
        float s1 = alpha * (rs ? rs[r + 8] : 1.0f), t1 = beta * (rb ? rb[r + 8] : 0.0f);
#pragma unroll
        for (int nt = 0; nt < 4; nt++) {
            int c = n0 + wn * 32 + nt * 8 + 2 * tig;
            float y00 = acc[mt][nt].x * s0 + t0, y01 = acc[mt][nt].y * s0 + t0;
            float y10 = acc[mt][nt].z * s1 + t1, y11 = acc[mt][nt].w * s1 + t1;
            float2 lo, hi;
            if (CVT) {
                lo = make_float2(__uint_as_float(f2tf(y00)), __uint_as_float(f2tf(y01)));
                hi = make_float2(__uint_as_float(f2tf(y10)), __uint_as_float(f2tf(y11)));
            } else {
                lo = make_float2(y00, y01);
                hi = make_float2(y10, y11);
            }
            *reinterpret_cast<float2*>(Y + (long)r * ldy + c) = lo;
            *reinterpret_cast<float2*>(Y + (long)(r + 8) * ldy + c) = hi;
        }
    }
}

#define GEMM128_SMEM ((2 * 128 * 36 + 2 * 32 * 136) * 4)
#define GEMM64_SMEM  ((2 * 64 * 36 + 2 * 32 * 136) * 4)

// ---------------- fused flash attention (512 threads, tf32 inputs) ----------------
// Q/K/V buffers already hold tf32 bits; Q has 0.125 scale + bias folded.
// 16 warps as 4x4 (wm x wn). wm-group owns 32 query rows + its sP slice.
// QK warp tile: 32 q x 32 keys.  PV warp tile: 32 q x 16 e.
#define SQ_OFF 0
#define SK_OFF 8704
#define SV_OFF 26112
#define SP_OFF 34560
#define RMAX_OFF 51456
#define RSUM_OFF 51584
#define RSCL_OFF 51712
#define PART_OFF 51840
#define FLASH_SMEM_BYTES ((52352) * 4)

__global__ __launch_bounds__(512, 1) void flash_kernel(
    const float* __restrict__ Qf, const float* __restrict__ Kf,
    const float* __restrict__ Vf, float* __restrict__ O)
{
    extern __shared__ float smem[];
    uint32_t* sQ = reinterpret_cast<uint32_t*>(smem + SQ_OFF);  // [64][136] tf32
    uint32_t* sK = reinterpret_cast<uint32_t*>(smem + SK_OFF);  // [2][64][136] tf32
    uint32_t* sV = reinterpret_cast<uint32_t*>(smem + SV_OFF);  // [64][132] tf32
    uint32_t* sP = reinterpret_cast<uint32_t*>(smem + SP_OFF);  // [128][132] tf32
    float* rmax = smem + RMAX_OFF;
    float* rsum = smem + RSUM_OFF;
    float* rscl = smem + RSCL_OFF;
    float* part = smem + PART_OFF;  // [128][4]

    const int tid  = threadIdx.x;
    const int lane = tid & 31;
    const int wid  = tid >> 5;
    const int wm   = wid >> 2;      // 0..3 : row group
    const int wn   = wid & 3;       // 0..3
    const int g    = lane >> 2;     // 0..7
    const int tig  = lane & 3;      // 0..3
    const int bar  = wm + 1;        // named barrier id per group

    const int l0 = blockIdx.x * 128;
    const int nh = blockIdx.y;
    const int n  = nh >> 2, h = nh & 3;
    const uint32_t* qb = reinterpret_cast<const uint32_t*>(Qf) + ((long)n * CCH + h * 64) * LF + l0;
    const uint32_t* kb = reinterpret_cast<const uint32_t*>(Kf) + ((long)n * CCH + h * 64) * L2;
    const uint32_t* vb = reinterpret_cast<const uint32_t*>(Vf) + ((long)n * CCH + h * 64) * L2;
    float*          ob = O + ((long)n * CCH + h * 64) * LF + l0;

    if (tid < 128) { rmax[tid] = -1e30f; rsum[tid] = 0.0f; }

    // prologue: Q (group), K0 (group)
#pragma unroll
    for (int i = 0; i < 4; i++) {
        int idx = tid + i * 512;
        int r = idx >> 5, c = (idx & 31) << 2;
        cpa16(stou(sQ + r * 136 + c), qb + (long)r * LF + c);
    }
    cp_commit();
#pragma unroll
    for (int i = 0; i < 4; i++) {
        int idx = tid + i * 512;
        int r = idx >> 5, c = (idx & 31) << 2;
        cpa16(stou(sK + r * 136 + c), kb + (long)r * L2 + c);
    }
    cp_commit();

    float4 accO[2][2];
#pragma unroll
    for (int mt = 0; mt < 2; mt++)
#pragma unroll
        for (int nt = 0; nt < 2; nt++) accO[mt][nt] = make_float4(0.f, 0.f, 0.f, 0.f);

#pragma unroll
    for (int t = 0; t < 8; t++) {
        const uint32_t* sKb = sK + (t & 1) * 8704;

        // prefetch V_t and K_{t+1}
        {
            const uint32_t* vsrc = vb + t * 128;
#pragma unroll
            for (int i = 0; i < 4; i++) {
                int idx = tid + i * 512;
                int r = idx >> 5, c = (idx & 31) << 2;
                cpa16(stou(sV + r * 132 + c), vsrc + (long)r * L2 + c);
            }
            cp_commit();
        }
        if (t < 7) {
            uint32_t* dK = sK + ((t + 1) & 1) * 8704;
            const uint32_t* ksrc = kb + (t + 1) * 128;
#pragma unroll
            for (int i = 0; i < 4; i++) {
                int idx = tid + i * 512;
                int r = idx >> 5, c = (idx & 31) << 2;
                cpa16(stou(dK + r * 136 + c), ksrc + (long)r * L2 + c);
            }
            cp_commit();
        }

        if (t < 7) cp_wait<2>(); else cp_wait<1>();
        __syncthreads();

        // ---- S = Q^T K (warp: 32 q rows x 32 keys) ----
        float4 accS[2][4];
#pragma unroll
        for (int mt = 0; mt < 2; mt++)
#pragma unroll
            for (int nt = 0; nt < 4; nt++) accS[mt][nt] = make_float4(0.f, 0.f, 0.f, 0.f);

#pragma unroll
        for (int kk = 0; kk < 8; kk++) {
            uint32_t a[2][4], b[4][2];
#pragma unroll
            for (int mt = 0; mt < 2; mt++) {
                int l = wm * 32 + mt * 16 + g;
                int e = kk * 8 + tig;
                a[mt][0] = sQ[e * 136 + l];
                a[mt][1] = sQ[e * 136 + l + 8];
                a[mt][2] = sQ[(e + 4) * 136 + l];
                a[mt][3] = sQ[(e + 4) * 136 + l + 8];
            }
#pragma unroll
            for (int nt = 0; nt < 4; nt++) {
                int m = wn * 32 + nt * 8 + g;
                b[nt][0] = sKb[(kk * 8 + tig) * 136 + m];
                b[nt][1] = sKb[(kk * 8 + tig + 4) * 136 + m];
            }
#pragma unroll
            for (int mt = 0; mt < 2; mt++)
#pragma unroll
                for (int nt = 0; nt < 4; nt++)
                    mma_tf32(accS[mt][nt], a[mt], b[nt]);
        }

        // ---- per-row tile max (group-scoped) ----
        {
#pragma unroll
            for (int mt = 0; mt < 2; mt++)
#pragma unroll
                for (int hh = 0; hh < 2; hh++) {
                    float lo;
                    if (hh == 0) {
                        lo = -1e30f;
#pragma unroll
                        for (int nt = 0; nt < 4; nt++)
                            lo = fmaxf(lo, fmaxf(accS[mt][nt].x, accS[mt][nt].y));
                    } else {
                        lo = -1e30f;
#pragma unroll
                        for (int nt = 0; nt < 4; nt++)
                            lo = fmaxf(lo, fmaxf(accS[mt][nt].z, accS[mt][nt].w));
                    }
                    lo = fmaxf(lo, __shfl_xor_sync(0xffffffffu, lo, 1));
                    lo = fmaxf(lo, __shfl_xor_sync(0xffffffffu, lo, 2));
                    if (tig == 0) part[(wm * 32 + mt * 16 + hh * 8 + g) * 4 + wn] = lo;
                }
        }
        GBAR(bar);
        if (wn == 0) {
            int r = wm * 32 + lane;
            float tm = fmaxf(fmaxf(part[r * 4 + 0], part[r * 4 + 1]),
                             fmaxf(part[r * 4 + 2], part[r * 4 + 3]));
            float om = rmax[r];
            float nm = fmaxf(om, tm);
            float sc = __expf(om - nm);
            rmax[r] = nm;
            rscl[r] = sc;
            rsum[r] *= sc;
        }
        GBAR(bar);

        // ---- P = exp(S - rowmax) -> tf32 in sP, partial sums ----
        {
#pragma unroll
            for (int mt = 0; mt < 2; mt++) {
#pragma unroll
                for (int hh = 0; hh < 2; hh++) {
                    int row = wm * 32 + mt * 16 + hh * 8 + g;
                    float nm = rmax[row];
                    float s = 0.0f;
#pragma unroll
                    for (int nt = 0; nt < 4; nt++) {
                        float v0 = hh ? accS[mt][nt].z : accS[mt][nt].x;
                        float v1 = hh ? accS[mt][nt].w : accS[mt][nt].y;
                        float e0 = __expf(v0 - nm);
                        float e1 = __expf(v1 - nm);
                        s += e0 + e1;
                        int col = wn * 32 + nt * 8 + 2 * tig;
                        sP[row * 132 + col]     = f2tf(e0);
                        sP[row * 132 + col + 1] = f2tf(e1);
                    }
                    s += __shfl_xor_sync(0xffffffffu, s, 1);
                    s += __shfl_xor_sync(0xffffffffu, s, 2);
                    if (tig == 0) part[row * 4 + wn] = s;
                }
            }
        }
        GBAR(bar);
        if (wn == 0) {
            int r = wm * 32 + lane;
            rsum[r] += part[r * 4 + 0] + part[r * 4 + 1] +
                       part[r * 4 + 2] + part[r * 4 + 3];
        }

        // ---- rescale running O ----
#pragma unroll
        for (int mt = 0; mt < 2; mt++) {
            int row = wm * 32 + mt * 16 + g;
            float s0 = rscl[row], s1 = rscl[row + 8];
#pragma unroll
            for (int nt = 0; nt < 2; nt++) {
                accO[mt][nt].x *= s0; accO[mt][nt].y *= s0;
                accO[mt][nt].z *= s1; accO[mt][nt].w *= s1;
            }
        }

        // ---- wait V_t, O += P V^T (warp: 32 q x 16 e) ----
        if (t < 7) cp_wait<1>(); else cp_wait<0>();
        __syncthreads();

#pragma unroll 4
        for (int kk = 0; kk < 16; kk++) {
            uint32_t a[2][4], b[2][2];
#pragma unroll
            for (int mt = 0; mt < 2; mt++) {
                int row = wm * 32 + mt * 16 + g;
                int m = kk * 8 + tig;
                a[mt][0] = sP[row * 132 + m];
                a[mt][1] = sP[(row + 8) * 132 + m];
                a[mt][2] = sP[row * 132 + m + 4];
                a[mt][3] = sP[(row + 8) * 132 + m + 4];
            }
#pragma unroll
            for (int nt = 0; nt < 2; nt++) {
                int e = wn * 16 + nt * 8 + g;
                b[nt][0] = sV[e * 132 + kk * 8 + tig];
                b[nt][1] = sV[e * 132 + kk * 8 + tig + 4];
            }
#pragma unroll
            for (int mt = 0; mt < 2; mt++)
#pragma unroll
                for (int nt = 0; nt < 2; nt++)
                    mma_tf32(accO[mt][nt], a[mt], b[nt]);
        }
        __syncthreads();  // protect sV / sP for next iteration
    }

    // ---- epilogue: O[e][l] = accO / rowsum ----
    GBAR(bar);  // rsum final update visibility within group
#pragma unroll
    for (int mt = 0; mt < 2; mt++) {
        int row = wm * 32 + mt * 16 + g;
        float i0 = 1.0f / rsum[row];
        float i1 = 1.0f / rsum[row + 8];
#pragma unroll
        for (int nt = 0; nt < 2; nt++) {
            int e = wn * 16 + nt * 8 + 2 * tig;
            ob[(long)e * LF + row]           = accO[mt][nt].x * i0;
            ob[(long)(e + 1) * LF + row]     = accO[mt][nt].y * i0;
            ob[(long)e * LF + row + 8]       = accO[mt][nt].z * i1;
            ob[(long)(e + 1) * LF + row + 8] = accO[mt][nt].w * i1;
        }
    }
}

// ---------------- launch ----------------
extern "C" void kernel_launch(void* const* d_in, const int* in_sizes, int n_in,
                              void* d_out, int out_size) {
    const float* x  = (const float*)d_in[0];
    const float* Wq = (const float*)d_in[1];  const float* bq = (const float*)d_in[2];
    const float* Wk = (const float*)d_in[3];  const float* bk = (const float*)d_in[4];
    const float* Wv = (const float*)d_in[5];  const float* bv = (const float*)d_in[6];
    const float* Wo = (const float*)d_in[7];  const float* bo = (const float*)d_in[8];
    const float* Wa = (const float*)d_in[9];
    const float* g1 = (const float*)d_in[10]; const float* b1 = (const float*)d_in[11];
    const float* m1 = (const float*)d_in[12]; const float* v1 = (const float*)d_in[13];
    const float* g2 = (const float*)d_in[14]; const float* b2 = (const float*)d_in[15];
    const float* m2 = (const float*)d_in[16]; const float* v2 = (const float*)d_in[17];
    float* out = (float*)d_out;
    (void)in_sizes; (void)n_in; (void)out_size;

    float *pXagg, *pXa, *pQ, *pK, *pV, *pO, *pS, *pT;
    cudaGetSymbolAddress((void**)&pXagg, d_xagg);
    cudaGetSymbolAddress((void**)&pXa,   d_xa);
    cudaGetSymbolAddress((void**)&pQ,    d_qb);
    cudaGetSymbolAddress((void**)&pK,    d_kb);
    cudaGetSymbolAddress((void**)&pV,    d_vb);
    cudaGetSymbolAddress((void**)&pO,    d_ob);
    cudaGetSymbolAddress((void**)&pS,    d_bns);
    cudaGetSymbolAddress((void**)&pT,    d_bnt);

    cudaFuncSetAttribute(flash_kernel, cudaFuncAttributeMaxDynamicSharedMemorySize,
                         FLASH_SMEM_BYTES);
    cudaFuncSetAttribute(mma_gemm<128, 4, false>, cudaFuncAttributeMaxDynamicSharedMemorySize,
                         GEMM128_SMEM);
    cudaFuncSetAttribute(mma_gemm<128, 4, true>, cudaFuncAttributeMaxDynamicSharedMemorySize,
                         GEMM128_SMEM);
    cudaFuncSetAttribute(mma_gemm<64, 2, false>, cudaFuncAttributeMaxDynamicSharedMemorySize,
                         GEMM64_SMEM);
    cudaFuncSetAttribute(mma_gemm<64, 2, true>, cudaFuncAttributeMaxDynamicSharedMemorySize,
                         GEMM64_SMEM);

    // 1) fold the two BNs
    bnfold_kernel<<<1, 256>>>(g1, b1, m1, v1, g2, b2, m2, v2);

    // 2) avg+max pooling
    aggregate_kernel<<<(NB * CCH * L2) / 256, 256>>>(x);

    // 3) q = tf32(0.125*(Wq x + bq))
    mma_gemm<128, 4, true><<<dim3(LF / 128, CCH / 128, NB), 256, GEMM128_SMEM>>>(
        Wq, x, pQ, CCH, CCH, LF, LF, 0, (long)CCH * LF, (long)CCH * LF,
        0.125f, 0.125f, nullptr, bq);

    // 4) xa = BN2(BN1(Wa @ xagg))  (fp32 out; feeds k/v GEMM B operand)
    mma_gemm<64, 2, false><<<dim3(L2 / 128, CCH / 64, NB), 256, GEMM64_SMEM>>>(
        Wa, pXagg, pXa, CCH, CCH, L2, L2, 0, (long)CCH * L2, (long)CCH * L2,
        1.0f, 1.0f, pS, pT);

    // 5) k, v projections (tf32 out)
    mma_gemm<64, 2, true><<<dim3(L2 / 128, CCH / 64, NB), 256, GEMM64_SMEM>>>(
        Wk, pXa, pK, CCH, CCH, L2, L2, 0, (long)CCH * L2, (long)CCH * L2,
        1.0f, 1.0f, nullptr, bk);
    mma_gemm<64, 2, true><<<dim3(L2 / 128, CCH / 64, NB), 256, GEMM64_SMEM>>>(
        Wv, pXa, pV, CCH, CCH, L2, L2, 0, (long)CCH * L2, (long)CCH * L2,
        1.0f, 1.0f, nullptr, bv);

    // 6) fused attention (512 threads)
    flash_kernel<<<dim3(LF / 128, NB * HH), 512, FLASH_SMEM_BYTES>>>(pQ, pK, pV, pO);

    // 7) out = Wo @ o + bo
    mma_gemm<128, 4, false><<<dim3(LF / 128, CCH / 128, NB), 256, GEMM128_SMEM>>>(
        Wo, pO, out, CCH, CCH, LF, LF, 0, (long)CCH * LF, (long)CCH * LF,
        1.0f, 1.0f, nullptr, bo);
}

// round 7
// speedup vs baseline: 4.3386x; 1.1101x over previous
#include <cuda_runtime.h>
#include <cuda_bf16.h>
#include <cstdint>

// Problem constants
#define NB  4
#define CCH 256
#define LF  4096
#define L2  1024
#define HH  4
#define EE  64

// ---------------- device scratch (static; no cudaMalloc) ----------------
__device__ float d_xagg[NB * CCH * L2];
__device__ float d_xa  [NB * CCH * L2];
__device__ float d_qb  [NB * CCH * LF];   // tf32 bits of 0.125*(Wq x + bq)
__device__ float d_kb  [NB * CCH * L2];   // tf32 bits of (Wk xa + bk)
__device__ float d_vb  [NB * CCH * L2];   // tf32 bits of (Wv xa + bv)
__device__ float d_ob  [NB * CCH * LF];
__device__ float d_bns[CCH];
__device__ float d_bnt[CCH];

// ---------------- BN fold ----------------
__global__ void bnfold_kernel(const float* __restrict__ g1, const float* __restrict__ b1,
                              const float* __restrict__ m1, const float* __restrict__ v1,
                              const float* __restrict__ g2, const float* __restrict__ b2,
                              const float* __restrict__ m2, const float* __restrict__ v2) {
    int c = threadIdx.x;
    float i1 = g1[c] * rsqrtf(v1[c] + 1e-5f);
    float c1 = b1[c] - m1[c] * i1;
    float i2 = g2[c] * rsqrtf(v2[c] + 1e-5f);
    float c2 = b2[c] - m2[c] * i2;
    d_bns[c] = i1 * i2;
    d_bnt[c] = c1 * i2 + c2;
}

// ---------------- aggregation: mean + max over groups of 4 ----------------
__global__ void aggregate_kernel(const float* __restrict__ x) {
    int i = blockIdx.x * blockDim.x + threadIdx.x;
    float4 t = reinterpret_cast<const float4*>(x)[i];
    float mx = fmaxf(fmaxf(t.x, t.y), fmaxf(t.z, t.w));
    d_xagg[i] = 0.25f * (t.x + t.y + t.z + t.w) + mx;
}

// ---------------- tf32 / cp.async helpers ----------------
__device__ __forceinline__ uint32_t f2tf(float x) {
    uint32_t r;
    asm("cvt.rna.tf32.f32 %0, %1;" : "=r"(r) : "f"(x));
    return r;
}
__device__ __forceinline__ void mma_tf32(float4& c, const uint32_t a[4], const uint32_t b[2]) {
    asm volatile(
        "mma.sync.aligned.m16n8k8.row.col.f32.tf32.tf32.f32 "
        "{%0,%1,%2,%3}, {%4,%5,%6,%7}, {%8,%9}, {%0,%1,%2,%3};\n"
        : "+f"(c.x), "+f"(c.y), "+f"(c.z), "+f"(c.w)
        : "r"(a[0]), "r"(a[1]), "r"(a[2]), "r"(a[3]), "r"(b[0]), "r"(b[1]));
}
__device__ __forceinline__ uint32_t stou(const void* p) {
    return (uint32_t)__cvta_generic_to_shared(p);
}
__device__ __forceinline__ void cpa16(uint32_t dst, const void* src) {
    asm volatile("cp.async.cg.shared.global [%0], [%1], 16;\n" :: "r"(dst), "l"(src));
}
__device__ __forceinline__ void cp_commit() { asm volatile("cp.async.commit_group;\n"); }
template <int N> __device__ __forceinline__ void cp_wait() {
    asm volatile("cp.async.wait_group %0;\n" :: "n"(N));
}

// ---------------- cp.async double-buffered tf32 GEMM ----------------
// Y[m][n] = alpha*(rs?rs[m]:1)*sum_k A[m][k]*B[k][n] + beta*(rb?rb[m]:0)
// CVT: store tf32 bits.  DUAL: blockIdx.z = 2*batch + sel; sel picks (A2,Y2,rb2).
template <int BM, int TMt, bool CVT, bool DUAL>
__global__ __launch_bounds__(256) void mma_gemm(
    const float* __restrict__ A, const float* __restrict__ A2,
    const float* __restrict__ B,
    float* __restrict__ Y, float* __restrict__ Y2,
    int K, int lda, int ldb, int ldy,
    long aB, long bB, long yB, float alpha, float beta,
    const float* __restrict__ rs,
    const float* __restrict__ rb, const float* __restrict__ rb2)
{
    extern __shared__ float sm[];
    float* sA = sm;                 // [2][BM][36]
    float* sB = sm + 2 * BM * 36;   // [2][32][136]

    long zb = DUAL ? (long)(blockIdx.z >> 1) : (long)blockIdx.z;
    if (DUAL && (blockIdx.z & 1)) { A = A2; Y = Y2; rb = rb2; }
    A += zb * aB;
    B += zb * bB;
    Y += zb * yB;

    const int tid  = threadIdx.x;
    const int lane = tid & 31;
    const int wid  = tid >> 5;
    const int wm   = wid >> 2;
    const int wn   = wid & 3;
    const int g    = lane >> 2;
    const int tig  = lane & 3;
    const int m0   = blockIdx.y * BM;
    const int n0   = blockIdx.x * 128;

    float4 acc[TMt][4];
#pragma unroll
    for (int i = 0; i < TMt; i++)
#pragma unroll
        for (int j = 0; j < 4; j++) acc[i][j] = make_float4(0.f, 0.f, 0.f, 0.f);

    const int ntiles = K >> 5;

    auto prefetch = [&](int t, int buf) {
        float* dA = sA + buf * BM * 36;
        float* dB = sB + buf * 32 * 136;
#pragma unroll
        for (int i = tid; i < BM * 8; i += 256) {
            int r = i >> 3, c = (i & 7) << 2;
            cpa16(stou(dA + r * 36 + c), A + (long)(m0 + r) * lda + (t << 5) + c);
        }
#pragma unroll
        for (int i = tid; i < 1024; i += 256) {
            int r = i >> 5, c = (i & 31) << 2;
            cpa16(stou(dB + r * 136 + c), B + (long)((t << 5) + r) * ldb + n0 + c);
        }
    };

    prefetch(0, 0);
    cp_commit();

    for (int t = 0; t < ntiles; t++) {
        const int buf = t & 1;
        if (t + 1 < ntiles) {
            prefetch(t + 1, buf ^ 1);
            cp_commit();
            cp_wait<1>();
        } else {
            cp_wait<0>();
        }
        __syncthreads();

        const float* cA = sA + buf * BM * 36;
        const float* cB = sB + buf * 32 * 136;

#pragma unroll
        for (int kk = 0; kk < 32; kk += 8) {
            uint32_t a[TMt][4], b[4][2];
#pragma unroll
            for (int mt = 0; mt < TMt; mt++) {
                int r = wm * (TMt * 16) + mt * 16 + g;
                a[mt][0] = f2tf(cA[r * 36 + kk + tig]);
                a[mt][1] = f2tf(cA[(r + 8) * 36 + kk + tig]);
                a[mt][2] = f2tf(cA[r * 36 + kk + tig + 4]);
                a[mt][3] = f2tf(cA[(r + 8) * 36 + kk + tig + 4]);
            }
#pragma unroll
            for (int nt = 0; nt < 4; nt++) {
                int c = wn * 32 + nt * 8 + g;
                b[nt][0] = f2tf(cB[(kk + tig) * 136 + c]);
                b[nt][1] = f2tf(cB[(kk + tig + 4) * 136 + c]);
            }
#pragma unroll
            for (int mt = 0; mt < TMt; mt++)
#pragma unroll
                for (int nt = 0; nt < 4; nt++)
                    mma_tf32(acc[mt][nt], a[mt], b[nt]);
        }
        __syncthreads();
    }

#pragma unroll
    for (int mt = 0; mt < TMt; mt++) {
        int r = m0 + wm * (TMt * 16) + mt * 16 + g;
        float s0 = alpha * (rs ? rs[r] : 1.0f),     t0 = beta * (rb ? rb[r] : 0.0f);
        float s1 = alpha * (rs ? rs[r + 8] : 1.0f), t1 = beta * (rb ? rb[r + 8] : 0.0f);
#pragma unroll
        for (int nt = 0; nt < 4; nt++) {
            int c = n0 + wn * 32 + nt * 8 + 2 * tig;
            float y00 = acc[mt][nt].x * s0 + t0, y01 = acc[mt][nt].y * s0 + t0;
            float y10 = acc[mt][nt].z * s1 + t1, y11 = acc[mt][nt].w * s1 + t1;
            float2 lo, hi;
            if (CVT) {
                lo = make_float2(__uint_as_float(f2tf(y00)), __uint_as_float(f2tf(y01)));
                hi = make_float2(__uint_as_float(f2tf(y10)), __uint_as_float(f2tf(y11)));
            } else {
                lo = make_float2(y00, y01);
                hi = make_float2(y10, y11);
            }
            *reinterpret_cast<float2*>(Y + (long)r * ldy + c) = lo;
            *reinterpret_cast<float2*>(Y + (long)(r + 8) * ldy + c) = hi;
        }
    }
}

#define GEMM128_SMEM ((2 * 128 * 36 + 2 * 32 * 136) * 4)
#define GEMM64_SMEM  ((2 * 64 * 36 + 2 * 32 * 136) * 4)

// ---------------- fused flash attention (256 threads, warp-exclusive rows) ----------------
// 8 warps; warp w owns query rows [w*16, w*16+16). QK: 16q x 128keys. PV: 16q x 64e.
// Softmax stats (running max/sum) live in registers, replicated across the tig quad.
#define SQ_OFF 0
#define SK_OFF 8704
#define SV_OFF 26112
#define SP_OFF 34560
#define FLASH_SMEM_BYTES ((51456) * 4)

__global__ __launch_bounds__(256, 1) void flash_kernel(
    const float* __restrict__ Qf, const float* __restrict__ Kf,
    const float* __restrict__ Vf, float* __restrict__ O)
{
    extern __shared__ float smem[];
    uint32_t* sQ = reinterpret_cast<uint32_t*>(smem + SQ_OFF);  // [64 e][136] tf32
    uint32_t* sK = reinterpret_cast<uint32_t*>(smem + SK_OFF);  // [2][64 e][136]
    uint32_t* sV = reinterpret_cast<uint32_t*>(smem + SV_OFF);  // [64 e][132]
    uint32_t* sP = reinterpret_cast<uint32_t*>(smem + SP_OFF);  // [128 q][132]

    const int tid  = threadIdx.x;
    const int lane = tid & 31;
    const int w    = tid >> 5;      // 0..7
    const int g    = lane >> 2;     // 0..7
    const int tig  = lane & 3;      // 0..3

    const int l0 = blockIdx.x * 128;
    const int nh = blockIdx.y;
    const int n  = nh >> 2, h = nh & 3;
    const uint32_t* qb = reinterpret_cast<const uint32_t*>(Qf) + ((long)n * CCH + h * 64) * LF + l0;
    const uint32_t* kb = reinterpret_cast<const uint32_t*>(Kf) + ((long)n * CCH + h * 64) * L2;
    const uint32_t* vb = reinterpret_cast<const uint32_t*>(Vf) + ((long)n * CCH + h * 64) * L2;
    float*          ob = O + ((long)n * CCH + h * 64) * LF + l0;

    const int row_lo = w * 16 + g;
    const int row_hi = row_lo + 8;

    // prologue: Q, K0
#pragma unroll
    for (int i = 0; i < 8; i++) {
        int idx = tid + i * 256;
        int r = idx >> 5, c = (idx & 31) << 2;
        cpa16(stou(sQ + r * 136 + c), qb + (long)r * LF + c);
    }
    cp_commit();
#pragma unroll
    for (int i = 0; i < 8; i++) {
        int idx = tid + i * 256;
        int r = idx >> 5, c = (idx & 31) << 2;
        cpa16(stou(sK + r * 136 + c), kb + (long)r * L2 + c);
    }
    cp_commit();

    float m_lo = -1e30f, m_hi = -1e30f;
    float s_lo = 0.0f,   s_hi = 0.0f;
    float4 accO[8];
#pragma unroll
    for (int nt = 0; nt < 8; nt++) accO[nt] = make_float4(0.f, 0.f, 0.f, 0.f);

#pragma unroll 1
    for (int t = 0; t < 8; t++) {
        const uint32_t* sKb = sK + (t & 1) * 8704;

        // prefetch V_t; prefetch K_{t+1}
        {
            const uint32_t* vsrc = vb + t * 128;
#pragma unroll
            for (int i = 0; i < 8; i++) {
                int idx = tid + i * 256;
                int r = idx >> 5, c = (idx & 31) << 2;
                cpa16(stou(sV + r * 132 + c), vsrc + (long)r * L2 + c);
            }
            cp_commit();
        }
        if (t < 7) {
            uint32_t* dK = sK + ((t + 1) & 1) * 8704;
            const uint32_t* ksrc = kb + (t + 1) * 128;
#pragma unroll
            for (int i = 0; i < 8; i++) {
                int idx = tid + i * 256;
                int r = idx >> 5, c = (idx & 31) << 2;
                cpa16(stou(dK + r * 136 + c), ksrc + (long)r * L2 + c);
            }
            cp_commit();
        }

        if (t < 7) cp_wait<2>(); else cp_wait<1>();   // K_t (and Q) ready
        __syncthreads();

        // ---- S = Q^T K : warp tile 16q x 128keys (16 n-tiles) ----
        float4 accS[16];
#pragma unroll
        for (int nt = 0; nt < 16; nt++) accS[nt] = make_float4(0.f, 0.f, 0.f, 0.f);

#pragma unroll
        for (int kk = 0; kk < 8; kk++) {
            const int e = kk * 8 + tig;
            uint32_t a[4];
            a[0] = sQ[e * 136 + row_lo];
            a[1] = sQ[e * 136 + row_hi];
            a[2] = sQ[(e + 4) * 136 + row_lo];
            a[3] = sQ[(e + 4) * 136 + row_hi];
#pragma unroll
            for (int nt = 0; nt < 16; nt++) {
                uint32_t b[2];
                int m = nt * 8 + g;
                b[0] = sKb[e * 136 + m];
                b[1] = sKb[(e + 4) * 136 + m];
                mma_tf32(accS[nt], a, b);
            }
        }

        // ---- warp-local online softmax ----
        float tm_lo = -1e30f, tm_hi = -1e30f;
#pragma unroll
        for (int nt = 0; nt < 16; nt++) {
            tm_lo = fmaxf(tm_lo, fmaxf(accS[nt].x, accS[nt].y));
            tm_hi = fmaxf(tm_hi, fmaxf(accS[nt].z, accS[nt].w));
        }
        tm_lo = fmaxf(tm_lo, __shfl_xor_sync(0xffffffffu, tm_lo, 1));
        tm_lo = fmaxf(tm_lo, __shfl_xor_sync(0xffffffffu, tm_lo, 2));
        tm_hi = fmaxf(tm_hi, __shfl_xor_sync(0xffffffffu, tm_hi, 1));
        tm_hi = fmaxf(tm_hi, __shfl_xor_sync(0xffffffffu, tm_hi, 2));

        float nm_lo = fmaxf(m_lo, tm_lo);
        float nm_hi = fmaxf(m_hi, tm_hi);
        float sc_lo = __expf(m_lo - nm_lo);
        float sc_hi = __expf(m_hi - nm_hi);
        m_lo = nm_lo; m_hi = nm_hi;
        s_lo *= sc_lo; s_hi *= sc_hi;

        // rescale running O
#pragma unroll
        for (int nt = 0; nt < 8; nt++) {
            accO[nt].x *= sc_lo; accO[nt].y *= sc_lo;
            accO[nt].z *= sc_hi; accO[nt].w *= sc_hi;
        }

        // exp, stage P (tf32) into warp-private sP rows, accumulate sums
        float sl = 0.0f, sh = 0.0f;
#pragma unroll
        for (int nt = 0; nt < 16; nt++) {
            float e0 = __expf(accS[nt].x - m_lo);
            float e1 = __expf(accS[nt].y - m_lo);
            float e2 = __expf(accS[nt].z - m_hi);
            float e3 = __expf(accS[nt].w - m_hi);
            sl += e0 + e1;
            sh += e2 + e3;
            int col = nt * 8 + 2 * tig;
            uint2 lo = make_uint2(f2tf(e0), f2tf(e1));
            uint2 hi = make_uint2(f2tf(e2), f2tf(e3));
            *reinterpret_cast<uint2*>(sP + row_lo * 132 + col) = lo;
            *reinterpret_cast<uint2*>(sP + row_hi * 132 + col) = hi;
        }
        sl += __shfl_xor_sync(0xffffffffu, sl, 1);
        sl += __shfl_xor_sync(0xffffffffu, sl, 2);
        sh += __shfl_xor_sync(0xffffffffu, sh, 1);
        sh += __shfl_xor_sync(0xffffffffu, sh, 2);
        s_lo += sl; s_hi += sh;

        __syncwarp();   // sP rows are warp-private: warp-scope ordering suffices

        // ---- wait V_t, O += P V^T : warp tile 16q x 64e (8 n-tiles) ----
        if (t < 7) cp_wait<1>(); else cp_wait<0>();
        __syncthreads();

#pragma unroll
        for (int kk = 0; kk < 16; kk++) {
            const int m = kk * 8 + tig;
            uint32_t a[4];
            a[0] = sP[row_lo * 132 + m];
            a[1] = sP[row_hi * 132 + m];
            a[2] = sP[row_lo * 132 + m + 4];
            a[3] = sP[row_hi * 132 + m + 4];
#pragma unroll
            for (int nt = 0; nt < 8; nt++) {
                uint32_t b[2];
                int e = nt * 8 + g;
                b[0] = sV[e * 132 + m];
                b[1] = sV[e * 132 + m + 4];
                mma_tf32(accO[nt], a, b);
            }
        }
        __syncthreads();   // all warps done with sV (and sK tile) before next loads
    }

    // ---- epilogue: O[e][l] = accO / rowsum ----
    float i_lo = 1.0f / s_lo;
    float i_hi = 1.0f / s_hi;
#pragma unroll
    for (int nt = 0; nt < 8; nt++) {
        int e = nt * 8 + 2 * tig;
        ob[(long)e * LF + row_lo]           = accO[nt].x * i_lo;
        ob[(long)(e + 1) * LF + row_lo]     = accO[nt].y * i_lo;
        ob[(long)e * LF + row_hi]           = accO[nt].z * i_hi;
        ob[(long)(e + 1) * LF + row_hi]     = accO[nt].w * i_hi;
    }
}

// ---------------- launch ----------------
extern "C" void kernel_launch(void* const* d_in, const int* in_sizes, int n_in,
                              void* d_out, int out_size) {
    const float* x  = (const float*)d_in[0];
    const float* Wq = (const float*)d_in[1];  const float* bq = (const float*)d_in[2];
    const float* Wk = (const float*)d_in[3];  const float* bk = (const float*)d_in[4];
    const float* Wv = (const float*)d_in[5];  const float* bv = (const float*)d_in[6];
    const float* Wo = (const float*)d_in[7];  const float* bo = (const float*)d_in[8];
    const float* Wa = (const float*)d_in[9];
    const float* g1 = (const float*)d_in[10]; const float* b1 = (const float*)d_in[11];
    const float* m1 = (const float*)d_in[12]; const float* v1 = (const float*)d_in[13];
    const float* g2 = (const float*)d_in[14]; const float* b2 = (const float*)d_in[15];
    const float* m2 = (const float*)d_in[16]; const float* v2 = (const float*)d_in[17];
    float* out = (float*)d_out;
    (void)in_sizes; (void)n_in; (void)out_size;

    float *pXagg, *pXa, *pQ, *pK, *pV, *pO, *pS, *pT;
    cudaGetSymbolAddress((void**)&pXagg, d_xagg);
    cudaGetSymbolAddress((void**)&pXa,   d_xa);
    cudaGetSymbolAddress((void**)&pQ,    d_qb);
    cudaGetSymbolAddress((void**)&pK,    d_kb);
    cudaGetSymbolAddress((void**)&pV,    d_vb);
    cudaGetSymbolAddress((void**)&pO,    d_ob);
    cudaGetSymbolAddress((void**)&pS,    d_bns);
    cudaGetSymbolAddress((void**)&pT,    d_bnt);

    cudaFuncSetAttribute(flash_kernel, cudaFuncAttributeMaxDynamicSharedMemorySize,
                         FLASH_SMEM_BYTES);
    cudaFuncSetAttribute(mma_gemm<128, 4, false, false>,
                         cudaFuncAttributeMaxDynamicSharedMemorySize, GEMM128_SMEM);
    cudaFuncSetAttribute(mma_gemm<128, 4, true, false>,
                         cudaFuncAttributeMaxDynamicSharedMemorySize, GEMM128_SMEM);
    cudaFuncSetAttribute(mma_gemm<64, 2, false, false>,
                         cudaFuncAttributeMaxDynamicSharedMemorySize, GEMM64_SMEM);
    cudaFuncSetAttribute(mma_gemm<64, 2, true, true>,
                         cudaFuncAttributeMaxDynamicSharedMemorySize, GEMM64_SMEM);

    // 1) fold the two BNs
    bnfold_kernel<<<1, 256>>>(g1, b1, m1, v1, g2, b2, m2, v2);

    // 2) avg+max pooling
    aggregate_kernel<<<(NB * CCH * L2) / 256, 256>>>(x);

    // 3) q = tf32(0.125*(Wq x + bq))
    mma_gemm<128, 4, true, false><<<dim3(LF / 128, CCH / 128, NB), 256, GEMM128_SMEM>>>(
        Wq, nullptr, x, pQ, nullptr, CCH, CCH, LF, LF,
        0, (long)CCH * LF, (long)CCH * LF, 0.125f, 0.125f, nullptr, bq, nullptr);

    // 4) xa = BN2(BN1(Wa @ xagg))
    mma_gemm<64, 2, false, false><<<dim3(L2 / 128, CCH / 64, NB), 256, GEMM64_SMEM>>>(
        Wa, nullptr, pXagg, pXa, nullptr, CCH, CCH, L2, L2,
        0, (long)CCH * L2, (long)CCH * L2, 1.0f, 1.0f, pS, pT, nullptr);

    // 5) k and v projections fused into one DUAL launch (tf32 out)
    mma_gemm<64, 2, true, true><<<dim3(L2 / 128, CCH / 64, NB * 2), 256, GEMM64_SMEM>>>(
        Wk, Wv, pXa, pK, pV, CCH, CCH, L2, L2,
        0, (long)CCH * L2, (long)CCH * L2, 1.0f, 1.0f, nullptr, bk, bv);

    // 6) fused attention (256 threads, warp-exclusive rows)
    flash_kernel<<<dim3(LF / 128, NB * HH), 256, FLASH_SMEM_BYTES>>>(pQ, pK, pV, pO);

    // 7) out = Wo @ o + bo
    mma_gemm<128, 4, false, false><<<dim3(LF / 128, CCH / 128, NB), 256, GEMM128_SMEM>>>(
        Wo, nullptr, pO, out, nullptr, CCH, CCH, LF, LF,
        0, (long)CCH * LF, (long)CCH * LF, 1.0f, 1.0f, nullptr, bo, nullptr);
}

// round 8
// speedup vs baseline: 6.3605x; 1.4660x over previous
#include <cuda_runtime.h>
#include <cuda_fp16.h>
#include <cstdint>

// Problem constants
#define NB  4
#define CCH 256
#define LF  4096
#define L2  1024
#define HH  4
#define EE  64

// ---------------- device scratch (static; no cudaMalloc) ----------------
__device__ float  d_xagg[NB * CCH * L2];
__device__ float  d_xa  [NB * CCH * L2];
__device__ __half d_qh  [NB * HH * LF * EE];  // [n][h][l][e] fp16, 0.125*(Wq x + bq)
__device__ __half d_kh  [NB * HH * L2 * EE];  // [n][h][m][e] fp16
__device__ __half d_vh  [NB * HH * EE * L2];  // [n][h][e][m] fp16
__device__ float  d_ob  [NB * CCH * LF];
__device__ float  d_bns[CCH];
__device__ float  d_bnt[CCH];

// ---------------- BN fold ----------------
__global__ void bnfold_kernel(const float* __restrict__ g1, const float* __restrict__ b1,
                              const float* __restrict__ m1, const float* __restrict__ v1,
                              const float* __restrict__ g2, const float* __restrict__ b2,
                              const float* __restrict__ m2, const float* __restrict__ v2) {
    int c = threadIdx.x;
    float i1 = g1[c] * rsqrtf(v1[c] + 1e-5f);
    float c1 = b1[c] - m1[c] * i1;
    float i2 = g2[c] * rsqrtf(v2[c] + 1e-5f);
    float c2 = b2[c] - m2[c] * i2;
    d_bns[c] = i1 * i2;
    d_bnt[c] = c1 * i2 + c2;
}

// ---------------- aggregation: mean + max over groups of 4 ----------------
__global__ void aggregate_kernel(const float* __restrict__ x) {
    int i = blockIdx.x * blockDim.x + threadIdx.x;
    float4 t = reinterpret_cast<const float4*>(x)[i];
    float mx = fmaxf(fmaxf(t.x, t.y), fmaxf(t.z, t.w));
    d_xagg[i] = 0.25f * (t.x + t.y + t.z + t.w) + mx;
}

// ---------------- helpers ----------------
__device__ __forceinline__ uint32_t f2tf(float x) {
    uint32_t r;
    asm("cvt.rna.tf32.f32 %0, %1;" : "=r"(r) : "f"(x));
    return r;
}
__device__ __forceinline__ void mma_tf32(float4& c, const uint32_t a[4], const uint32_t b[2]) {
    asm volatile(
        "mma.sync.aligned.m16n8k8.row.col.f32.tf32.tf32.f32 "
        "{%0,%1,%2,%3}, {%4,%5,%6,%7}, {%8,%9}, {%0,%1,%2,%3};\n"
        : "+f"(c.x), "+f"(c.y), "+f"(c.z), "+f"(c.w)
        : "r"(a[0]), "r"(a[1]), "r"(a[2]), "r"(a[3]), "r"(b[0]), "r"(b[1]));
}
__device__ __forceinline__ void mma_f16(float4& c, const uint32_t a[4], const uint32_t b[2]) {
    asm volatile(
        "mma.sync.aligned.m16n8k16.row.col.f32.f16.f16.f32 "
        "{%0,%1,%2,%3}, {%4,%5,%6,%7}, {%8,%9}, {%0,%1,%2,%3};\n"
        : "+f"(c.x), "+f"(c.y), "+f"(c.z), "+f"(c.w)
        : "r"(a[0]), "r"(a[1]), "r"(a[2]), "r"(a[3]), "r"(b[0]), "r"(b[1]));
}
__device__ __forceinline__ uint32_t h2pack(float a, float b) {
    __half2 h = __floats2half2_rn(a, b);
    return *reinterpret_cast<uint32_t*>(&h);
}
__device__ __forceinline__ uint32_t stou(const void* p) {
    return (uint32_t)__cvta_generic_to_shared(p);
}
__device__ __forceinline__ void cpa16(uint32_t dst, const void* src) {
    asm volatile("cp.async.cg.shared.global [%0], [%1], 16;\n" :: "r"(dst), "l"(src));
}
__device__ __forceinline__ void cp_commit() { asm volatile("cp.async.commit_group;\n"); }
template <int N> __device__ __forceinline__ void cp_wait() {
    asm volatile("cp.async.wait_group %0;\n" :: "n"(N));
}

// ---------------- cp.async double-buffered tf32 GEMM ----------------
// acc = sum_k A[m][k]*B[k][n];  y = alpha*(rs?rs[m]:1)*acc + beta*(rb?rb[m]:0)
// OMODE 0: Y[m][n] fp32.
// OMODE 1: fp16 transposed per 64-row head: Yh[(z*HH+h)*ldy + (n0+col)][e], h=r>>6, e=r&63.
// OMODE 2: fp16 direct: Yh[(z*CCH+r)*ldy + c].
template <int BM, int TMt, int OMODE>
__global__ __launch_bounds__(256) void mma_gemm(
    const float* __restrict__ A, const float* __restrict__ B,
    float* __restrict__ Y, __half* __restrict__ Yh,
    int K, int lda, int ldb, int ldy,
    long aB, long bB, long yB, float alpha, float beta,
    const float* __restrict__ rs, const float* __restrict__ rb)
{
    extern __shared__ float sm[];
    float* sA = sm;                 // [2][BM][36]
    float* sB = sm + 2 * BM * 36;   // [2][32][136]

    const int zb = blockIdx.z;
    A += (long)zb * aB;
    B += (long)zb * bB;

    const int tid  = threadIdx.x;
    const int lane = tid & 31;
    const int wid  = tid >> 5;
    const int wm   = wid >> 2;
    const int wn   = wid & 3;
    const int g    = lane >> 2;
    const int tig  = lane & 3;
    const int m0   = blockIdx.y * BM;
    const int n0   = blockIdx.x * 128;

    float4 acc[TMt][4];
#pragma unroll
    for (int i = 0; i < TMt; i++)
#pragma unroll
        for (int j = 0; j < 4; j++) acc[i][j] = make_float4(0.f, 0.f, 0.f, 0.f);

    const int ntiles = K >> 5;

    auto prefetch = [&](int t, int buf) {
        float* dA = sA + buf * BM * 36;
        float* dB = sB + buf * 32 * 136;
#pragma unroll
        for (int i = tid; i < BM * 8; i += 256) {
            int r = i >> 3, c = (i & 7) << 2;
            cpa16(stou(dA + r * 36 + c), A + (long)(m0 + r) * lda + (t << 5) + c);
        }
#pragma unroll
        for (int i = tid; i < 1024; i += 256) {
            int r = i >> 5, c = (i & 31) << 2;
            cpa16(stou(dB + r * 136 + c), B + (long)((t << 5) + r) * ldb + n0 + c);
        }
    };

    prefetch(0, 0);
    cp_commit();

    for (int t = 0; t < ntiles; t++) {
        const int buf = t & 1;
        if (t + 1 < ntiles) {
            prefetch(t + 1, buf ^ 1);
            cp_commit();
            cp_wait<1>();
        } else {
            cp_wait<0>();
        }
        __syncthreads();

        const float* cA = sA + buf * BM * 36;
        const float* cB = sB + buf * 32 * 136;

#pragma unroll
        for (int kk = 0; kk < 32; kk += 8) {
            uint32_t a[TMt][4], b[4][2];
#pragma unroll
            for (int mt = 0; mt < TMt; mt++) {
                int r = wm * (TMt * 16) + mt * 16 + g;
                a[mt][0] = f2tf(cA[r * 36 + kk + tig]);
                a[mt][1] = f2tf(cA[(r + 8) * 36 + kk + tig]);
                a[mt][2] = f2tf(cA[r * 36 + kk + tig + 4]);
                a[mt][3] = f2tf(cA[(r + 8) * 36 + kk + tig + 4]);
            }
#pragma unroll
            for (int nt = 0; nt < 4; nt++) {
                int c = wn * 32 + nt * 8 + g;
                b[nt][0] = f2tf(cB[(kk + tig) * 136 + c]);
                b[nt][1] = f2tf(cB[(kk + tig + 4) * 136 + c]);
            }
#pragma unroll
            for (int mt = 0; mt < TMt; mt++)
#pragma unroll
                for (int nt = 0; nt < 4; nt++)
                    mma_tf32(acc[mt][nt], a[mt], b[nt]);
        }
        __syncthreads();
    }

    if (OMODE == 1) {
        // stage fp16 into smem transposed [col 128][row BM+2], then coalesced store
        __half* sT = reinterpret_cast<__half*>(sm);
        const int st = BM + 2;
#pragma unroll
        for (int mt = 0; mt < TMt; mt++) {
            int rl = wm * (TMt * 16) + mt * 16 + g;
            int r = m0 + rl;
            float s0 = alpha, t0 = beta * (rb ? rb[r] : 0.0f);
            float s1 = alpha, t1 = beta * (rb ? rb[r + 8] : 0.0f);
#pragma unroll
            for (int nt = 0; nt < 4; nt++) {
                int c = wn * 32 + nt * 8 + 2 * tig;
                sT[c * st + rl]           = __float2half_rn(acc[mt][nt].x * s0 + t0);
                sT[(c + 1) * st + rl]     = __float2half_rn(acc[mt][nt].y * s0 + t0);
                sT[c * st + rl + 8]       = __float2half_rn(acc[mt][nt].z * s1 + t1);
                sT[(c + 1) * st + rl + 8] = __float2half_rn(acc[mt][nt].w * s1 + t1);
            }
        }
        __syncthreads();
        uint32_t* Y32 = reinterpret_cast<uint32_t*>(Yh);
        for (int i = tid; i < 128 * (BM / 2); i += 256) {
            int lc = i / (BM / 2);
            int rp = (i % (BM / 2)) * 2;
            uint32_t v = *reinterpret_cast<uint32_t*>(&sT[lc * st + rp]);
            int r = m0 + rp;
            int h = r >> 6, e = r & 63;
            Y32[(((long)zb * HH + h) * ldy + n0 + lc) * 32 + (e >> 1)] = v;
        }
    } else {
#pragma unroll
        for (int mt = 0; mt < TMt; mt++) {
            int r = m0 + wm * (TMt * 16) + mt * 16 + g;
            float s0 = alpha * (rs ? rs[r] : 1.0f),     t0 = beta * (rb ? rb[r] : 0.0f);
            float s1 = alpha * (rs ? rs[r + 8] : 1.0f), t1 = beta * (rb ? rb[r + 8] : 0.0f);
#pragma unroll
            for (int nt = 0; nt < 4; nt++) {
                int c = n0 + wn * 32 + nt * 8 + 2 * tig;
                float y00 = acc[mt][nt].x * s0 + t0, y01 = acc[mt][nt].y * s0 + t0;
                float y10 = acc[mt][nt].z * s1 + t1, y11 = acc[mt][nt].w * s1 + t1;
                if (OMODE == 2) {
                    uint32_t* Y32 = reinterpret_cast<uint32_t*>(Yh);
                    Y32[(((long)zb * CCH + r) * ldy + c) >> 1]       = h2pack(y00, y01);
                    Y32[(((long)zb * CCH + r + 8) * ldy + c) >> 1]   = h2pack(y10, y11);
                } else {
                    float* Yb = Y + (long)zb * yB;
                    *reinterpret_cast<float2*>(Yb + (long)r * ldy + c) = make_float2(y00, y01);
                    *reinterpret_cast<float2*>(Yb + (long)(r + 8) * ldy + c) = make_float2(y10, y11);
                }
            }
        }
    }
}

#define GEMM128_SMEM ((2 * 128 * 36 + 2 * 32 * 136) * 4)
#define GEMM64_SMEM  ((2 * 64 * 36 + 2 * 32 * 136) * 4)

// ---------------- fused flash attention (fp16, 256 threads, warp-exclusive rows) ----------------
// Q: [l][64e] half, K: [m][64e] half, V: [64e][m] half.  8 warps; warp w owns q rows w*16..+16.
// QK: m16n8k16, A=Q(16q x 64e), B=K(8m x 16e). PV: A=P from registers (FA-2 reuse), B=V.
// smem halves: sQ[128][72], sK[2][128][72], sV[64][136]  (72.7 KB total)
#define SQH 0
#define SKH (128 * 72)
#define SVH (SKH + 2 * 128 * 72)
#define FLASH_SMEM_BYTES ((SVH + 64 * 136) * 2)

__global__ __launch_bounds__(256, 1) void flash_kernel(
    const __half* __restrict__ Qh, const __half* __restrict__ Kh,
    const __half* __restrict__ Vh, float* __restrict__ O)
{
    extern __shared__ __half smh[];
    __half* sQ = smh + SQH;
    __half* sK = smh + SKH;
    __half* sV = smh + SVH;
    const uint32_t* sQ32 = reinterpret_cast<const uint32_t*>(sQ);
    const uint32_t* sV32 = reinterpret_cast<const uint32_t*>(sV);

    const int tid  = threadIdx.x;
    const int lane = tid & 31;
    const int w    = tid >> 5;
    const int g    = lane >> 2;
    const int tig  = lane & 3;

    const int l0 = blockIdx.x * 128;
    const int nh = blockIdx.y;
    const int n  = nh >> 2, h = nh & 3;
    const __half* qb = Qh + (((long)(n * HH + h)) * LF + l0) * EE;
    const __half* kb = Kh + ((long)(n * HH + h)) * L2 * EE;
    const __half* vb = Vh + ((long)(n * HH + h)) * EE * L2;
    float*        ob = O + ((long)n * CCH + h * 64) * LF + l0;

    const int row_lo = w * 16 + g;
    const int row_hi = row_lo + 8;

    // prologue: Q tile (128 rows x 64e), K tile 0 (128 rows x 64e)
#pragma unroll
    for (int i = 0; i < 4; i++) {
        int idx = tid + i * 256;
        int r = idx >> 3, c8 = idx & 7;
        cpa16(stou(sQ + r * 72 + c8 * 8), qb + (long)r * EE + c8 * 8);
    }
    cp_commit();
#pragma unroll
    for (int i = 0; i < 4; i++) {
        int idx = tid + i * 256;
        int r = idx >> 3, c8 = idx & 7;
        cpa16(stou(sK + r * 72 + c8 * 8), kb + (long)r * EE + c8 * 8);
    }
    cp_commit();

    float m_lo = -1e30f, m_hi = -1e30f;
    float s_lo = 0.0f,   s_hi = 0.0f;
    float4 accO[8];
#pragma unroll
    for (int nt = 0; nt < 8; nt++) accO[nt] = make_float4(0.f, 0.f, 0.f, 0.f);

#pragma unroll 1
    for (int t = 0; t < 8; t++) {
        const uint32_t* sKb32 = reinterpret_cast<const uint32_t*>(sK + (t & 1) * (128 * 72));

        // prefetch V_t (64 rows x 128 m)
#pragma unroll
        for (int i = 0; i < 4; i++) {
            int idx = tid + i * 256;
            int r = idx >> 4, c16 = idx & 15;
            cpa16(stou(sV + r * 136 + c16 * 8), vb + (long)r * L2 + t * 128 + c16 * 8);
        }
        cp_commit();
        // prefetch K_{t+1}
        if (t < 7) {
            __half* dK = sK + ((t + 1) & 1) * (128 * 72);
            const __half* ksrc = kb + (long)(t + 1) * 128 * EE;
#pragma unroll
            for (int i = 0; i < 4; i++) {
                int idx = tid + i * 256;
                int r = idx >> 3, c8 = idx & 7;
                cpa16(stou(dK + r * 72 + c8 * 8), ksrc + (long)r * EE + c8 * 8);
            }
            cp_commit();
        }

        if (t < 7) cp_wait<2>(); else cp_wait<1>();   // K_t (and Q) ready
        __syncthreads();

        // ---- S = Q K^T : warp 16q x 128keys, k=64e (4 k16-steps, 16 n8-tiles) ----
        float4 accS[16];
#pragma unroll
        for (int nt = 0; nt < 16; nt++) accS[nt] = make_float4(0.f, 0.f, 0.f, 0.f);

#pragma unroll
        for (int kk = 0; kk < 4; kk++) {
            uint32_t a[4];
            a[0] = sQ32[row_lo * 36 + kk * 8 + tig];
            a[1] = sQ32[row_hi * 36 + kk * 8 + tig];
            a[2] = sQ32[row_lo * 36 + kk * 8 + tig + 4];
            a[3] = sQ32[row_hi * 36 + kk * 8 + tig + 4];
#pragma unroll
            for (int nt = 0; nt < 16; nt++) {
                uint32_t b[2];
                b[0] = sKb32[(nt * 8 + g) * 36 + kk * 8 + tig];
                b[1] = sKb32[(nt * 8 + g) * 36 + kk * 8 + tig + 4];
                mma_f16(accS[nt], a, b);
            }
        }

        // ---- warp-local online softmax ----
        float tm_lo = -1e30f, tm_hi = -1e30f;
#pragma unroll
        for (int nt = 0; nt < 16; nt++) {
            tm_lo = fmaxf(tm_lo, fmaxf(accS[nt].x, accS[nt].y));
            tm_hi = fmaxf(tm_hi, fmaxf(accS[nt].z, accS[nt].w));
        }
        tm_lo = fmaxf(tm_lo, __shfl_xor_sync(0xffffffffu, tm_lo, 1));
        tm_lo = fmaxf(tm_lo, __shfl_xor_sync(0xffffffffu, tm_lo, 2));
        tm_hi = fmaxf(tm_hi, __shfl_xor_sync(0xffffffffu, tm_hi, 1));
        tm_hi = fmaxf(tm_hi, __shfl_xor_sync(0xffffffffu, tm_hi, 2));

        float nm_lo = fmaxf(m_lo, tm_lo);
        float nm_hi = fmaxf(m_hi, tm_hi);
        float sc_lo = __expf(m_lo - nm_lo);
        float sc_hi = __expf(m_hi - nm_hi);
        m_lo = nm_lo; m_hi = nm_hi;
        s_lo *= sc_lo; s_hi *= sc_hi;

#pragma unroll
        for (int nt = 0; nt < 8; nt++) {
            accO[nt].x *= sc_lo; accO[nt].y *= sc_lo;
            accO[nt].z *= sc_hi; accO[nt].w *= sc_hi;
        }

        // ---- P = exp(S - rowmax): pack to fp16 in registers, accumulate sums ----
        uint32_t pLo[16], pHi[16];
        float sl = 0.0f, sh = 0.0f;
#pragma unroll
        for (int nt = 0; nt < 16; nt++) {
            float e0 = __expf(accS[nt].x - m_lo);
            float e1 = __expf(accS[nt].y - m_lo);
            float e2 = __expf(accS[nt].z - m_hi);
            float e3 = __expf(accS[nt].w - m_hi);
            sl += e0 + e1;
            sh += e2 + e3;
            pLo[nt] = h2pack(e0, e1);
            pHi[nt] = h2pack(e2, e3);
        }
        sl += __shfl_xor_sync(0xffffffffu, sl, 1);
        sl += __shfl_xor_sync(0xffffffffu, sl, 2);
        sh += __shfl_xor_sync(0xffffffffu, sh, 1);
        sh += __shfl_xor_sync(0xffffffffu, sh, 2);
        s_lo += sl; s_hi += sh;

        // ---- wait V_t, O += P V^T : A=P from regs, 8 k16-steps, 8 n8-tiles ----
        if (t < 7) cp_wait<1>(); else cp_wait<0>();
        __syncthreads();

#pragma unroll
        for (int kk = 0; kk < 8; kk++) {
            uint32_t a[4];
            a[0] = pLo[2 * kk];
            a[1] = pHi[2 * kk];
            a[2] = pLo[2 * kk + 1];
            a[3] = pHi[2 * kk + 1];
#pragma unroll
            for (int nt = 0; nt < 8; nt++) {
                uint32_t b[2];
                b[0] = sV32[(nt * 8 + g) * 68 + kk * 8 + tig];
                b[1] = sV32[(nt * 8 + g) * 68 + kk * 8 + tig + 4];
                mma_f16(accO[nt], a, b);
            }
        }
        __syncthreads();   // all warps done with sV / sK tile before next loads
    }

    // ---- epilogue: O[e][l] = accO / rowsum ----
    float i_lo = 1.0f / s_lo;
    float i_hi = 1.0f / s_hi;
#pragma unroll
    for (int nt = 0; nt < 8; nt++) {
        int e = nt * 8 + 2 * tig;
        ob[(long)e * LF + row_lo]           = accO[nt].x * i_lo;
        ob[(long)(e + 1) * LF + row_lo]     = accO[nt].y * i_lo;
        ob[(long)e * LF + row_hi]           = accO[nt].z * i_hi;
        ob[(long)(e + 1) * LF + row_hi]     = accO[nt].w * i_hi;
    }
}

// ---------------- launch ----------------
extern "C" void kernel_launch(void* const* d_in, const int* in_sizes, int n_in,
                              void* d_out, int out_size) {
    const float* x  = (const float*)d_in[0];
    const float* Wq = (const float*)d_in[1];  const float* bq = (const float*)d_in[2];
    const float* Wk = (const float*)d_in[3];  const float* bk = (const float*)d_in[4];
    const float* Wv = (const float*)d_in[5];  const float* bv = (const float*)d_in[6];
    const float* Wo = (const float*)d_in[7];  const float* bo = (const float*)d_in[8];
    const float* Wa = (const float*)d_in[9];
    const float* g1 = (const float*)d_in[10]; const float* b1 = (const float*)d_in[11];
    const float* m1 = (const float*)d_in[12]; const float* v1 = (const float*)d_in[13];
    const float* g2 = (const float*)d_in[14]; const float* b2 = (const float*)d_in[15];
    const float* m2 = (const float*)d_in[16]; const float* v2 = (const float*)d_in[17];
    float* out = (float*)d_out;
    (void)in_sizes; (void)n_in; (void)out_size;

    float *pXagg, *pXa, *pO, *pS, *pT;
    __half *pQh, *pKh, *pVh;
    cudaGetSymbolAddress((void**)&pXagg, d_xagg);
    cudaGetSymbolAddress((void**)&pXa,   d_xa);
    cudaGetSymbolAddress((void**)&pQh,   d_qh);
    cudaGetSymbolAddress((void**)&pKh,   d_kh);
    cudaGetSymbolAddress((void**)&pVh,   d_vh);
    cudaGetSymbolAddress((void**)&pO,    d_ob);
    cudaGetSymbolAddress((void**)&pS,    d_bns);
    cudaGetSymbolAddress((void**)&pT,    d_bnt);

    cudaFuncSetAttribute(flash_kernel, cudaFuncAttributeMaxDynamicSharedMemorySize,
                         FLASH_SMEM_BYTES);
    cudaFuncSetAttribute(mma_gemm<128, 4, 0>, cudaFuncAttributeMaxDynamicSharedMemorySize,
                         GEMM128_SMEM);
    cudaFuncSetAttribute(mma_gemm<128, 4, 1>, cudaFuncAttributeMaxDynamicSharedMemorySize,
                         GEMM128_SMEM);
    cudaFuncSetAttribute(mma_gemm<64, 2, 0>, cudaFuncAttributeMaxDynamicSharedMemorySize,
                         GEMM64_SMEM);
    cudaFuncSetAttribute(mma_gemm<64, 2, 1>, cudaFuncAttributeMaxDynamicSharedMemorySize,
                         GEMM64_SMEM);
    cudaFuncSetAttribute(mma_gemm<64, 2, 2>, cudaFuncAttributeMaxDynamicSharedMemorySize,
                         GEMM64_SMEM);

    // 1) fold the two BNs
    bnfold_kernel<<<1, 256>>>(g1, b1, m1, v1, g2, b2, m2, v2);

    // 2) avg+max pooling
    aggregate_kernel<<<(NB * CCH * L2) / 256, 256>>>(x);

    // 3) Q = fp16[l][e] of 0.125*(Wq x + bq)
    mma_gemm<128, 4, 1><<<dim3(LF / 128, CCH / 128, NB), 256, GEMM128_SMEM>>>(
        Wq, x, nullptr, pQh, CCH, CCH, LF, LF,
        0, (long)CCH * LF, 0, 0.125f, 0.125f, nullptr, bq);

    // 4) xa = BN2(BN1(Wa @ xagg))  (fp32)
    mma_gemm<64, 2, 0><<<dim3(L2 / 128, CCH / 64, NB), 256, GEMM64_SMEM>>>(
        Wa, pXagg, pXa, nullptr, CCH, CCH, L2, L2,
        0, (long)CCH * L2, (long)CCH * L2, 1.0f, 1.0f, pS, pT);

    // 5) K = fp16[m][e]; V = fp16[e][m]
    mma_gemm<64, 2, 1><<<dim3(L2 / 128, CCH / 64, NB), 256, GEMM64_SMEM>>>(
        Wk, pXa, nullptr, pKh, CCH, CCH, L2, L2,
        0, (long)CCH * L2, 0, 1.0f, 1.0f, nullptr, bk);
    mma_gemm<64, 2, 2><<<dim3(L2 / 128, CCH / 64, NB), 256, GEMM64_SMEM>>>(
        Wv, pXa, nullptr, pVh, CCH, CCH, L2, L2,
        0, (long)CCH * L2, 0, 1.0f, 1.0f, nullptr, bv);

    // 6) fused attention (fp16 mma, register P)
    flash_kernel<<<dim3(LF / 128, NB * HH), 256, FLASH_SMEM_BYTES>>>(pQh, pKh, pVh, pO);

    // 7) out = Wo @ o + bo
    mma_gemm<128, 4, 0><<<dim3(LF / 128, CCH / 128, NB), 256, GEMM128_SMEM>>>(
        Wo, pO, out, nullptr, CCH, CCH, LF, LF,
        0, (long)CCH * LF, (long)CCH * LF, 1.0f, 1.0f, nullptr, bo);
}

// round 9
// speedup vs baseline: 6.6133x; 1.0397x over previous
#include <cuda_runtime.h>
#include <cuda_fp16.h>
#include <cstdint>

// Problem constants
#define NB  4
#define CCH 256
#define LF  4096
#define L2  1024
#define HH  4
#define EE  64

// ---------------- device scratch (static; no cudaMalloc) ----------------
__device__ float  d_xagg[NB * CCH * L2];
__device__ float  d_xa  [NB * CCH * L2];
__device__ __half d_qh  [NB * HH * LF * EE];  // [n][h][l][e] fp16, 0.125*(Wq x + bq)
__device__ __half d_kh  [NB * HH * L2 * EE];  // [n][h][m][e] fp16
__device__ __half d_vh  [NB * HH * EE * L2];  // [n][h][e][m] fp16
__device__ float  d_ob  [NB * CCH * LF];
__device__ float  d_bns[CCH];
__device__ float  d_bnt[CCH];

// ---------------- BN fold ----------------
__global__ void bnfold_kernel(const float* __restrict__ g1, const float* __restrict__ b1,
                              const float* __restrict__ m1, const float* __restrict__ v1,
                              const float* __restrict__ g2, const float* __restrict__ b2,
                              const float* __restrict__ m2, const float* __restrict__ v2) {
    int c = threadIdx.x;
    float i1 = g1[c] * rsqrtf(v1[c] + 1e-5f);
    float c1 = b1[c] - m1[c] * i1;
    float i2 = g2[c] * rsqrtf(v2[c] + 1e-5f);
    float c2 = b2[c] - m2[c] * i2;
    d_bns[c] = i1 * i2;
    d_bnt[c] = c1 * i2 + c2;
}

// ---------------- aggregation: mean + max over groups of 4 ----------------
__global__ void aggregate_kernel(const float* __restrict__ x) {
    int i = blockIdx.x * blockDim.x + threadIdx.x;
    float4 t = reinterpret_cast<const float4*>(x)[i];
    float mx = fmaxf(fmaxf(t.x, t.y), fmaxf(t.z, t.w));
    d_xagg[i] = 0.25f * (t.x + t.y + t.z + t.w) + mx;
}

// ---------------- helpers ----------------
__device__ __forceinline__ uint32_t f2tf(float x) {
    uint32_t r;
    asm("cvt.rna.tf32.f32 %0, %1;" : "=r"(r) : "f"(x));
    return r;
}
__device__ __forceinline__ void mma_tf32(float4& c, const uint32_t a[4], const uint32_t b[2]) {
    asm volatile(
        "mma.sync.aligned.m16n8k8.row.col.f32.tf32.tf32.f32 "
        "{%0,%1,%2,%3}, {%4,%5,%6,%7}, {%8,%9}, {%0,%1,%2,%3};\n"
        : "+f"(c.x), "+f"(c.y), "+f"(c.z), "+f"(c.w)
        : "r"(a[0]), "r"(a[1]), "r"(a[2]), "r"(a[3]), "r"(b[0]), "r"(b[1]));
}
__device__ __forceinline__ void mma_f16(float4& c, const uint32_t a[4], const uint32_t b[2]) {
    asm volatile(
        "mma.sync.aligned.m16n8k16.row.col.f32.f16.f16.f32 "
        "{%0,%1,%2,%3}, {%4,%5,%6,%7}, {%8,%9}, {%0,%1,%2,%3};\n"
        : "+f"(c.x), "+f"(c.y), "+f"(c.z), "+f"(c.w)
        : "r"(a[0]), "r"(a[1]), "r"(a[2]), "r"(a[3]), "r"(b[0]), "r"(b[1]));
}
__device__ __forceinline__ uint32_t h2pack(float a, float b) {
    __half2 h = __floats2half2_rn(a, b);
    return *reinterpret_cast<uint32_t*>(&h);
}
__device__ __forceinline__ uint32_t stou(const void* p) {
    return (uint32_t)__cvta_generic_to_shared(p);
}
__device__ __forceinline__ void cpa16(uint32_t dst, const void* src) {
    asm volatile("cp.async.cg.shared.global [%0], [%1], 16;\n" :: "r"(dst), "l"(src));
}
__device__ __forceinline__ void cp_commit() { asm volatile("cp.async.commit_group;\n"); }
template <int N> __device__ __forceinline__ void cp_wait() {
    asm volatile("cp.async.wait_group %0;\n" :: "n"(N));
}

// ---------------- cp.async 3-stage tf32 GEMM ----------------
// acc = sum_k A[m][k]*B[k][n];  y = alpha*(rs?rs[m]:1)*acc + beta*(rb?rb[m]:0)
// OMODE 0: Y[m][n] fp32.
// OMODE 1: fp16 transposed per 64-row head: Yh[(z*HH+h)*ldy + col][e].
// OMODE 2: fp16 direct: Yh[(z*CCH+r)*ldy + c].
// OMODE 3: DUAL — z even: K path (A,rb -> Yh, transposed); z odd: V path (A2,rb2 -> Yh2, direct).
template <int BM, int TMt, int OMODE>
__global__ __launch_bounds__(256) void mma_gemm(
    const float* __restrict__ A, const float* __restrict__ A2,
    const float* __restrict__ B,
    float* __restrict__ Y, __half* __restrict__ Yh, __half* __restrict__ Yh2,
    int K, int lda, int ldb, int ldy,
    long aB, long bB, long yB, float alpha, float beta,
    const float* __restrict__ rs,
    const float* __restrict__ rb, const float* __restrict__ rb2)
{
    extern __shared__ float sm[];
    float* sA = sm;                 // [3][BM][36]
    float* sB = sm + 3 * BM * 36;   // [3][32][136]

    int sel = 0;
    long zb;
    if (OMODE == 3) {
        sel = blockIdx.z & 1;
        zb  = blockIdx.z >> 1;
        if (sel) { A = A2; rb = rb2; }
    } else {
        zb = blockIdx.z;
    }
    A += zb * aB;
    B += zb * bB;

    const int tid  = threadIdx.x;
    const int lane = tid & 31;
    const int wid  = tid >> 5;
    const int wm   = wid >> 2;
    const int wn   = wid & 3;
    const int g    = lane >> 2;
    const int tig  = lane & 3;
    const int m0   = blockIdx.y * BM;
    const int n0   = blockIdx.x * 128;

    float4 acc[TMt][4];
#pragma unroll
    for (int i = 0; i < TMt; i++)
#pragma unroll
        for (int j = 0; j < 4; j++) acc[i][j] = make_float4(0.f, 0.f, 0.f, 0.f);

    const int ntiles = K >> 5;

    auto prefetch = [&](int t, int buf) {
        float* dA = sA + buf * BM * 36;
        float* dB = sB + buf * 32 * 136;
#pragma unroll
        for (int i = tid; i < BM * 8; i += 256) {
            int r = i >> 3, c = (i & 7) << 2;
            cpa16(stou(dA + r * 36 + c), A + (long)(m0 + r) * lda + (t << 5) + c);
        }
#pragma unroll
        for (int i = tid; i < 1024; i += 256) {
            int r = i >> 5, c = (i & 31) << 2;
            cpa16(stou(dB + r * 136 + c), B + (long)((t << 5) + r) * ldb + n0 + c);
        }
    };

    prefetch(0, 0); cp_commit();
    prefetch(1, 1); cp_commit();

    for (int t = 0; t < ntiles; t++) {
        if (t < ntiles - 1) cp_wait<1>(); else cp_wait<0>();
        __syncthreads();
        if (t + 2 < ntiles) { prefetch(t + 2, (t + 2) % 3); cp_commit(); }

        const float* cA = sA + (t % 3) * BM * 36;
        const float* cB = sB + (t % 3) * 32 * 136;

#pragma unroll
        for (int kk = 0; kk < 32; kk += 8) {
            uint32_t a[TMt][4], b[4][2];
#pragma unroll
            for (int mt = 0; mt < TMt; mt++) {
                int r = wm * (TMt * 16) + mt * 16 + g;
                a[mt][0] = f2tf(cA[r * 36 + kk + tig]);
                a[mt][1] = f2tf(cA[(r + 8) * 36 + kk + tig]);
                a[mt][2] = f2tf(cA[r * 36 + kk + tig + 4]);
                a[mt][3] = f2tf(cA[(r + 8) * 36 + kk + tig + 4]);
            }
#pragma unroll
            for (int nt = 0; nt < 4; nt++) {
                int c = wn * 32 + nt * 8 + g;
                b[nt][0] = f2tf(cB[(kk + tig) * 136 + c]);
                b[nt][1] = f2tf(cB[(kk + tig + 4) * 136 + c]);
            }
#pragma unroll
            for (int mt = 0; mt < TMt; mt++)
#pragma unroll
                for (int nt = 0; nt < 4; nt++)
                    mma_tf32(acc[mt][nt], a[mt], b[nt]);
        }
        // no trailing sync: next iteration syncs before touching smem buffers
    }

    const bool kpath = (OMODE == 1) || (OMODE == 3 && sel == 0);
    if (kpath) {
        // transpose to fp16 via smem, then coalesced store: Yh[(zb*HH+h)*ldy + col][e]
        __syncthreads();   // smem reuse: last compute tile must be finished block-wide
        __half* sT = reinterpret_cast<__half*>(sm);
        const int st = BM + 2;
#pragma unroll
        for (int mt = 0; mt < TMt; mt++) {
            int rl = wm * (TMt * 16) + mt * 16 + g;
            int r = m0 + rl;
            float t0 = beta * (rb ? rb[r] : 0.0f);
            float t1 = beta * (rb ? rb[r + 8] : 0.0f);
#pragma unroll
            for (int nt = 0; nt < 4; nt++) {
                int c = wn * 32 + nt * 8 + 2 * tig;
                sT[c * st + rl]           = __float2half_rn(acc[mt][nt].x * alpha + t0);
                sT[(c + 1) * st + rl]     = __float2half_rn(acc[mt][nt].y * alpha + t0);
                sT[c * st + rl + 8]       = __float2half_rn(acc[mt][nt].z * alpha + t1);
                sT[(c + 1) * st + rl + 8] = __float2half_rn(acc[mt][nt].w * alpha + t1);
            }
        }
        __syncthreads();
        uint32_t* Y32 = reinterpret_cast<uint32_t*>(Yh);
        for (int i = tid; i < 128 * (BM / 2); i += 256) {
            int lc = i / (BM / 2);
            int rp = (i % (BM / 2)) * 2;
            uint32_t v = *reinterpret_cast<uint32_t*>(&sT[lc * st + rp]);
            int r = m0 + rp;
            int h = r >> 6, e = r & 63;
            Y32[((zb * HH + h) * (long)ldy + n0 + lc) * 32 + (e >> 1)] = v;
        }
    } else {
#pragma unroll
        for (int mt = 0; mt < TMt; mt++) {
            int r = m0 + wm * (TMt * 16) + mt * 16 + g;
            float s0 = alpha * (rs ? rs[r] : 1.0f),     t0 = beta * (rb ? rb[r] : 0.0f);
            float s1 = alpha * (rs ? rs[r + 8] : 1.0f), t1 = beta * (rb ? rb[r + 8] : 0.0f);
#pragma unroll
            for (int nt = 0; nt < 4; nt++) {
                int c = n0 + wn * 32 + nt * 8 + 2 * tig;
                float y00 = acc[mt][nt].x * s0 + t0, y01 = acc[mt][nt].y * s0 + t0;
                float y10 = acc[mt][nt].z * s1 + t1, y11 = acc[mt][nt].w * s1 + t1;
                if (OMODE == 2 || OMODE == 3) {
                    __half* Yd = (OMODE == 3) ? Yh2 : Yh;
                    uint32_t* Y32 = reinterpret_cast<uint32_t*>(Yd);
                    Y32[((zb * CCH + r) * (long)ldy + c) >> 1]     = h2pack(y00, y01);
                    Y32[((zb * CCH + r + 8) * (long)ldy + c) >> 1] = h2pack(y10, y11);
                } else {
                    float* Yb = Y + zb * yB;
                    *reinterpret_cast<float2*>(Yb + (long)r * ldy + c) = make_float2(y00, y01);
                    *reinterpret_cast<float2*>(Yb + (long)(r + 8) * ldy + c) = make_float2(y10, y11);
                }
            }
        }
    }
}

#define GEMM128_SMEM (3 * (128 * 36 + 32 * 136) * 4)
#define GEMM64_SMEM  (3 * (64 * 36 + 32 * 136) * 4)

// ---------------- fused flash attention (fp16, double-buffered K AND V) ----------------
// Q: [l][64e], K: [m][64e], V: [64e][m] fp16.  8 warps; warp w owns q rows w*16..+16.
// One __syncthreads per key tile; K_{t+1}+V_{t+1} prefetched in a single cp.async group.
#define SQH 0
#define SKH (128 * 72)
#define SVH (SKH + 2 * 128 * 72)
#define FLASH_SMEM_BYTES ((SVH + 2 * 64 * 136) * 2)

__global__ __launch_bounds__(256, 1) void flash_kernel(
    const __half* __restrict__ Qh, const __half* __restrict__ Kh,
    const __half* __restrict__ Vh, float* __restrict__ O)
{
    extern __shared__ __half smh[];
    __half* sQ = smh + SQH;
    __half* sK = smh + SKH;
    __half* sV = smh + SVH;
    const uint32_t* sQ32 = reinterpret_cast<const uint32_t*>(sQ);

    const int tid  = threadIdx.x;
    const int lane = tid & 31;
    const int w    = tid >> 5;
    const int g    = lane >> 2;
    const int tig  = lane & 3;

    const int l0 = blockIdx.x * 128;
    const int nh = blockIdx.y;
    const int n  = nh >> 2, h = nh & 3;
    const __half* qb = Qh + (((long)(n * HH + h)) * LF + l0) * EE;
    const __half* kb = Kh + ((long)(n * HH + h)) * L2 * EE;
    const __half* vb = Vh + ((long)(n * HH + h)) * EE * L2;
    float*        ob = O + ((long)n * CCH + h * 64) * LF + l0;

    const int row_lo = w * 16 + g;
    const int row_hi = row_lo + 8;

    // prologue: Q (group 0); K0+V0 (group 1)
#pragma unroll
    for (int i = 0; i < 4; i++) {
        int idx = tid + i * 256;
        int r = idx >> 3, c8 = idx & 7;
        cpa16(stou(sQ + r * 72 + c8 * 8), qb + (long)r * EE + c8 * 8);
    }
    cp_commit();
#pragma unroll
    for (int i = 0; i < 4; i++) {
        int idx = tid + i * 256;
        int r = idx >> 3, c8 = idx & 7;
        cpa16(stou(sK + r * 72 + c8 * 8), kb + (long)r * EE + c8 * 8);
    }
#pragma unroll
    for (int i = 0; i < 4; i++) {
        int idx = tid + i * 256;
        int r = idx >> 4, c16 = idx & 15;
        cpa16(stou(sV + r * 136 + c16 * 8), vb + (long)r * L2 + c16 * 8);
    }
    cp_commit();

    float m_lo = -1e30f, m_hi = -1e30f;
    float s_lo = 0.0f,   s_hi = 0.0f;
    float4 accO[8];
#pragma unroll
    for (int nt = 0; nt < 8; nt++) accO[nt] = make_float4(0.f, 0.f, 0.f, 0.f);

#pragma unroll 1
    for (int t = 0; t < 8; t++) {
        cp_wait<0>();          // tile-t K/V (and Q) resident
        __syncthreads();       // everyone done with tile t-1 buffers

        // prefetch K_{t+1}, V_{t+1} into the other buffers (one group)
        if (t < 7) {
            __half* dK = sK + ((t + 1) & 1) * (128 * 72);
            const __half* ksrc = kb + (long)(t + 1) * 128 * EE;
#pragma unroll
            for (int i = 0; i < 4; i++) {
                int idx = tid + i * 256;
                int r = idx >> 3, c8 = idx & 7;
                cpa16(stou(dK + r * 72 + c8 * 8), ksrc + (long)r * EE + c8 * 8);
            }
            __half* dV = sV + ((t + 1) & 1) * (64 * 136);
#pragma unroll
            for (int i = 0; i < 4; i++) {
                int idx = tid + i * 256;
                int r = idx >> 4, c16 = idx & 15;
                cpa16(stou(dV + r * 136 + c16 * 8), vb + (long)r * L2 + (t + 1) * 128 + c16 * 8);
            }
            cp_commit();
        }

        const uint32_t* sKb32 = reinterpret_cast<const uint32_t*>(sK + (t & 1) * (128 * 72));
        const uint32_t* sVb32 = reinterpret_cast<const uint32_t*>(sV + (t & 1) * (64 * 136));

        // ---- S = Q K^T : warp 16q x 128keys (4 k16-steps, 16 n8-tiles) ----
        float4 accS[16];
#pragma unroll
        for (int nt = 0; nt < 16; nt++) accS[nt] = make_float4(0.f, 0.f, 0.f, 0.f);

#pragma unroll
        for (int kk = 0; kk < 4; kk++) {
            uint32_t a[4];
            a[0] = sQ32[row_lo * 36 + kk * 8 + tig];
            a[1] = sQ32[row_hi * 36 + kk * 8 + tig];
            a[2] = sQ32[row_lo * 36 + kk * 8 + tig + 4];
            a[3] = sQ32[row_hi * 36 + kk * 8 + tig + 4];
#pragma unroll
            for (int nt = 0; nt < 16; nt++) {
                uint32_t b[2];
                b[0] = sKb32[(nt * 8 + g) * 36 + kk * 8 + tig];
                b[1] = sKb32[(nt * 8 + g) * 36 + kk * 8 + tig + 4];
                mma_f16(accS[nt], a, b);
            }
        }

        // ---- warp-local online softmax ----
        float tm_lo = -1e30f, tm_hi = -1e30f;
#pragma unroll
        for (int nt = 0; nt < 16; nt++) {
            tm_lo = fmaxf(tm_lo, fmaxf(accS[nt].x, accS[nt].y));
            tm_hi = fmaxf(tm_hi, fmaxf(accS[nt].z, accS[nt].w));
        }
        tm_lo = fmaxf(tm_lo, __shfl_xor_sync(0xffffffffu, tm_lo, 1));
        tm_lo = fmaxf(tm_lo, __shfl_xor_sync(0xffffffffu, tm_lo, 2));
        tm_hi = fmaxf(tm_hi, __shfl_xor_sync(0xffffffffu, tm_hi, 1));
        tm_hi = fmaxf(tm_hi, __shfl_xor_sync(0xffffffffu, tm_hi, 2));

        float nm_lo = fmaxf(m_lo, tm_lo);
        float nm_hi = fmaxf(m_hi, tm_hi);
        float sc_lo = __expf(m_lo - nm_lo);
        float sc_hi = __expf(m_hi - nm_hi);
        m_lo = nm_lo; m_hi = nm_hi;
        s_lo *= sc_lo; s_hi *= sc_hi;

#pragma unroll
        for (int nt = 0; nt < 8; nt++) {
            accO[nt].x *= sc_lo; accO[nt].y *= sc_lo;
            accO[nt].z *= sc_hi; accO[nt].w *= sc_hi;
        }

        // ---- P = exp(S - rowmax): fp16 in registers, accumulate sums ----
        uint32_t pLo[16], pHi[16];
        float sl = 0.0f, sh = 0.0f;
#pragma unroll
        for (int nt = 0; nt < 16; nt++) {
            float e0 = __expf(accS[nt].x - m_lo);
            float e1 = __expf(accS[nt].y - m_lo);
            float e2 = __expf(accS[nt].z - m_hi);
            float e3 = __expf(accS[nt].w - m_hi);
            sl += e0 + e1;
            sh += e2 + e3;
            pLo[nt] = h2pack(e0, e1);
            pHi[nt] = h2pack(e2, e3);
        }
        sl += __shfl_xor_sync(0xffffffffu, sl, 1);
        sl += __shfl_xor_sync(0xffffffffu, sl, 2);
        sh += __shfl_xor_sync(0xffffffffu, sh, 1);
        sh += __shfl_xor_sync(0xffffffffu, sh, 2);
        s_lo += sl; s_hi += sh;

        // ---- O += P V^T : A=P from regs (8 k16-steps, 8 n8-tiles) ----
#pragma unroll
        for (int kk = 0; kk < 8; kk++) {
            uint32_t a[4];
            a[0] = pLo[2 * kk];
            a[1] = pHi[2 * kk];
            a[2] = pLo[2 * kk + 1];
            a[3] = pHi[2 * kk + 1];
#pragma unroll
            for (int nt = 0; nt < 8; nt++) {
                uint32_t b[2];
                b[0] = sVb32[(nt * 8 + g) * 68 + kk * 8 + tig];
                b[1] = sVb32[(nt * 8 + g) * 68 + kk * 8 + tig + 4];
                mma_f16(accO[nt], a, b);
            }
        }
        // no trailing sync: next iteration's sync protects the buffers
    }

    // ---- epilogue: O[e][l] = accO / rowsum ----
    float i_lo = 1.0f / s_lo;
    float i_hi = 1.0f / s_hi;
#pragma unroll
    for (int nt = 0; nt < 8; nt++) {
        int e = nt * 8 + 2 * tig;
        ob[(long)e * LF + row_lo]           = accO[nt].x * i_lo;
        ob[(long)(e + 1) * LF + row_lo]     = accO[nt].y * i_lo;
        ob[(long)e * LF + row_hi]           = accO[nt].z * i_hi;
        ob[(long)(e + 1) * LF + row_hi]     = accO[nt].w * i_hi;
    }
}

// ---------------- launch ----------------
extern "C" void kernel_launch(void* const* d_in, const int* in_sizes, int n_in,
                              void* d_out, int out_size) {
    const float* x  = (const float*)d_in[0];
    const float* Wq = (const float*)d_in[1];  const float* bq = (const float*)d_in[2];
    const float* Wk = (const float*)d_in[3];  const float* bk = (const float*)d_in[4];
    const float* Wv = (const float*)d_in[5];  const float* bv = (const float*)d_in[6];
    const float* Wo = (const float*)d_in[7];  const float* bo = (const float*)d_in[8];
    const float* Wa = (const float*)d_in[9];
    const float* g1 = (const float*)d_in[10]; const float* b1 = (const float*)d_in[11];
    const float* m1 = (const float*)d_in[12]; const float* v1 = (const float*)d_in[13];
    const float* g2 = (const float*)d_in[14]; const float* b2 = (const float*)d_in[15];
    const float* m2 = (const float*)d_in[16]; const float* v2 = (const float*)d_in[17];
    float* out = (float*)d_out;
    (void)in_sizes; (void)n_in; (void)out_size;

    float *pXagg, *pXa, *pO, *pS, *pT;
    __half *pQh, *pKh, *pVh;
    cudaGetSymbolAddress((void**)&pXagg, d_xagg);
    cudaGetSymbolAddress((void**)&pXa,   d_xa);
    cudaGetSymbolAddress((void**)&pQh,   d_qh);
    cudaGetSymbolAddress((void**)&pKh,   d_kh);
    cudaGetSymbolAddress((void**)&pVh,   d_vh);
    cudaGetSymbolAddress((void**)&pO,    d_ob);
    cudaGetSymbolAddress((void**)&pS,    d_bns);
    cudaGetSymbolAddress((void**)&pT,    d_bnt);

    cudaFuncSetAttribute(flash_kernel, cudaFuncAttributeMaxDynamicSharedMemorySize,
                         FLASH_SMEM_BYTES);
    cudaFuncSetAttribute(mma_gemm<128, 4, 0>, cudaFuncAttributeMaxDynamicSharedMemorySize,
                         GEMM128_SMEM);
    cudaFuncSetAttribute(mma_gemm<128, 4, 1>, cudaFuncAttributeMaxDynamicSharedMemorySize,
                         GEMM128_SMEM);
    cudaFuncSetAttribute(mma_gemm<64, 2, 0>, cudaFuncAttributeMaxDynamicSharedMemorySize,
                         GEMM64_SMEM);
    cudaFuncSetAttribute(mma_gemm<64, 2, 3>, cudaFuncAttributeMaxDynamicSharedMemorySize,
                         GEMM64_SMEM);

    // 1) fold the two BNs
    bnfold_kernel<<<1, 256>>>(g1, b1, m1, v1, g2, b2, m2, v2);

    // 2) avg+max pooling
    aggregate_kernel<<<(NB * CCH * L2) / 256, 256>>>(x);

    // 3) Q = fp16[l][e] of 0.125*(Wq x + bq)
    mma_gemm<128, 4, 1><<<dim3(LF / 128, CCH / 128, NB), 256, GEMM128_SMEM>>>(
        Wq, nullptr, x, nullptr, pQh, nullptr, CCH, CCH, LF, LF,
        0, (long)CCH * LF, 0, 0.125f, 0.125f, nullptr, bq, nullptr);

    // 4) xa = BN2(BN1(Wa @ xagg))  (fp32)
    mma_gemm<64, 2, 0><<<dim3(L2 / 128, CCH / 64, NB), 256, GEMM64_SMEM>>>(
        Wa, nullptr, pXagg, pXa, nullptr, nullptr, CCH, CCH, L2, L2,
        0, (long)CCH * L2, (long)CCH * L2, 1.0f, 1.0f, pS, pT, nullptr);

    // 5) K = fp16[m][e] and V = fp16[e][m] in ONE dual launch
    mma_gemm<64, 2, 3><<<dim3(L2 / 128, CCH / 64, NB * 2), 256, GEMM64_SMEM>>>(
        Wk, Wv, pXa, nullptr, pKh, pVh, CCH, CCH, L2, L2,
        0, (long)CCH * L2, 0, 1.0f, 1.0f, nullptr, bk, bv);

    // 6) fused attention (fp16 mma, register P, 1 sync/tile)
    flash_kernel<<<dim3(LF / 128, NB * HH), 256, FLASH_SMEM_BYTES>>>(pQh, pKh, pVh, pO);

    // 7) out = Wo @ o + bo
    mma_gemm<128, 4, 0><<<dim3(LF / 128, CCH / 128, NB), 256, GEMM128_SMEM>>>(
        Wo, nullptr, pO, out, nullptr, nullptr, CCH, CCH, LF, LF,
        0, (long)CCH * LF, (long)CCH * LF, 1.0f, 1.0f, nullptr, bo, nullptr);
}

// round 11
// speedup vs baseline: 7.0131x; 1.0605x over previous
#include <cuda_runtime.h>
#include <cuda_fp16.h>
#include <cstdint>

// Problem constants
#define NB  4
#define CCH 256
#define LF  4096
#define L2  1024
#define HH  4
#define EE  64

// ---------------- device scratch (static; no cudaMalloc) ----------------
__device__ float  d_xagg[NB * CCH * L2];
__device__ float  d_xa  [NB * CCH * L2];
__device__ __half d_qh  [NB * HH * LF * EE];  // [n][h][l][e] fp16, log2e*0.125*(Wq x + bq)
__device__ __half d_kh  [NB * HH * L2 * EE];  // [n][h][m][e] fp16
__device__ __half d_vh  [NB * HH * EE * L2];  // [n][h][e][m] fp16
__device__ float  d_ob  [NB * CCH * LF];
__device__ float  d_bns[CCH];
__device__ float  d_bnt[CCH];

// ---------------- BN fold ----------------
__global__ void bnfold_kernel(const float* __restrict__ g1, const float* __restrict__ b1,
                              const float* __restrict__ m1, const float* __restrict__ v1,
                              const float* __restrict__ g2, const float* __restrict__ b2,
                              const float* __restrict__ m2, const float* __restrict__ v2) {
    int c = threadIdx.x;
    float i1 = g1[c] * rsqrtf(v1[c] + 1e-5f);
    float c1 = b1[c] - m1[c] * i1;
    float i2 = g2[c] * rsqrtf(v2[c] + 1e-5f);
    float c2 = b2[c] - m2[c] * i2;
    d_bns[c] = i1 * i2;
    d_bnt[c] = c1 * i2 + c2;
}

// ---------------- aggregation: mean + max over groups of 4 ----------------
__global__ void aggregate_kernel(const float* __restrict__ x) {
    int i = blockIdx.x * blockDim.x + threadIdx.x;
    float4 t = reinterpret_cast<const float4*>(x)[i];
    float mx = fmaxf(fmaxf(t.x, t.y), fmaxf(t.z, t.w));
    d_xagg[i] = 0.25f * (t.x + t.y + t.z + t.w) + mx;
}

// ---------------- helpers ----------------
__device__ __forceinline__ uint32_t f2tf(float x) {
    uint32_t r;
    asm("cvt.rna.tf32.f32 %0, %1;" : "=r"(r) : "f"(x));
    return r;
}
__device__ __forceinline__ void mma_tf32(float4& c, const uint32_t a[4], const uint32_t b[2]) {
    asm volatile(
        "mma.sync.aligned.m16n8k8.row.col.f32.tf32.tf32.f32 "
        "{%0,%1,%2,%3}, {%4,%5,%6,%7}, {%8,%9}, {%0,%1,%2,%3};\n"
        : "+f"(c.x), "+f"(c.y), "+f"(c.z), "+f"(c.w)
        : "r"(a[0]), "r"(a[1]), "r"(a[2]), "r"(a[3]), "r"(b[0]), "r"(b[1]));
}
__device__ __forceinline__ void mma_f16(float4& c, uint32_t a0, uint32_t a1, uint32_t a2,
                                        uint32_t a3, uint32_t b0, uint32_t b1) {
    asm volatile(
        "mma.sync.aligned.m16n8k16.row.col.f32.f16.f16.f32 "
        "{%0,%1,%2,%3}, {%4,%5,%6,%7}, {%8,%9}, {%0,%1,%2,%3};\n"
        : "+f"(c.x), "+f"(c.y), "+f"(c.z), "+f"(c.w)
        : "r"(a0), "r"(a1), "r"(a2), "r"(a3), "r"(b0), "r"(b1));
}
__device__ __forceinline__ uint32_t h2pack(float a, float b) {
    __half2 h = __floats2half2_rn(a, b);
    return *reinterpret_cast<uint32_t*>(&h);
}
__device__ __forceinline__ uint32_t ex2h2(uint32_t in) {
    uint32_t r;
    asm("ex2.approx.f16x2 %0, %1;" : "=r"(r) : "r"(in));
    return r;
}
__device__ __forceinline__ float ex2f(float x) {
    float r;
    asm("ex2.approx.f32 %0, %1;" : "=f"(r) : "f"(x));
    return r;
}
__device__ __forceinline__ uint32_t stou(const void* p) {
    return (uint32_t)__cvta_generic_to_shared(p);
}
__device__ __forceinline__ void cpa16(uint32_t dst, const void* src) {
    asm volatile("cp.async.cg.shared.global [%0], [%1], 16;\n" :: "r"(dst), "l"(src));
}
__device__ __forceinline__ void cp_commit() { asm volatile("cp.async.commit_group;\n"); }
template <int N> __device__ __forceinline__ void cp_wait() {
    asm volatile("cp.async.wait_group %0;\n" :: "n"(N));
}
#define LDSM_X4(r0, r1, r2, r3, addr) \
    asm volatile("ldmatrix.sync.aligned.m8n8.x4.shared.b16 {%0,%1,%2,%3}, [%4];" \
                 : "=r"(r0), "=r"(r1), "=r"(r2), "=r"(r3) : "r"(addr))
#define LDSM_X2(r0, r1, addr) \
    asm volatile("ldmatrix.sync.aligned.m8n8.x2.shared.b16 {%0,%1}, [%2];" \
                 : "=r"(r0), "=r"(r1) : "r"(addr))

// ---------------- cp.async 3-stage tf32 GEMM (unchanged machinery) ----------------
// OMODE 0: Y[m][n] fp32.  OMODE 1: fp16 transposed per 64-row head.
// OMODE 2: fp16 direct.   OMODE 3: DUAL K/V (z even: K transposed, z odd: V direct).
template <int BM, int TMt, int OMODE>
__global__ __launch_bounds__(256) void mma_gemm(
    const float* __restrict__ A, const float* __restrict__ A2,
    const float* __restrict__ B,
    float* __restrict__ Y, __half* __restrict__ Yh, __half* __restrict__ Yh2,
    int K, int lda, int ldb, int ldy,
    long aB, long bB, long yB, float alpha, float beta,
    const float* __restrict__ rs,
    const float* __restrict__ rb, const float* __restrict__ rb2)
{
    extern __shared__ float sm[];
    float* sA = sm;
    float* sB = sm + 3 * BM * 36;

    int sel = 0;
    long zb;
    if (OMODE == 3) {
        sel = blockIdx.z & 1;
        zb  = blockIdx.z >> 1;
        if (sel) { A = A2; rb = rb2; }
    } else {
        zb = blockIdx.z;
    }
    A += zb * aB;
    B += zb * bB;

    const int tid  = threadIdx.x;
    const int lane = tid & 31;
    const int wid  = tid >> 5;
    const int wm   = wid >> 2;
    const int wn   = wid & 3;
    const int g    = lane >> 2;
    const int tig  = lane & 3;
    const int m0   = blockIdx.y * BM;
    const int n0   = blockIdx.x * 128;

    float4 acc[TMt][4];
#pragma unroll
    for (int i = 0; i < TMt; i++)
#pragma unroll
        for (int j = 0; j < 4; j++) acc[i][j] = make_float4(0.f, 0.f, 0.f, 0.f);

    const int ntiles = K >> 5;

    auto prefetch = [&](int t, int buf) {
        float* dA = sA + buf * BM * 36;
        float* dB = sB + buf * 32 * 136;
#pragma unroll
        for (int i = tid; i < BM * 8; i += 256) {
            int r = i >> 3, c = (i & 7) << 2;
            cpa16(stou(dA + r * 36 + c), A + (long)(m0 + r) * lda + (t << 5) + c);
        }
#pragma unroll
        for (int i = tid; i < 1024; i += 256) {
            int r = i >> 5, c = (i & 31) << 2;
            cpa16(stou(dB + r * 136 + c), B + (long)((t << 5) + r) * ldb + n0 + c);
        }
    };

    prefetch(0, 0); cp_commit();
    prefetch(1, 1); cp_commit();

    for (int t = 0; t < ntiles; t++) {
        if (t < ntiles - 1) cp_wait<1>(); else cp_wait<0>();
        __syncthreads();
        if (t + 2 < ntiles) { prefetch(t + 2, (t + 2) % 3); cp_commit(); }

        const float* cA = sA + (t % 3) * BM * 36;
        const float* cB = sB + (t % 3) * 32 * 136;

#pragma unroll
        for (int kk = 0; kk < 32; kk += 8) {
            uint32_t a[TMt][4], b[4][2];
#pragma unroll
            for (int mt = 0; mt < TMt; mt++) {
                int r = wm * (TMt * 16) + mt * 16 + g;
                a[mt][0] = f2tf(cA[r * 36 + kk + tig]);
                a[mt][1] = f2tf(cA[(r + 8) * 36 + kk + tig]);
                a[mt][2] = f2tf(cA[r * 36 + kk + tig + 4]);
                a[mt][3] = f2tf(cA[(r + 8) * 36 + kk + tig + 4]);
            }
#pragma unroll
            for (int nt = 0; nt < 4; nt++) {
                int c = wn * 32 + nt * 8 + g;
                b[nt][0] = f2tf(cB[(kk + tig) * 136 + c]);
                b[nt][1] = f2tf(cB[(kk + tig + 4) * 136 + c]);
            }
#pragma unroll
            for (int mt = 0; mt < TMt; mt++)
#pragma unroll
                for (int nt = 0; nt < 4; nt++)
                    mma_tf32(acc[mt][nt], a[mt], b[nt]);
        }
    }

    const bool kpath = (OMODE == 1) || (OMODE == 3 && sel == 0);
    if (kpath) {
        __syncthreads();
        __half* sT = reinterpret_cast<__half*>(sm);
        const int st = BM + 2;
#pragma unroll
        for (int mt = 0; mt < TMt; mt++) {
            int rl = wm * (TMt * 16) + mt * 16 + g;
            int r = m0 + rl;
            float t0 = beta * (rb ? rb[r] : 0.0f);
            float t1 = beta * (rb ? rb[r + 8] : 0.0f);
#pragma unroll
            for (int nt = 0; nt < 4; nt++) {
                int c = wn * 32 + nt * 8 + 2 * tig;
                sT[c * st + rl]           = __float2half_rn(acc[mt][nt].x * alpha + t0);
                sT[(c + 1) * st + rl]     = __float2half_rn(acc[mt][nt].y * alpha + t0);
                sT[c * st + rl + 8]       = __float2half_rn(acc[mt][nt].z * alpha + t1);
                sT[(c + 1) * st + rl + 8] = __float2half_rn(acc[mt][nt].w * alpha + t1);
            }
        }
        __syncthreads();
        uint32_t* Y32 = reinterpret_cast<uint32_t*>(Yh);
        for (int i = tid; i < 128 * (BM / 2); i += 256) {
            int lc = i / (BM / 2);
            int rp = (i % (BM / 2)) * 2;
            uint32_t v = *reinterpret_cast<uint32_t*>(&sT[lc * st + rp]);
            int r = m0 + rp;
            int h = r >> 6, e = r & 63;
            Y32[((zb * HH + h) * (long)ldy + n0 + lc) * 32 + (e >> 1)] = v;
        }
    } else {
#pragma unroll
        for (int mt = 0; mt < TMt; mt++) {
            int r = m0 + wm * (TMt * 16) + mt * 16 + g;
            float s0 = alpha * (rs ? rs[r] : 1.0f),     t0 = beta * (rb ? rb[r] : 0.0f);
            float s1 = alpha * (rs ? rs[r + 8] : 1.0f), t1 = beta * (rb ? rb[r + 8] : 0.0f);
#pragma unroll
            for (int nt = 0; nt < 4; nt++) {
                int c = n0 + wn * 32 + nt * 8 + 2 * tig;
                float y00 = acc[mt][nt].x * s0 + t0, y01 = acc[mt][nt].y * s0 + t0;
                float y10 = acc[mt][nt].z * s1 + t1, y11 = acc[mt][nt].w * s1 + t1;
                if (OMODE == 2 || OMODE == 3) {
                    __half* Yd = (OMODE == 3) ? Yh2 : Yh;
                    uint32_t* Y32 = reinterpret_cast<uint32_t*>(Yd);
                    Y32[((zb * CCH + r) * (long)ldy + c) >> 1]     = h2pack(y00, y01);
                    Y32[((zb * CCH + r + 8) * (long)ldy + c) >> 1] = h2pack(y10, y11);
                } else {
                    float* Yb = Y + zb * yB;
                    *reinterpret_cast<float2*>(Yb + (long)r * ldy + c) = make_float2(y00, y01);
                    *reinterpret_cast<float2*>(Yb + (long)(r + 8) * ldy + c) = make_float2(y10, y11);
                }
            }
        }
    }
}

#define GEMM128_SMEM (3 * (128 * 36 + 32 * 136) * 4)
#define GEMM64_SMEM  (3 * (64 * 36 + 32 * 136) * 4)

// ---------------- fused flash attention (ldmatrix + ex2.f16x2 + mma row-sum) ----------------
// Q: [l][64e] (log2-domain), K: [m][64e], V: [64e][m] fp16.
// sV has 72 e-rows: row 64 = ones, 65-71 = zeros -> accO[8] accumulates row sums.
#define SQH 0
#define SKH (128 * 72)
#define SVH (SKH + 2 * 128 * 72)
#define FLASH_SMEM_BYTES ((SVH + 2 * 72 * 136) * 2)

__global__ __launch_bounds__(256, 1) void flash_kernel(
    const __half* __restrict__ Qh, const __half* __restrict__ Kh,
    const __half* __restrict__ Vh, float* __restrict__ O)
{
    extern __shared__ __half smh[];
    __half* sQ = smh + SQH;
    __half* sK = smh + SKH;
    __half* sV = smh + SVH;

    const int tid  = threadIdx.x;
    const int lane = tid & 31;
    const int w    = tid >> 5;
    const int g    = lane >> 2;
    const int tig  = lane & 3;

    const int l0 = blockIdx.x * 128;
    const int nh = blockIdx.y;
    const int n  = nh >> 2, h = nh & 3;
    const __half* qb = Qh + (((long)(n * HH + h)) * LF + l0) * EE;
    const __half* kb = Kh + ((long)(n * HH + h)) * L2 * EE;
    const __half* vb = Vh + ((long)(n * HH + h)) * EE * L2;
    float*        ob = O + ((long)n * CCH + h * 64) * LF + l0;

    const int row_lo = w * 16 + g;
    const int row_hi = row_lo + 8;

    // ldmatrix per-lane address offsets (bytes)
    const int qrow = lane & 7;
    const int sel  = lane >> 3;          // 0..3
    const uint32_t sQb = stou(sQ), sKb0 = stou(sK), sVb0 = stou(sV);
    const uint32_t qa_off = ((w * 16 + (lane & 15)) * 72 + (lane >> 4) * 8) * 2;
    const uint32_t kb_off = (((sel >> 1) * 8 + qrow) * 72 + (sel & 1) * 8) * 2;
    const uint32_t vb_off = (((sel >> 1) * 8 + qrow) * 136 + (sel & 1) * 8) * 2;
    const uint32_t v2_off = ((64 + qrow) * 136 + ((lane >> 3) & 1) * 8) * 2;

    // prologue: Q (group 0); K0+V0 (group 1)
#pragma unroll
    for (int i = 0; i < 4; i++) {
        int idx = tid + i * 256;
        int r = idx >> 3, c8 = idx & 7;
        cpa16(stou(sQ + r * 72 + c8 * 8), qb + (long)r * EE + c8 * 8);
    }
    cp_commit();
#pragma unroll
    for (int i = 0; i < 4; i++) {
        int idx = tid + i * 256;
        int r = idx >> 3, c8 = idx & 7;
        cpa16(stou(sK + r * 72 + c8 * 8), kb + (long)r * EE + c8 * 8);
    }
#pragma unroll
    for (int i = 0; i < 4; i++) {
        int idx = tid + i * 256;
        int r = idx >> 4, c16 = idx & 15;
        cpa16(stou(sV + r * 136 + c16 * 8), vb + (long)r * L2 + c16 * 8);
    }
    cp_commit();

    // init ones/zeros rows 64-71 of both V buffers (cp.async never touches them)
    {
        uint32_t* sV32w = reinterpret_cast<uint32_t*>(sV);
        for (int i = tid; i < 2 * 8 * 68; i += 256) {
            int buf = i / (8 * 68);
            int rem = i % (8 * 68);
            int r = rem / 68, c = rem % 68;
            sV32w[buf * (72 * 68) + (64 + r) * 68 + c] = (r == 0) ? 0x3C003C00u : 0u;
        }
    }

    float m_lo = -1e30f, m_hi = -1e30f;
    float4 accO[9];
#pragma unroll
    for (int nt = 0; nt < 9; nt++) accO[nt] = make_float4(0.f, 0.f, 0.f, 0.f);

    cp_wait<0>();
    __syncthreads();   // Q, K0, V0 resident; ones rows visible

    // hoist Q A-fragments (tile-invariant)
    uint32_t qa[4][4];
#pragma unroll
    for (int kk = 0; kk < 4; kk++)
        LDSM_X4(qa[kk][0], qa[kk][1], qa[kk][2], qa[kk][3], sQb + qa_off + kk * 32);

#pragma unroll 1
    for (int t = 0; t < 8; t++) {
        if (t > 0) {
            cp_wait<0>();
            __syncthreads();   // K_t/V_t resident; all warps done with t-1 buffers
        }
        // prefetch K_{t+1}, V_{t+1}
        if (t < 7) {
            __half* dK = sK + ((t + 1) & 1) * (128 * 72);
            const __half* ksrc = kb + (long)(t + 1) * 128 * EE;
#pragma unroll
            for (int i = 0; i < 4; i++) {
                int idx = tid + i * 256;
                int r = idx >> 3, c8 = idx & 7;
                cpa16(stou(dK + r * 72 + c8 * 8), ksrc + (long)r * EE + c8 * 8);
            }
            __half* dV = sV + ((t + 1) & 1) * (72 * 136);
#pragma unroll
            for (int i = 0; i < 4; i++) {
                int idx = tid + i * 256;
                int r = idx >> 4, c16 = idx & 15;
                cpa16(stou(dV + r * 136 + c16 * 8), vb + (long)r * L2 + (t + 1) * 128 + c16 * 8);
            }
            cp_commit();
        }

        const uint32_t kbase = sKb0 + (uint32_t)((t & 1) * (128 * 72 * 2));
        const uint32_t vbase = sVb0 + (uint32_t)((t & 1) * (72 * 136 * 2));

        // ---- S = Q K^T : 4 k16-steps x 16 n8-tiles via ldmatrix.x4 pairs ----
        float4 accS[16];
#pragma unroll
        for (int nt = 0; nt < 16; nt++) accS[nt] = make_float4(0.f, 0.f, 0.f, 0.f);

#pragma unroll
        for (int kk = 0; kk < 4; kk++) {
#pragma unroll
            for (int jp = 0; jp < 8; jp++) {
                uint32_t b0, b1, b2, b3;
                LDSM_X4(b0, b1, b2, b3, kbase + jp * (16 * 72 * 2) + kk * 32 + kb_off);
                mma_f16(accS[2 * jp],     qa[kk][0], qa[kk][1], qa[kk][2], qa[kk][3], b0, b1);
                mma_f16(accS[2 * jp + 1], qa[kk][0], qa[kk][1], qa[kk][2], qa[kk][3], b2, b3);
            }
        }

        // ---- warp-local online softmax (log2 domain) ----
        float tm_lo = -1e30f, tm_hi = -1e30f;
#pragma unroll
        for (int nt = 0; nt < 16; nt++) {
            tm_lo = fmaxf(tm_lo, fmaxf(accS[nt].x, accS[nt].y));
            tm_hi = fmaxf(tm_hi, fmaxf(accS[nt].z, accS[nt].w));
        }
        tm_lo = fmaxf(tm_lo, __shfl_xor_sync(0xffffffffu, tm_lo, 1));
        tm_lo = fmaxf(tm_lo, __shfl_xor_sync(0xffffffffu, tm_lo, 2));
        tm_hi = fmaxf(tm_hi, __shfl_xor_sync(0xffffffffu, tm_hi, 1));
        tm_hi = fmaxf(tm_hi, __shfl_xor_sync(0xffffffffu, tm_hi, 2));

        float nm_lo = fmaxf(m_lo, tm_lo);
        float nm_hi = fmaxf(m_hi, tm_hi);
        float sc_lo = ex2f(m_lo - nm_lo);
        float sc_hi = ex2f(m_hi - nm_hi);
        m_lo = nm_lo; m_hi = nm_hi;

#pragma unroll
        for (int nt = 0; nt < 9; nt++) {
            accO[nt].x *= sc_lo; accO[nt].y *= sc_lo;
            accO[nt].z *= sc_hi; accO[nt].w *= sc_hi;
        }

        // ---- P = exp2(S - m) via ex2.approx.f16x2 (packed) ----
        uint32_t pLo[16], pHi[16];
#pragma unroll
        for (int nt = 0; nt < 16; nt++) {
            pLo[nt] = ex2h2(h2pack(accS[nt].x - m_lo, accS[nt].y - m_lo));
            pHi[nt] = ex2h2(h2pack(accS[nt].z - m_hi, accS[nt].w - m_hi));
        }

        // ---- O += P V^T (and row-sum via ones tile): 8 k16-steps ----
#pragma unroll
        for (int kk = 0; kk < 8; kk++) {
            uint32_t a0 = pLo[2 * kk], a1 = pHi[2 * kk];
            uint32_t a2 = pLo[2 * kk + 1], a3 = pHi[2 * kk + 1];
#pragma unroll
            for (int jp = 0; jp < 4; jp++) {
                uint32_t b0, b1, b2, b3;
                LDSM_X4(b0, b1, b2, b3, vbase + jp * (16 * 136 * 2) + kk * 32 + vb_off);
                mma_f16(accO[2 * jp],     a0, a1, a2, a3, b0, b1);
                mma_f16(accO[2 * jp + 1], a0, a1, a2, a3, b2, b3);
            }
            uint32_t c0, c1;
            LDSM_X2(c0, c1, vbase + kk * 32 + v2_off);
            mma_f16(accO[8], a0, a1, a2, a3, c0, c1);
        }
        // no trailing sync: next iteration's sync protects the buffers
    }

    // ---- epilogue: O[e][l] = accO / rowsum (rowsum = accO[8] col 0 at tig=0) ----
    float s_lo = __shfl_sync(0xffffffffu, accO[8].x, lane & ~3);
    float s_hi = __shfl_sync(0xffffffffu, accO[8].z, lane & ~3);
    float i_lo = 1.0f / s_lo;
    float i_hi = 1.0f / s_hi;
#pragma unroll
    for (int nt = 0; nt < 8; nt++) {
        int e = nt * 8 + 2 * tig;
        ob[(long)e * LF + row_lo]           = accO[nt].x * i_lo;
        ob[(long)(e + 1) * LF + row_lo]     = accO[nt].y * i_lo;
        ob[(long)e * LF + row_hi]           = accO[nt].z * i_hi;
        ob[(long)(e + 1) * LF + row_hi]     = accO[nt].w * i_hi;
    }
}

// ---------------- launch ----------------
extern "C" void kernel_launch(void* const* d_in, const int* in_sizes, int n_in,
                              void* d_out, int out_size) {
    const float* x  = (const float*)d_in[0];
    const float* Wq = (const float*)d_in[1];  const float* bq = (const float*)d_in[2];
    const float* Wk = (const float*)d_in[3];  const float* bk = (const float*)d_in[4];
    const float* Wv = (const float*)d_in[5];  const float* bv = (const float*)d_in[6];
    const float* Wo = (const float*)d_in[7];  const float* bo = (const float*)d_in[8];
    const float* Wa = (const float*)d_in[9];
    const float* g1 = (const float*)d_in[10]; const float* b1 = (const float*)d_in[11];
    const float* m1 = (const float*)d_in[12]; const float* v1 = (const float*)d_in[13];
    const float* g2 = (const float*)d_in[14]; const float* b2 = (const float*)d_in[15];
    const float* m2 = (const float*)d_in[16]; const float* v2 = (const float*)d_in[17];
    float* out = (float*)d_out;
    (void)in_sizes; (void)n_in; (void)out_size;

    float *pXagg, *pXa, *pO, *pS, *pT;
    __half *pQh, *pKh, *pVh;
    cudaGetSymbolAddress((void**)&pXagg, d_xagg);
    cudaGetSymbolAddress((void**)&pXa,   d_xa);
    cudaGetSymbolAddress((void**)&pQh,   d_qh);
    cudaGetSymbolAddress((void**)&pKh,   d_kh);
    cudaGetSymbolAddress((void**)&pVh,   d_vh);
    cudaGetSymbolAddress((void**)&pO,    d_ob);
    cudaGetSymbolAddress((void**)&pS,    d_bns);
    cudaGetSymbolAddress((void**)&pT,    d_bnt);

    cudaFuncSetAttribute(flash_kernel, cudaFuncAttributeMaxDynamicSharedMemorySize,
                         FLASH_SMEM_BYTES);
    cudaFuncSetAttribute(mma_gemm<128, 4, 0>, cudaFuncAttributeMaxDynamicSharedMemorySize,
                         GEMM128_SMEM);
    cudaFuncSetAttribute(mma_gemm<128, 4, 1>, cudaFuncAttributeMaxDynamicSharedMemorySize,
                         GEMM128_SMEM);
    cudaFuncSetAttribute(mma_gemm<64, 2, 0>, cudaFuncAttributeMaxDynamicSharedMemorySize,
                         GEMM64_SMEM);
    cudaFuncSetAttribute(mma_gemm<64, 2, 3>, cudaFuncAttributeMaxDynamicSharedMemorySize,
                         GEMM64_SMEM);

    const float QSCALE = 0.125f * 1.44269504089f;  // fold 1/sqrt(E) and log2e into Q

    // 1) fold the two BNs
    bnfold_kernel<<<1, 256>>>(g1, b1, m1, v1, g2, b2, m2, v2);

    // 2) avg+max pooling
    aggregate_kernel<<<(NB * CCH * L2) / 256, 256>>>(x);

    // 3) Q = fp16[l][e] of log2e*0.125*(Wq x + bq)
    mma_gemm<128, 4, 1><<<dim3(LF / 128, CCH / 128, NB), 256, GEMM128_SMEM>>>(
        Wq, nullptr, x, nullptr, pQh, nullptr, CCH, CCH, LF, LF,
        0, (long)CCH * LF, 0, QSCALE, QSCALE, nullptr, bq, nullptr);

    // 4) xa = BN2(BN1(Wa @ xagg))  (fp32)
    mma_gemm<64, 2, 0><<<dim3(L2 / 128, CCH / 64, NB), 256, GEMM64_SMEM>>>(
        Wa, nullptr, pXagg, pXa, nullptr, nullptr, CCH, CCH, L2, L2,
        0, (long)CCH * L2, (long)CCH * L2, 1.0f, 1.0f, pS, pT, nullptr);

    // 5) K = fp16[m][e] and V = fp16[e][m] in ONE dual launch
    mma_gemm<64, 2, 3><<<dim3(L2 / 128, CCH / 64, NB * 2), 256, GEMM64_SMEM>>>(
        Wk, Wv, pXa, nullptr, pKh, pVh, CCH, CCH, L2, L2,
        0, (long)CCH * L2, 0, 1.0f, 1.0f, nullptr, bk, bv);

    // 6) fused attention
    flash_kernel<<<dim3(LF / 128, NB * HH), 256, FLASH_SMEM_BYTES>>>(pQh, pKh, pVh, pO);

    // 7) out = Wo @ o + bo
    mma_gemm<128, 4, 0><<<dim3(LF / 128, CCH / 128, NB), 256, GEMM128_SMEM>>>(
        Wo, nullptr, pO, out, nullptr, nullptr, CCH, CCH, LF, LF,
        0, (long)CCH * LF, (long)CCH * LF, 1.0f, 1.0f, nullptr, bo, nullptr);
}

// round 12
// speedup vs baseline: 8.3586x; 1.1919x over previous
#include <cuda_runtime.h>
#include <cuda_fp16.h>
#include <cstdint>

// Problem constants
#define NB  4
#define CCH 256
#define LF  4096
#define L2  1024
#define HH  4
#define EE  64

// ---------------- device scratch (static; no cudaMalloc) ----------------
__device__ __half d_xh   [NB * CCH * LF];   // fp16 copy of x
__device__ __half d_xaggh[NB * CCH * L2];   // fp16 pooled input
__device__ __half d_xah  [NB * CCH * L2];   // fp16 BN'd aggregation
__device__ __half d_qh   [NB * HH * LF * EE];  // [n][h][l][e], log2e*0.125*(Wq x + bq)
__device__ __half d_kh   [NB * HH * L2 * EE];  // [n][h][m][e]
__device__ __half d_vh   [NB * HH * EE * L2];  // [n][h][e][m]
__device__ __half d_oh   [NB * CCH * LF];   // attention output [n][C][L] fp16
__device__ __half d_wqh[CCH * CCH], d_wkh[CCH * CCH], d_wvh[CCH * CCH];
__device__ __half d_woh[CCH * CCH], d_wah[CCH * CCH];
__device__ float  d_bns[CCH];
__device__ float  d_bnt[CCH];

// ---------------- BN fold ----------------
__global__ void bnfold_kernel(const float* __restrict__ g1, const float* __restrict__ b1,
                              const float* __restrict__ m1, const float* __restrict__ v1,
                              const float* __restrict__ g2, const float* __restrict__ b2,
                              const float* __restrict__ m2, const float* __restrict__ v2) {
    int c = threadIdx.x;
    float i1 = g1[c] * rsqrtf(v1[c] + 1e-5f);
    float c1 = b1[c] - m1[c] * i1;
    float i2 = g2[c] * rsqrtf(v2[c] + 1e-5f);
    float c2 = b2[c] - m2[c] * i2;
    d_bns[c] = i1 * i2;
    d_bnt[c] = c1 * i2 + c2;
}

// ---------------- conversions ----------------
__global__ void cvtx_kernel(const float* __restrict__ x) {
    int i = blockIdx.x * blockDim.x + threadIdx.x;
    float4 t = reinterpret_cast<const float4*>(x)[i];
    __half2* o = reinterpret_cast<__half2*>(d_xh);
    o[2 * i]     = __floats2half2_rn(t.x, t.y);
    o[2 * i + 1] = __floats2half2_rn(t.z, t.w);
}

__global__ void cvtw_kernel(const float* __restrict__ wq, const float* __restrict__ wk,
                            const float* __restrict__ wv, const float* __restrict__ wo,
                            const float* __restrict__ wa) {
    const float* src[5] = {wq, wk, wv, wo, wa};
    __half* dst[5] = {d_wqh, d_wkh, d_wvh, d_woh, d_wah};
    int m = blockIdx.y;
    int i = blockIdx.x * blockDim.x + threadIdx.x;   // float4 index, 16384 per matrix
    float4 t = reinterpret_cast<const float4*>(src[m])[i];
    __half2* o = reinterpret_cast<__half2*>(dst[m]);
    o[2 * i]     = __floats2half2_rn(t.x, t.y);
    o[2 * i + 1] = __floats2half2_rn(t.z, t.w);
}

// ---------------- aggregation: mean + max over groups of 4, fp16 out ----------------
__global__ void aggregate_kernel(const float* __restrict__ x) {
    int i = blockIdx.x * blockDim.x + threadIdx.x;
    float4 t = reinterpret_cast<const float4*>(x)[i];
    float mx = fmaxf(fmaxf(t.x, t.y), fmaxf(t.z, t.w));
    d_xaggh[i] = __float2half_rn(0.25f * (t.x + t.y + t.z + t.w) + mx);
}

// ---------------- helpers ----------------
__device__ __forceinline__ void mma_f16(float4& c, uint32_t a0, uint32_t a1, uint32_t a2,
                                        uint32_t a3, uint32_t b0, uint32_t b1) {
    asm volatile(
        "mma.sync.aligned.m16n8k16.row.col.f32.f16.f16.f32 "
        "{%0,%1,%2,%3}, {%4,%5,%6,%7}, {%8,%9}, {%0,%1,%2,%3};\n"
        : "+f"(c.x), "+f"(c.y), "+f"(c.z), "+f"(c.w)
        : "r"(a0), "r"(a1), "r"(a2), "r"(a3), "r"(b0), "r"(b1));
}
__device__ __forceinline__ uint32_t h2pack(float a, float b) {
    __half2 h = __floats2half2_rn(a, b);
    return *reinterpret_cast<uint32_t*>(&h);
}
__device__ __forceinline__ uint32_t ex2h2(uint32_t in) {
    uint32_t r;
    asm("ex2.approx.f16x2 %0, %1;" : "=r"(r) : "r"(in));
    return r;
}
__device__ __forceinline__ float ex2f(float x) {
    float r;
    asm("ex2.approx.f32 %0, %1;" : "=f"(r) : "f"(x));
    return r;
}
__device__ __forceinline__ uint32_t stou(const void* p) {
    return (uint32_t)__cvta_generic_to_shared(p);
}
__device__ __forceinline__ void cpa16(uint32_t dst, const void* src) {
    asm volatile("cp.async.cg.shared.global [%0], [%1], 16;\n" :: "r"(dst), "l"(src));
}
__device__ __forceinline__ void cp_commit() { asm volatile("cp.async.commit_group;\n"); }
template <int N> __device__ __forceinline__ void cp_wait() {
    asm volatile("cp.async.wait_group %0;\n" :: "n"(N));
}
#define LDSM_X4(r0, r1, r2, r3, addr) \
    asm volatile("ldmatrix.sync.aligned.m8n8.x4.shared.b16 {%0,%1,%2,%3}, [%4];" \
                 : "=r"(r0), "=r"(r1), "=r"(r2), "=r"(r3) : "r"(addr))
#define LDSM_X4_T(r0, r1, r2, r3, addr) \
    asm volatile("ldmatrix.sync.aligned.m8n8.x4.trans.shared.b16 {%0,%1,%2,%3}, [%4];" \
                 : "=r"(r0), "=r"(r1), "=r"(r2), "=r"(r3) : "r"(addr))
#define LDSM_X2(r0, r1, addr) \
    asm volatile("ldmatrix.sync.aligned.m8n8.x2.shared.b16 {%0,%1}, [%2];" \
                 : "=r"(r0), "=r"(r1) : "r"(addr))

// ---------------- fp16 3-stage GEMM ----------------
// acc = sum_k A[m][k]*B[k][n]  (A fp16 [M][K] lda, B fp16 [K][N] ldb, K=256)
// y = alpha*(rs?rs[m]:1)*acc + beta*(rb?rb[m]:0)
// OMODE 0: Y fp32 [m][n].  OMODE 1: fp16 transposed per 64-row head -> Yh[(z*HH+h)*ldy+col][e].
// OMODE 2: fp16 direct Yh[(z*CCH+r)*ldy+c].  OMODE 3: DUAL (z even: K transposed; z odd: V direct).
template <int BM, int TMt, int OMODE>
__global__ __launch_bounds__(256) void hgemm(
    const __half* __restrict__ A, const __half* __restrict__ A2,
    const __half* __restrict__ B,
    float* __restrict__ Y, __half* __restrict__ Yh, __half* __restrict__ Yh2,
    int lda, int ldb, int ldy,
    long aB, long bB, long yB, float alpha, float beta,
    const float* __restrict__ rs,
    const float* __restrict__ rb, const float* __restrict__ rb2)
{
    extern __shared__ __half smH[];
    __half* sA = smH;                   // [3][BM][40]
    __half* sB = smH + 3 * BM * 40;     // [3][32][136]

    int sel = 0;
    long zb;
    if (OMODE == 3) {
        sel = blockIdx.z & 1;
        zb  = blockIdx.z >> 1;
        if (sel) { A = A2; rb = rb2; }
    } else {
        zb = blockIdx.z;
    }
    A += zb * aB;
    B += zb * bB;

    const int tid  = threadIdx.x;
    const int lane = tid & 31;
    const int wid  = tid >> 5;
    const int wm   = wid >> 2;
    const int wn   = wid & 3;
    const int g    = lane >> 2;
    const int tig  = lane & 3;
    const int m0   = blockIdx.y * BM;
    const int n0   = blockIdx.x * 128;

    const uint32_t a_off = ((lane & 15) * 40 + (lane >> 4) * 8) * 2;
    const uint32_t b_off = ((lane & 15) * 136 + (lane >> 4) * 8) * 2;

    float4 acc[TMt][4];
#pragma unroll
    for (int i = 0; i < TMt; i++)
#pragma unroll
        for (int j = 0; j < 4; j++) acc[i][j] = make_float4(0.f, 0.f, 0.f, 0.f);

    auto prefetch = [&](int t, int buf) {
        __half* dA = sA + buf * BM * 40;
        __half* dB = sB + buf * 32 * 136;
#pragma unroll
        for (int i = tid; i < BM * 4; i += 256) {
            int r = i >> 2, c = (i & 3) * 8;
            cpa16(stou(dA + r * 40 + c), A + (long)(m0 + r) * lda + t * 32 + c);
        }
#pragma unroll
        for (int i = tid; i < 512; i += 256) {
            int r = i >> 4, c = (i & 15) * 8;
            cpa16(stou(dB + r * 136 + c), B + (long)(t * 32 + r) * ldb + n0 + c);
        }
    };

    prefetch(0, 0); cp_commit();
    prefetch(1, 1); cp_commit();

    for (int t = 0; t < 8; t++) {
        if (t < 7) cp_wait<1>(); else cp_wait<0>();
        __syncthreads();
        if (t + 2 < 8) { prefetch(t + 2, (t + 2) % 3); cp_commit(); }

        const uint32_t aBase = stou(sA) + (uint32_t)((t % 3) * BM * 40 * 2);
        const uint32_t bBase = stou(sB) + (uint32_t)((t % 3) * 32 * 136 * 2);

#pragma unroll
        for (int s = 0; s < 2; s++) {
            uint32_t a[TMt][4];
#pragma unroll
            for (int mt = 0; mt < TMt; mt++)
                LDSM_X4(a[mt][0], a[mt][1], a[mt][2], a[mt][3],
                        aBase + (uint32_t)(((wm * TMt * 16 + mt * 16) * 40 + s * 16) * 2) + a_off);
            uint32_t b[2][4];
#pragma unroll
            for (int j = 0; j < 2; j++)
                LDSM_X4_T(b[j][0], b[j][1], b[j][2], b[j][3],
                          bBase + (uint32_t)((s * 16 * 136 + wn * 32 + j * 16) * 2) + b_off);
#pragma unroll
            for (int mt = 0; mt < TMt; mt++)
#pragma unroll
                for (int nt = 0; nt < 4; nt++)
                    mma_f16(acc[mt][nt], a[mt][0], a[mt][1], a[mt][2], a[mt][3],
                            b[nt >> 1][(nt & 1) * 2], b[nt >> 1][(nt & 1) * 2 + 1]);
        }
    }

    const bool kpath = (OMODE == 1) || (OMODE == 3 && sel == 0);
    if (kpath) {
        __syncthreads();
        __half* sT = smH;
        const int st = BM + 2;
#pragma unroll
        for (int mt = 0; mt < TMt; mt++) {
            int rl = wm * (TMt * 16) + mt * 16 + g;
            int r = m0 + rl;
            float t0 = beta * (rb ? rb[r] : 0.0f);
            float t1 = beta * (rb ? rb[r + 8] : 0.0f);
#pragma unroll
            for (int nt = 0; nt < 4; nt++) {
                int c = wn * 32 + nt * 8 + 2 * tig;
                sT[c * st + rl]           = __float2half_rn(acc[mt][nt].x * alpha + t0);
                sT[(c + 1) * st + rl]     = __float2half_rn(acc[mt][nt].y * alpha + t0);
                sT[c * st + rl + 8]       = __float2half_rn(acc[mt][nt].z * alpha + t1);
                sT[(c + 1) * st + rl + 8] = __float2half_rn(acc[mt][nt].w * alpha + t1);
            }
        }
        __syncthreads();
        uint32_t* Y32 = reinterpret_cast<uint32_t*>(Yh);
        for (int i = tid; i < 128 * (BM / 2); i += 256) {
            int lc = i / (BM / 2);
            int rp = (i % (BM / 2)) * 2;
            uint32_t v = *reinterpret_cast<uint32_t*>(&sT[lc * st + rp]);
            int r = m0 + rp;
            int h = r >> 6, e = r & 63;
            Y32[((zb * HH + h) * (long)ldy + n0 + lc) * 32 + (e >> 1)] = v;
        }
    } else {
#pragma unroll
        for (int mt = 0; mt < TMt; mt++) {
            int r = m0 + wm * (TMt * 16) + mt * 16 + g;
            float s0 = alpha * (rs ? rs[r] : 1.0f),     t0 = beta * (rb ? rb[r] : 0.0f);
            float s1 = alpha * (rs ? rs[r + 8] : 1.0f), t1 = beta * (rb ? rb[r + 8] : 0.0f);
#pragma unroll
            for (int nt = 0; nt < 4; nt++) {
                int c = n0 + wn * 32 + nt * 8 + 2 * tig;
                float y00 = acc[mt][nt].x * s0 + t0, y01 = acc[mt][nt].y * s0 + t0;
                float y10 = acc[mt][nt].z * s1 + t1, y11 = acc[mt][nt].w * s1 + t1;
                if (OMODE == 2 || OMODE == 3) {
                    __half* Yd = (OMODE == 3) ? Yh2 : Yh;
                    uint32_t* Y32 = reinterpret_cast<uint32_t*>(Yd);
                    Y32[((zb * CCH + r) * (long)ldy + c) >> 1]     = h2pack(y00, y01);
                    Y32[((zb * CCH + r + 8) * (long)ldy + c) >> 1] = h2pack(y10, y11);
                } else {
                    float* Yb = Y + zb * yB;
                    *reinterpret_cast<float2*>(Yb + (long)r * ldy + c) = make_float2(y00, y01);
                    *reinterpret_cast<float2*>(Yb + (long)(r + 8) * ldy + c) = make_float2(y10, y11);
                }
            }
        }
    }
}

#define HGEMM128_SMEM (3 * (128 * 40 + 32 * 136) * 2)
#define HGEMM64_SMEM  (3 * (64 * 40 + 32 * 136) * 2)

// ---------------- fused flash attention (fp16 in, fp16 out) ----------------
#define SQH 0
#define SKH (128 * 72)
#define SVH (SKH + 2 * 128 * 72)
#define FLASH_SMEM_BYTES ((SVH + 2 * 72 * 136) * 2)

__global__ __launch_bounds__(256, 1) void flash_kernel(
    const __half* __restrict__ Qh, const __half* __restrict__ Kh,
    const __half* __restrict__ Vh, __half* __restrict__ O)
{
    extern __shared__ __half smh[];
    __half* sQ = smh + SQH;
    __half* sK = smh + SKH;
    __half* sV = smh + SVH;

    const int tid  = threadIdx.x;
    const int lane = tid & 31;
    const int w    = tid >> 5;
    const int g    = lane >> 2;
    const int tig  = lane & 3;

    const int l0 = blockIdx.x * 128;
    const int nh = blockIdx.y;
    const int n  = nh >> 2, h = nh & 3;
    const __half* qb = Qh + (((long)(n * HH + h)) * LF + l0) * EE;
    const __half* kb = Kh + ((long)(n * HH + h)) * L2 * EE;
    const __half* vb = Vh + ((long)(n * HH + h)) * EE * L2;
    __half*       ob = O + ((long)n * CCH + h * 64) * LF + l0;

    const int row_lo = w * 16 + g;
    const int row_hi = row_lo + 8;

    const int qrow = lane & 7;
    const int sel  = lane >> 3;
    const uint32_t sQb = stou(sQ), sKb0 = stou(sK), sVb0 = stou(sV);
    const uint32_t qa_off = ((w * 16 + (lane & 15)) * 72 + (lane >> 4) * 8) * 2;
    const uint32_t kb_off = (((sel >> 1) * 8 + qrow) * 72 + (sel & 1) * 8) * 2;
    const uint32_t vb_off = (((sel >> 1) * 8 + qrow) * 136 + (sel & 1) * 8) * 2;
    const uint32_t v2_off = ((64 + qrow) * 136 + ((lane >> 3) & 1) * 8) * 2;

    // prologue: Q (group 0); K0+V0 (group 1)
#pragma unroll
    for (int i = 0; i < 4; i++) {
        int idx = tid + i * 256;
        int r = idx >> 3, c8 = idx & 7;
        cpa16(stou(sQ + r * 72 + c8 * 8), qb + (long)r * EE + c8 * 8);
    }
    cp_commit();
#pragma unroll
    for (int i = 0; i < 4; i++) {
        int idx = tid + i * 256;
        int r = idx >> 3, c8 = idx & 7;
        cpa16(stou(sK + r * 72 + c8 * 8), kb + (long)r * EE + c8 * 8);
    }
#pragma unroll
    for (int i = 0; i < 4; i++) {
        int idx = tid + i * 256;
        int r = idx >> 4, c16 = idx & 15;
        cpa16(stou(sV + r * 136 + c16 * 8), vb + (long)r * L2 + c16 * 8);
    }
    cp_commit();

    // ones/zeros rows 64-71 of both V buffers
    {
        uint32_t* sV32w = reinterpret_cast<uint32_t*>(sV);
        for (int i = tid; i < 2 * 8 * 68; i += 256) {
            int buf = i / (8 * 68);
            int rem = i % (8 * 68);
            int r = rem / 68, c = rem % 68;
            sV32w[buf * (72 * 68) + (64 + r) * 68 + c] = (r == 0) ? 0x3C003C00u : 0u;
        }
    }

    float m_lo = -1e30f, m_hi = -1e30f;
    float4 accO[9];
#pragma unroll
    for (int nt = 0; nt < 9; nt++) accO[nt] = make_float4(0.f, 0.f, 0.f, 0.f);

    cp_wait<0>();
    __syncthreads();

    uint32_t qa[4][4];
#pragma unroll
    for (int kk = 0; kk < 4; kk++)
        LDSM_X4(qa[kk][0], qa[kk][1], qa[kk][2], qa[kk][3], sQb + qa_off + kk * 32);

#pragma unroll 1
    for (int t = 0; t < 8; t++) {
        if (t > 0) {
            cp_wait<0>();
            __syncthreads();
        }
        if (t < 7) {
            __half* dK = sK + ((t + 1) & 1) * (128 * 72);
            const __half* ksrc = kb + (long)(t + 1) * 128 * EE;
#pragma unroll
            for (int i = 0; i < 4; i++) {
                int idx = tid + i * 256;
                int r = idx >> 3, c8 = idx & 7;
                cpa16(stou(dK + r * 72 + c8 * 8), ksrc + (long)r * EE + c8 * 8);
            }
            __half* dV = sV + ((t + 1) & 1) * (72 * 136);
#pragma unroll
            for (int i = 0; i < 4; i++) {
                int idx = tid + i * 256;
                int r = idx >> 4, c16 = idx & 15;
                cpa16(stou(dV + r * 136 + c16 * 8), vb + (long)r * L2 + (t + 1) * 128 + c16 * 8);
            }
            cp_commit();
        }

        const uint32_t kbase = sKb0 + (uint32_t)((t & 1) * (128 * 72 * 2));
        const uint32_t vbase = sVb0 + (uint32_t)((t & 1) * (72 * 136 * 2));

        float4 accS[16];
#pragma unroll
        for (int nt = 0; nt < 16; nt++) accS[nt] = make_float4(0.f, 0.f, 0.f, 0.f);

#pragma unroll
        for (int kk = 0; kk < 4; kk++) {
#pragma unroll
            for (int jp = 0; jp < 8; jp++) {
                uint32_t b0, b1, b2, b3;
                LDSM_X4(b0, b1, b2, b3, kbase + jp * (16 * 72 * 2) + kk * 32 + kb_off);
                mma_f16(accS[2 * jp],     qa[kk][0], qa[kk][1], qa[kk][2], qa[kk][3], b0, b1);
                mma_f16(accS[2 * jp + 1], qa[kk][0], qa[kk][1], qa[kk][2], qa[kk][3], b2, b3);
            }
        }

        float tm_lo = -1e30f, tm_hi = -1e30f;
#pragma unroll
        for (int nt = 0; nt < 16; nt++) {
            tm_lo = fmaxf(tm_lo, fmaxf(accS[nt].x, accS[nt].y));
            tm_hi = fmaxf(tm_hi, fmaxf(accS[nt].z, accS[nt].w));
        }
        tm_lo = fmaxf(tm_lo, __shfl_xor_sync(0xffffffffu, tm_lo, 1));
        tm_lo = fmaxf(tm_lo, __shfl_xor_sync(0xffffffffu, tm_lo, 2));
        tm_hi = fmaxf(tm_hi, __shfl_xor_sync(0xffffffffu, tm_hi, 1));
        tm_hi = fmaxf(tm_hi, __shfl_xor_sync(0xffffffffu, tm_hi, 2));

        float nm_lo = fmaxf(m_lo, tm_lo);
        float nm_hi = fmaxf(m_hi, tm_hi);
        float sc_lo = ex2f(m_lo - nm_lo);
        float sc_hi = ex2f(m_hi - nm_hi);
        m_lo = nm_lo; m_hi = nm_hi;

#pragma unroll
        for (int nt = 0; nt < 9; nt++) {
            accO[nt].x *= sc_lo; accO[nt].y *= sc_lo;
            accO[nt].z *= sc_hi; accO[nt].w *= sc_hi;
        }

        uint32_t pLo[16], pHi[16];
#pragma unroll
        for (int nt = 0; nt < 16; nt++) {
            pLo[nt] = ex2h2(h2pack(accS[nt].x - m_lo, accS[nt].y - m_lo));
            pHi[nt] = ex2h2(h2pack(accS[nt].z - m_hi, accS[nt].w - m_hi));
        }

#pragma unroll
        for (int kk = 0; kk < 8; kk++) {
            uint32_t a0 = pLo[2 * kk], a1 = pHi[2 * kk];
            uint32_t a2 = pLo[2 * kk + 1], a3 = pHi[2 * kk + 1];
#pragma unroll
            for (int jp = 0; jp < 4; jp++) {
                uint32_t b0, b1, b2, b3;
                LDSM_X4(b0, b1, b2, b3, vbase + jp * (16 * 136 * 2) + kk * 32 + vb_off);
                mma_f16(accO[2 * jp],     a0, a1, a2, a3, b0, b1);
                mma_f16(accO[2 * jp + 1], a0, a1, a2, a3, b2, b3);
            }
            uint32_t c0, c1;
            LDSM_X2(c0, c1, vbase + kk * 32 + v2_off);
            mma_f16(accO[8], a0, a1, a2, a3, c0, c1);
        }
    }

    // ---- epilogue: O[e][l] = accO / rowsum, fp16 out ----
    float s_lo = __shfl_sync(0xffffffffu, accO[8].x, lane & ~3);
    float s_hi = __shfl_sync(0xffffffffu, accO[8].z, lane & ~3);
    float i_lo = 1.0f / s_lo;
    float i_hi = 1.0f / s_hi;
#pragma unroll
    for (int nt = 0; nt < 8; nt++) {
        int e = nt * 8 + 2 * tig;
        ob[(long)e * LF + row_lo]       = __float2half_rn(accO[nt].x * i_lo);
        ob[(long)(e + 1) * LF + row_lo] = __float2half_rn(accO[nt].y * i_lo);
        ob[(long)e * LF + row_hi]       = __float2half_rn(accO[nt].z * i_hi);
        ob[(long)(e + 1) * LF + row_hi] = __float2half_rn(accO[nt].w * i_hi);
    }
}

// ---------------- launch ----------------
extern "C" void kernel_launch(void* const* d_in, const int* in_sizes, int n_in,
                              void* d_out, int out_size) {
    const float* x  = (const float*)d_in[0];
    const float* Wq = (const float*)d_in[1];  const float* bq = (const float*)d_in[2];
    const float* Wk = (const float*)d_in[3];  const float* bk = (const float*)d_in[4];
    const float* Wv = (const float*)d_in[5];  const float* bv = (const float*)d_in[6];
    const float* Wo = (const float*)d_in[7];  const float* bo = (const float*)d_in[8];
    const float* Wa = (const float*)d_in[9];
    const float* g1 = (const float*)d_in[10]; const float* b1 = (const float*)d_in[11];
    const float* m1 = (const float*)d_in[12]; const float* v1 = (const float*)d_in[13];
    const float* g2 = (const float*)d_in[14]; const float* b2 = (const float*)d_in[15];
    const float* m2 = (const float*)d_in[16]; const float* v2 = (const float*)d_in[17];
    float* out = (float*)d_out;
    (void)in_sizes; (void)n_in; (void)out_size;

    float *pS, *pT;
    __half *pXh, *pXaggh, *pXah, *pQh, *pKh, *pVh, *pOh;
    __half *pWqh, *pWkh, *pWvh, *pWoh, *pWah;
    cudaGetSymbolAddress((void**)&pXh,    d_xh);
    cudaGetSymbolAddress((void**)&pXaggh, d_xaggh);
    cudaGetSymbolAddress((void**)&pXah,   d_xah);
    cudaGetSymbolAddress((void**)&pQh,    d_qh);
    cudaGetSymbolAddress((void**)&pKh,    d_kh);
    cudaGetSymbolAddress((void**)&pVh,    d_vh);
    cudaGetSymbolAddress((void**)&pOh,    d_oh);
    cudaGetSymbolAddress((void**)&pWqh,   d_wqh);
    cudaGetSymbolAddress((void**)&pWkh,   d_wkh);
    cudaGetSymbolAddress((void**)&pWvh,   d_wvh);
    cudaGetSymbolAddress((void**)&pWoh,   d_woh);
    cudaGetSymbolAddress((void**)&pWah,   d_wah);
    cudaGetSymbolAddress((void**)&pS,     d_bns);
    cudaGetSymbolAddress((void**)&pT,     d_bnt);

    cudaFuncSetAttribute(flash_kernel, cudaFuncAttributeMaxDynamicSharedMemorySize,
                         FLASH_SMEM_BYTES);
    cudaFuncSetAttribute(hgemm<128, 4, 0>, cudaFuncAttributeMaxDynamicSharedMemorySize,
                         HGEMM128_SMEM);
    cudaFuncSetAttribute(hgemm<128, 4, 1>, cudaFuncAttributeMaxDynamicSharedMemorySize,
                         HGEMM128_SMEM);
    cudaFuncSetAttribute(hgemm<64, 2, 2>, cudaFuncAttributeMaxDynamicSharedMemorySize,
                         HGEMM64_SMEM);
    cudaFuncSetAttribute(hgemm<64, 2, 3>, cudaFuncAttributeMaxDynamicSharedMemorySize,
                         HGEMM64_SMEM);

    const float QSCALE = 0.125f * 1.44269504089f;  // fold 1/sqrt(E) and log2e into Q

    // 1) fold BNs; convert weights and x to fp16; pool
    bnfold_kernel<<<1, 256>>>(g1, b1, m1, v1, g2, b2, m2, v2);
    cvtw_kernel<<<dim3(64, 5), 256>>>(Wq, Wk, Wv, Wo, Wa);
    cvtx_kernel<<<(NB * CCH * LF / 4) / 256, 256>>>(x);
    aggregate_kernel<<<(NB * CCH * L2) / 256, 256>>>(x);

    // 2) Q = fp16[l][e] of log2e*0.125*(Wq x + bq)
    hgemm<128, 4, 1><<<dim3(LF / 128, CCH / 128, NB), 256, HGEMM128_SMEM>>>(
        pWqh, nullptr, pXh, nullptr, pQh, nullptr, CCH, LF, LF,
        0, (long)CCH * LF, 0, QSCALE, QSCALE, nullptr, bq, nullptr);

    // 3) xa = BN2(BN1(Wa @ xagg))  fp16 direct
    hgemm<64, 2, 2><<<dim3(L2 / 128, CCH / 64, NB), 256, HGEMM64_SMEM>>>(
        pWah, nullptr, pXaggh, nullptr, pXah, nullptr, CCH, L2, L2,
        0, (long)CCH * L2, 0, 1.0f, 1.0f, pS, pT, nullptr);

    // 4) K (transposed) and V (direct) in ONE dual launch
    hgemm<64, 2, 3><<<dim3(L2 / 128, CCH / 64, NB * 2), 256, HGEMM64_SMEM>>>(
        pWkh, pWvh, pXah, nullptr, pKh, pVh, CCH, L2, L2,
        0, (long)CCH * L2, 0, 1.0f, 1.0f, nullptr, bk, bv);

    // 5) fused attention -> fp16 O
    flash_kernel<<<dim3(LF / 128, NB * HH), 256, FLASH_SMEM_BYTES>>>(pQh, pKh, pVh, pOh);

    // 6) out = Wo @ o + bo  (fp32 out)
    hgemm<128, 4, 0><<<dim3(LF / 128, CCH / 128, NB), 256, HGEMM128_SMEM>>>(
        pWoh, nullptr, pOh, out, nullptr, nullptr, CCH, LF, LF,
        0, (long)CCH * LF, (long)CCH * LF, 1.0f, 1.0f, nullptr, bo, nullptr);
}

// round 13
// speedup vs baseline: 9.5260x; 1.1397x over previous
#include <cuda_runtime.h>
#include <cuda_fp16.h>
#include <cstdint>

// Problem constants
#define NB  4
#define CCH 256
#define LF  4096
#define L2  1024
#define HH  4
#define EE  64

// ---------------- device scratch (static; no cudaMalloc) ----------------
__device__ __half d_xh   [NB * CCH * LF];
__device__ __half d_xaggh[NB * CCH * L2];
__device__ __half d_xah  [NB * CCH * L2];
__device__ __half d_qh   [NB * HH * LF * EE];  // [n][h][l][e], log2e*0.125*(Wq x + bq)
__device__ __half d_kh   [NB * HH * L2 * EE];  // [n][h][m][e]
__device__ __half d_vh   [NB * HH * EE * L2];  // [n][h][e][m]
__device__ __half d_oh   [NB * CCH * LF];
__device__ __half d_wqh[CCH * CCH], d_wkh[CCH * CCH], d_wvh[CCH * CCH];
__device__ __half d_woh[CCH * CCH], d_wah[CCH * CCH];
__device__ float  d_bns[CCH];
__device__ float  d_bnt[CCH];

// ---------------- fused prep: x->fp16 + pooling, weights->fp16, BN fold ----------------
// grid 1185 x 256: blocks [0,1024) process one (n,c) row each; [1024,1184) weights; 1184 BN.
__global__ void prep_kernel(const float* __restrict__ x,
                            const float* __restrict__ wq, const float* __restrict__ wk,
                            const float* __restrict__ wv, const float* __restrict__ wo,
                            const float* __restrict__ wa,
                            const float* __restrict__ g1, const float* __restrict__ b1,
                            const float* __restrict__ m1, const float* __restrict__ v1,
                            const float* __restrict__ g2, const float* __restrict__ b2,
                            const float* __restrict__ m2, const float* __restrict__ v2) {
    int b = blockIdx.x;
    int tid = threadIdx.x;
    if (b < NB * CCH) {
        const float4* xr = reinterpret_cast<const float4*>(x + (long)b * LF);
        __half2* xo = reinterpret_cast<__half2*>(d_xh) + (long)b * (LF / 2);
        __half*  ao = d_xaggh + (long)b * L2;
#pragma unroll
        for (int k = 0; k < 4; k++) {
            int j = tid + k * 256;              // float4 index = pool group index
            float4 t = xr[j];
            xo[2 * j]     = __floats2half2_rn(t.x, t.y);
            xo[2 * j + 1] = __floats2half2_rn(t.z, t.w);
            float mx = fmaxf(fmaxf(t.x, t.y), fmaxf(t.z, t.w));
            ao[j] = __float2half_rn(0.25f * (t.x + t.y + t.z + t.w) + mx);
        }
    } else if (b < NB * CCH + 160) {
        const float* src[5] = {wq, wk, wv, wo, wa};
        __half* dst[5] = {d_wqh, d_wkh, d_wvh, d_woh, d_wah};
#pragma unroll
        for (int k = 0; k < 2; k++) {
            int idx = (b - NB * CCH) * 512 + k * 256 + tid;   // float4 idx in [0, 81920)
            int m = idx >> 14;                                 // /16384
            int j = idx & 16383;
            float4 t = reinterpret_cast<const float4*>(src[m])[j];
            __half2* o = reinterpret_cast<__half2*>(dst[m]);
            o[2 * j]     = __floats2half2_rn(t.x, t.y);
            o[2 * j + 1] = __floats2half2_rn(t.z, t.w);
        }
    } else {
        int c = tid;
        float i1 = g1[c] * rsqrtf(v1[c] + 1e-5f);
        float c1 = b1[c] - m1[c] * i1;
        float i2 = g2[c] * rsqrtf(v2[c] + 1e-5f);
        float c2 = b2[c] - m2[c] * i2;
        d_bns[c] = i1 * i2;
        d_bnt[c] = c1 * i2 + c2;
    }
}

// ---------------- helpers ----------------
__device__ __forceinline__ void mma_f16(float4& c, uint32_t a0, uint32_t a1, uint32_t a2,
                                        uint32_t a3, uint32_t b0, uint32_t b1) {
    asm volatile(
        "mma.sync.aligned.m16n8k16.row.col.f32.f16.f16.f32 "
        "{%0,%1,%2,%3}, {%4,%5,%6,%7}, {%8,%9}, {%0,%1,%2,%3};\n"
        : "+f"(c.x), "+f"(c.y), "+f"(c.z), "+f"(c.w)
        : "r"(a0), "r"(a1), "r"(a2), "r"(a3), "r"(b0), "r"(b1));
}
__device__ __forceinline__ uint32_t h2pack(float a, float b) {
    __half2 h = __floats2half2_rn(a, b);
    return *reinterpret_cast<uint32_t*>(&h);
}
__device__ __forceinline__ uint32_t ex2h2(uint32_t in) {
    uint32_t r;
    asm("ex2.approx.f16x2 %0, %1;" : "=r"(r) : "r"(in));
    return r;
}
__device__ __forceinline__ float ex2f(float x) {
    float r;
    asm("ex2.approx.f32 %0, %1;" : "=f"(r) : "f"(x));
    return r;
}
__device__ __forceinline__ uint32_t stou(const void* p) {
    return (uint32_t)__cvta_generic_to_shared(p);
}
__device__ __forceinline__ void cpa16(uint32_t dst, const void* src) {
    asm volatile("cp.async.cg.shared.global [%0], [%1], 16;\n" :: "r"(dst), "l"(src));
}
__device__ __forceinline__ void cp_commit() { asm volatile("cp.async.commit_group;\n"); }
template <int N> __device__ __forceinline__ void cp_wait() {
    asm volatile("cp.async.wait_group %0;\n" :: "n"(N));
}
#define LDSM_X4(r0, r1, r2, r3, addr) \
    asm volatile("ldmatrix.sync.aligned.m8n8.x4.shared.b16 {%0,%1,%2,%3}, [%4];" \
                 : "=r"(r0), "=r"(r1), "=r"(r2), "=r"(r3) : "r"(addr))
#define LDSM_X4_T(r0, r1, r2, r3, addr) \
    asm volatile("ldmatrix.sync.aligned.m8n8.x4.trans.shared.b16 {%0,%1,%2,%3}, [%4];" \
                 : "=r"(r0), "=r"(r1), "=r"(r2), "=r"(r3) : "r"(addr))
#define LDSM_X2(r0, r1, addr) \
    asm volatile("ldmatrix.sync.aligned.m8n8.x2.shared.b16 {%0,%1}, [%2];" \
                 : "=r"(r0), "=r"(r1) : "r"(addr))

// ---------------- fp16 3-stage GEMM ----------------
// acc = sum_k A[m][k]*B[k][n]  (A fp16 [M][K] lda, B fp16 [K][N] ldb, K=256)
// OMODE 0: Y fp32.  OMODE 1: fp16 transposed per 64-row head.
// OMODE 2: fp16 direct.  OMODE 3: DUAL (z even: K transposed; z odd: V direct).
template <int BM, int TMt, int OMODE>
__global__ __launch_bounds__(256, 2) void hgemm(
    const __half* __restrict__ A, const __half* __restrict__ A2,
    const __half* __restrict__ B,
    float* __restrict__ Y, __half* __restrict__ Yh, __half* __restrict__ Yh2,
    int lda, int ldb, int ldy,
    long aB, long bB, long yB, float alpha, float beta,
    const float* __restrict__ rs,
    const float* __restrict__ rb, const float* __restrict__ rb2)
{
    extern __shared__ __half smH[];
    __half* sA = smH;                   // [3][BM][40]
    __half* sB = smH + 3 * BM * 40;     // [3][32][136]

    int sel = 0;
    long zb;
    if (OMODE == 3) {
        sel = blockIdx.z & 1;
        zb  = blockIdx.z >> 1;
        if (sel) { A = A2; rb = rb2; }
    } else {
        zb = blockIdx.z;
    }
    A += zb * aB;
    B += zb * bB;

    const int tid  = threadIdx.x;
    const int lane = tid & 31;
    const int wid  = tid >> 5;
    const int wm   = wid >> 2;
    const int wn   = wid & 3;
    const int g    = lane >> 2;
    const int tig  = lane & 3;
    const int m0   = blockIdx.y * BM;
    const int n0   = blockIdx.x * 128;

    const uint32_t a_off = ((lane & 15) * 40 + (lane >> 4) * 8) * 2;
    const uint32_t b_off = ((lane & 15) * 136 + (lane >> 4) * 8) * 2;

    float4 acc[TMt][4];
#pragma unroll
    for (int i = 0; i < TMt; i++)
#pragma unroll
        for (int j = 0; j < 4; j++) acc[i][j] = make_float4(0.f, 0.f, 0.f, 0.f);

    auto prefetch = [&](int t, int buf) {
        __half* dA = sA + buf * BM * 40;
        __half* dB = sB + buf * 32 * 136;
#pragma unroll
        for (int i = tid; i < BM * 4; i += 256) {
            int r = i >> 2, c = (i & 3) * 8;
            cpa16(stou(dA + r * 40 + c), A + (long)(m0 + r) * lda + t * 32 + c);
        }
#pragma unroll
        for (int i = tid; i < 512; i += 256) {
            int r = i >> 4, c = (i & 15) * 8;
            cpa16(stou(dB + r * 136 + c), B + (long)(t * 32 + r) * ldb + n0 + c);
        }
    };

    prefetch(0, 0); cp_commit();
    prefetch(1, 1); cp_commit();

    for (int t = 0; t < 8; t++) {
        if (t < 7) cp_wait<1>(); else cp_wait<0>();
        __syncthreads();
        if (t + 2 < 8) { prefetch(t + 2, (t + 2) % 3); cp_commit(); }

        const uint32_t aBase = stou(sA) + (uint32_t)((t % 3) * BM * 40 * 2);
        const uint32_t bBase = stou(sB) + (uint32_t)((t % 3) * 32 * 136 * 2);

#pragma unroll
        for (int s = 0; s < 2; s++) {
            uint32_t a[TMt][4];
#pragma unroll
            for (int mt = 0; mt < TMt; mt++)
                LDSM_X4(a[mt][0], a[mt][1], a[mt][2], a[mt][3],
                        aBase + (uint32_t)(((wm * TMt * 16 + mt * 16) * 40 + s * 16) * 2) + a_off);
            uint32_t b[2][4];
#pragma unroll
            for (int j = 0; j < 2; j++)
                LDSM_X4_T(b[j][0], b[j][1], b[j][2], b[j][3],
                          bBase + (uint32_t)((s * 16 * 136 + wn * 32 + j * 16) * 2) + b_off);
#pragma unroll
            for (int mt = 0; mt < TMt; mt++)
#pragma unroll
                for (int nt = 0; nt < 4; nt++)
                    mma_f16(acc[mt][nt], a[mt][0], a[mt][1], a[mt][2], a[mt][3],
                            b[nt >> 1][(nt & 1) * 2], b[nt >> 1][(nt & 1) * 2 + 1]);
        }
    }

    const bool kpath = (OMODE == 1) || (OMODE == 3 && sel == 0);
    if (kpath) {
        __syncthreads();
        __half* sT = smH;
        const int st = BM + 2;
#pragma unroll
        for (int mt = 0; mt < TMt; mt++) {
            int rl = wm * (TMt * 16) + mt * 16 + g;
            int r = m0 + rl;
            float t0 = beta * (rb ? rb[r] : 0.0f);
            float t1 = beta * (rb ? rb[r + 8] : 0.0f);
#pragma unroll
            for (int nt = 0; nt < 4; nt++) {
                int c = wn * 32 + nt * 8 + 2 * tig;
                sT[c * st + rl]           = __float2half_rn(acc[mt][nt].x * alpha + t0);
                sT[(c + 1) * st + rl]     = __float2half_rn(acc[mt][nt].y * alpha + t0);
                sT[c * st + rl + 8]       = __float2half_rn(acc[mt][nt].z * alpha + t1);
                sT[(c + 1) * st + rl + 8] = __float2half_rn(acc[mt][nt].w * alpha + t1);
            }
        }
        __syncthreads();
        uint32_t* Y32 = reinterpret_cast<uint32_t*>(Yh);
        for (int i = tid; i < 128 * (BM / 2); i += 256) {
            int lc = i / (BM / 2);
            int rp = (i % (BM / 2)) * 2;
            uint32_t v = *reinterpret_cast<uint32_t*>(&sT[lc * st + rp]);
            int r = m0 + rp;
            int h = r >> 6, e = r & 63;
            Y32[((zb * HH + h) * (long)ldy + n0 + lc) * 32 + (e >> 1)] = v;
        }
    } else {
#pragma unroll
        for (int mt = 0; mt < TMt; mt++) {
            int r = m0 + wm * (TMt * 16) + mt * 16 + g;
            float s0 = alpha * (rs ? rs[r] : 1.0f),     t0 = beta * (rb ? rb[r] : 0.0f);
            float s1 = alpha * (rs ? rs[r + 8] : 1.0f), t1 = beta * (rb ? rb[r + 8] : 0.0f);
#pragma unroll
            for (int nt = 0; nt < 4; nt++) {
                int c = n0 + wn * 32 + nt * 8 + 2 * tig;
                float y00 = acc[mt][nt].x * s0 + t0, y01 = acc[mt][nt].y * s0 + t0;
                float y10 = acc[mt][nt].z * s1 + t1, y11 = acc[mt][nt].w * s1 + t1;
                if (OMODE == 2 || OMODE == 3) {
                    __half* Yd = (OMODE == 3) ? Yh2 : Yh;
                    uint32_t* Y32 = reinterpret_cast<uint32_t*>(Yd);
                    Y32[((zb * CCH + r) * (long)ldy + c) >> 1]     = h2pack(y00, y01);
                    Y32[((zb * CCH + r + 8) * (long)ldy + c) >> 1] = h2pack(y10, y11);
                } else {
                    float* Yb = Y + zb * yB;
                    *reinterpret_cast<float2*>(Yb + (long)r * ldy + c) = make_float2(y00, y01);
                    *reinterpret_cast<float2*>(Yb + (long)(r + 8) * ldy + c) = make_float2(y10, y11);
                }
            }
        }
    }
}

#define HGEMM128_SMEM (3 * (128 * 40 + 32 * 136) * 2)
#define HGEMM64_SMEM  (3 * (64 * 40 + 32 * 136) * 2)

// ---------------- fused flash attention: 128 threads, 64-query blocks, 2 CTAs/SM ----------------
// Q: [l][64e] (log2 domain), K: [m][64e], V: [64e][m] fp16.  4 warps; warp w owns q rows w*16..+16.
// sV has 72 e-rows: row 64 = ones, 65-71 = zeros -> accO[8] accumulates row sums on tensor pipe.
#define SQH 0
#define SKH (64 * 72)
#define SVH (SKH + 2 * 128 * 72)
#define FLASH_SMEM_BYTES ((SVH + 2 * 72 * 136) * 2)   // 85,248 B

__global__ __launch_bounds__(128, 2) void flash_kernel(
    const __half* __restrict__ Qh, const __half* __restrict__ Kh,
    const __half* __restrict__ Vh, __half* __restrict__ O)
{
    extern __shared__ __half smh[];
    __half* sQ = smh + SQH;
    __half* sK = smh + SKH;
    __half* sV = smh + SVH;

    const int tid  = threadIdx.x;
    const int lane = tid & 31;
    const int w    = tid >> 5;      // 0..3
    const int g    = lane >> 2;
    const int tig  = lane & 3;

    const int l0 = blockIdx.x * 64;
    const int nh = blockIdx.y;
    const int n  = nh >> 2, h = nh & 3;
    const __half* qb = Qh + (((long)(n * HH + h)) * LF + l0) * EE;
    const __half* kb = Kh + ((long)(n * HH + h)) * L2 * EE;
    const __half* vb = Vh + ((long)(n * HH + h)) * EE * L2;
    __half*       ob = O + ((long)n * CCH + h * 64) * LF + l0;

    const int row_lo = w * 16 + g;
    const int row_hi = row_lo + 8;

    const int qrow = lane & 7;
    const int sel  = lane >> 3;
    const uint32_t sQb = stou(sQ), sKb0 = stou(sK), sVb0 = stou(sV);
    const uint32_t qa_off = ((w * 16 + (lane & 15)) * 72 + (lane >> 4) * 8) * 2;
    const uint32_t kb_off = (((sel >> 1) * 8 + qrow) * 72 + (sel & 1) * 8) * 2;
    const uint32_t vb_off = (((sel >> 1) * 8 + qrow) * 136 + (sel & 1) * 8) * 2;
    const uint32_t v2_off = ((64 + qrow) * 136 + ((lane >> 3) & 1) * 8) * 2;

    // prologue: Q (group 0); K0+V0 (group 1)
#pragma unroll
    for (int i = 0; i < 4; i++) {
        int idx = tid + i * 128;              // 512 total: 64 rows x 8 col-groups
        int r = idx >> 3, c8 = idx & 7;
        cpa16(stou(sQ + r * 72 + c8 * 8), qb + (long)r * EE + c8 * 8);
    }
    cp_commit();
#pragma unroll
    for (int i = 0; i < 8; i++) {
        int idx = tid + i * 128;              // 1024: 128 rows x 8 col-groups
        int r = idx >> 3, c8 = idx & 7;
        cpa16(stou(sK + r * 72 + c8 * 8), kb + (long)r * EE + c8 * 8);
    }
#pragma unroll
    for (int i = 0; i < 8; i++) {
        int idx = tid + i * 128;              // 1024: 64 rows x 16 col-groups
        int r = idx >> 4, c16 = idx & 15;
        cpa16(stou(sV + r * 136 + c16 * 8), vb + (long)r * L2 + c16 * 8);
    }
    cp_commit();

    // ones/zeros rows 64-71 of both V buffers
    {
        uint32_t* sV32w = reinterpret_cast<uint32_t*>(sV);
        for (int i = tid; i < 2 * 8 * 68; i += 128) {
            int buf = i / (8 * 68);
            int rem = i % (8 * 68);
            int r = rem / 68, c = rem % 68;
            sV32w[buf * (72 * 68) + (64 + r) * 68 + c] = (r == 0) ? 0x3C003C00u : 0u;
        }
    }

    float m_lo = -1e30f, m_hi = -1e30f;
    float4 accO[9];
#pragma unroll
    for (int nt = 0; nt < 9; nt++) accO[nt] = make_float4(0.f, 0.f, 0.f, 0.f);

    cp_wait<0>();
    __syncthreads();

    uint32_t qa[4][4];
#pragma unroll
    for (int kk = 0; kk < 4; kk++)
        LDSM_X4(qa[kk][0], qa[kk][1], qa[kk][2], qa[kk][3], sQb + qa_off + kk * 32);

#pragma unroll 1
    for (int t = 0; t < 8; t++) {
        if (t > 0) {
            cp_wait<0>();
            __syncthreads();
        }
        if (t < 7) {
            __half* dK = sK + ((t + 1) & 1) * (128 * 72);
            const __half* ksrc = kb + (long)(t + 1) * 128 * EE;
#pragma unroll
            for (int i = 0; i < 8; i++) {
                int idx = tid + i * 128;
                int r = idx >> 3, c8 = idx & 7;
                cpa16(stou(dK + r * 72 + c8 * 8), ksrc + (long)r * EE + c8 * 8);
            }
            __half* dV = sV + ((t + 1) & 1) * (72 * 136);
#pragma unroll
            for (int i = 0; i < 8; i++) {
                int idx = tid + i * 128;
                int r = idx >> 4, c16 = idx & 15;
                cpa16(stou(dV + r * 136 + c16 * 8), vb + (long)r * L2 + (t + 1) * 128 + c16 * 8);
            }
            cp_commit();
        }

        const uint32_t kbase = sKb0 + (uint32_t)((t & 1) * (128 * 72 * 2));
        const uint32_t vbase = sVb0 + (uint32_t)((t & 1) * (72 * 136 * 2));

        float4 accS[16];
#pragma unroll
        for (int nt = 0; nt < 16; nt++) accS[nt] = make_float4(0.f, 0.f, 0.f, 0.f);

#pragma unroll
        for (int kk = 0; kk < 4; kk++) {
#pragma unroll
            for (int jp = 0; jp < 8; jp++) {
                uint32_t b0, b1, b2, b3;
                LDSM_X4(b0, b1, b2, b3, kbase + jp * (16 * 72 * 2) + kk * 32 + kb_off);
                mma_f16(accS[2 * jp],     qa[kk][0], qa[kk][1], qa[kk][2], qa[kk][3], b0, b1);
                mma_f16(accS[2 * jp + 1], qa[kk][0], qa[kk][1], qa[kk][2], qa[kk][3], b2, b3);
            }
        }

        float tm_lo = -1e30f, tm_hi = -1e30f;
#pragma unroll
        for (int nt = 0; nt < 16; nt++) {
            tm_lo = fmaxf(tm_lo, fmaxf(accS[nt].x, accS[nt].y));
            tm_hi = fmaxf(tm_hi, fmaxf(accS[nt].z, accS[nt].w));
        }
        tm_lo = fmaxf(tm_lo, __shfl_xor_sync(0xffffffffu, tm_lo, 1));
        tm_lo = fmaxf(tm_lo, __shfl_xor_sync(0xffffffffu, tm_lo, 2));
        tm_hi = fmaxf(tm_hi, __shfl_xor_sync(0xffffffffu, tm_hi, 1));
        tm_hi = fmaxf(tm_hi, __shfl_xor_sync(0xffffffffu, tm_hi, 2));

        float nm_lo = fmaxf(m_lo, tm_lo);
        float nm_hi = fmaxf(m_hi, tm_hi);
        float sc_lo = ex2f(m_lo - nm_lo);
        float sc_hi = ex2f(m_hi - nm_hi);
        m_lo = nm_lo; m_hi = nm_hi;

#pragma unroll
        for (int nt = 0; nt < 9; nt++) {
            accO[nt].x *= sc_lo; accO[nt].y *= sc_lo;
            accO[nt].z *= sc_hi; accO[nt].w *= sc_hi;
        }

        uint32_t pLo[16], pHi[16];
#pragma unroll
        for (int nt = 0; nt < 16; nt++) {
            pLo[nt] = ex2h2(h2pack(accS[nt].x - m_lo, accS[nt].y - m_lo));
            pHi[nt] = ex2h2(h2pack(accS[nt].z - m_hi, accS[nt].w - m_hi));
        }

#pragma unroll
        for (int kk = 0; kk < 8; kk++) {
            uint32_t a0 = pLo[2 * kk], a1 = pHi[2 * kk];
            uint32_t a2 = pLo[2 * kk + 1], a3 = pHi[2 * kk + 1];
#pragma unroll
            for (int jp = 0; jp < 4; jp++) {
                uint32_t b0, b1, b2, b3;
                LDSM_X4(b0, b1, b2, b3, vbase + jp * (16 * 136 * 2) + kk * 32 + vb_off);
                mma_f16(accO[2 * jp],     a0, a1, a2, a3, b0, b1);
                mma_f16(accO[2 * jp + 1], a0, a1, a2, a3, b2, b3);
            }
            uint32_t c0, c1;
            LDSM_X2(c0, c1, vbase + kk * 32 + v2_off);
            mma_f16(accO[8], a0, a1, a2, a3, c0, c1);
        }
    }

    // ---- epilogue: O[e][l] = accO / rowsum, fp16 out ----
    float s_lo = __shfl_sync(0xffffffffu, accO[8].x, lane & ~3);
    float s_hi = __shfl_sync(0xffffffffu, accO[8].z, lane & ~3);
    float i_lo = 1.0f / s_lo;
    float i_hi = 1.0f / s_hi;
#pragma unroll
    for (int nt = 0; nt < 8; nt++) {
        int e = nt * 8 + 2 * tig;
        ob[(long)e * LF + row_lo]       = __float2half_rn(accO[nt].x * i_lo);
        ob[(long)(e + 1) * LF + row_lo] = __float2half_rn(accO[nt].y * i_lo);
        ob[(long)e * LF + row_hi]       = __float2half_rn(accO[nt].z * i_hi);
        ob[(long)(e + 1) * LF + row_hi] = __float2half_rn(accO[nt].w * i_hi);
    }
}

// ---------------- launch ----------------
extern "C" void kernel_launch(void* const* d_in, const int* in_sizes, int n_in,
                              void* d_out, int out_size) {
    const float* x  = (const float*)d_in[0];
    const float* Wq = (const float*)d_in[1];  const float* bq = (const float*)d_in[2];
    const float* Wk = (const float*)d_in[3];  const float* bk = (const float*)d_in[4];
    const float* Wv = (const float*)d_in[5];  const float* bv = (const float*)d_in[6];
    const float* Wo = (const float*)d_in[7];  const float* bo = (const float*)d_in[8];
    const float* Wa = (const float*)d_in[9];
    const float* g1 = (const float*)d_in[10]; const float* b1 = (const float*)d_in[11];
    const float* m1 = (const float*)d_in[12]; const float* v1 = (const float*)d_in[13];
    const float* g2 = (const float*)d_in[14]; const float* b2 = (const float*)d_in[15];
    const float* m2 = (const float*)d_in[16]; const float* v2 = (const float*)d_in[17];
    float* out = (float*)d_out;
    (void)in_sizes; (void)n_in; (void)out_size;

    float *pS, *pT;
    __half *pXh, *pXaggh, *pXah, *pQh, *pKh, *pVh, *pOh;
    __half *pWqh, *pWkh, *pWvh, *pWoh, *pWah;
    cudaGetSymbolAddress((void**)&pXh,    d_xh);
    cudaGetSymbolAddress((void**)&pXaggh, d_xaggh);
    cudaGetSymbolAddress((void**)&pXah,   d_xah);
    cudaGetSymbolAddress((void**)&pQh,    d_qh);
    cudaGetSymbolAddress((void**)&pKh,    d_kh);
    cudaGetSymbolAddress((void**)&pVh,    d_vh);
    cudaGetSymbolAddress((void**)&pOh,    d_oh);
    cudaGetSymbolAddress((void**)&pWqh,   d_wqh);
    cudaGetSymbolAddress((void**)&pWkh,   d_wkh);
    cudaGetSymbolAddress((void**)&pWvh,   d_wvh);
    cudaGetSymbolAddress((void**)&pWoh,   d_woh);
    cudaGetSymbolAddress((void**)&pWah,   d_wah);
    cudaGetSymbolAddress((void**)&pS,     d_bns);
    cudaGetSymbolAddress((void**)&pT,     d_bnt);

    cudaFuncSetAttribute(flash_kernel, cudaFuncAttributeMaxDynamicSharedMemorySize,
                         FLASH_SMEM_BYTES);
    cudaFuncSetAttribute(hgemm<128, 4, 0>, cudaFuncAttributeMaxDynamicSharedMemorySize,
                         HGEMM128_SMEM);
    cudaFuncSetAttribute(hgemm<128, 4, 1>, cudaFuncAttributeMaxDynamicSharedMemorySize,
                         HGEMM128_SMEM);
    cudaFuncSetAttribute(hgemm<64, 2, 2>, cudaFuncAttributeMaxDynamicSharedMemorySize,
                         HGEMM64_SMEM);
    cudaFuncSetAttribute(hgemm<64, 2, 3>, cudaFuncAttributeMaxDynamicSharedMemorySize,
                         HGEMM64_SMEM);

    const float QSCALE = 0.125f * 1.44269504089f;  // fold 1/sqrt(E) and log2e into Q

    // 1) fused prep: x->fp16 + pooling, weights->fp16, BN fold
    prep_kernel<<<NB * CCH + 160 + 1, 256>>>(x, Wq, Wk, Wv, Wo, Wa,
                                             g1, b1, m1, v1, g2, b2, m2, v2);

    // 2) Q = fp16[l][e] of log2e*0.125*(Wq x + bq)
    hgemm<128, 4, 1><<<dim3(LF / 128, CCH / 128, NB), 256, HGEMM128_SMEM>>>(
        pWqh, nullptr, pXh, nullptr, pQh, nullptr, CCH, LF, LF,
        0, (long)CCH * LF, 0, QSCALE, QSCALE, nullptr, bq, nullptr);

    // 3) xa = BN2(BN1(Wa @ xagg))  fp16 direct
    hgemm<64, 2, 2><<<dim3(L2 / 128, CCH / 64, NB), 256, HGEMM64_SMEM>>>(
        pWah, nullptr, pXaggh, nullptr, pXah, nullptr, CCH, L2, L2,
        0, (long)CCH * L2, 0, 1.0f, 1.0f, pS, pT, nullptr);

    // 4) K (transposed) and V (direct) in ONE dual launch
    hgemm<64, 2, 3><<<dim3(L2 / 128, CCH / 64, NB * 2), 256, HGEMM64_SMEM>>>(
        pWkh, pWvh, pXah, nullptr, pKh, pVh, CCH, L2, L2,
        0, (long)CCH * L2, 0, 1.0f, 1.0f, nullptr, bk, bv);

    // 5) fused attention: 64-query CTAs, 2 per SM
    flash_kernel<<<dim3(LF / 64, NB * HH), 128, FLASH_SMEM_BYTES>>>(pQh, pKh, pVh, pOh);

    // 6) out = Wo @ o + bo  (fp32 out)
    hgemm<128, 4, 0><<<dim3(LF / 128, CCH / 128, NB), 256, HGEMM128_SMEM>>>(
        pWoh, nullptr, pOh, out, nullptr, nullptr, CCH, LF, LF,
        0, (long)CCH * LF, (long)CCH * LF, 1.0f, 1.0f, nullptr, bo, nullptr);
}